// round 6
// baseline (speedup 1.0000x reference)
#include <cuda_runtime.h>
#include <cstdint>
#include <cstdio>

#define D    300
#define D4   75
#define MAXN 200000
#define MAXE 400000
#define NGR  1024
#define NJC  8192

// ---------------- scratch (static device memory; no allocs) ----------------
__device__ __align__(16) float g_buf0[(size_t)MAXN * D + 16];
__device__ __align__(16) float g_buf1[(size_t)MAXN * D + 16];
__device__ float g_deg[MAXN];      // deg, then dinv
__device__ float g_snorm[MAXN];    // self-loop norm = dinv^2
__device__ float g_enorm[MAXE];    // per-edge norm
__device__ float g_stats[2 * D];   // col sums / sumsq
__device__ float g_scale[D];
__device__ float g_shift[D];
__device__ __align__(16) float g_pool[(size_t)NJC * D];
__device__ float g_cnt[NJC];
__device__ __align__(16) float g_t0[(size_t)NJC * D];
__device__ __align__(16) float g_t1[(size_t)NJC * D];
__device__ __align__(16) float g_f0[(size_t)NGR * D];
__device__ __align__(16) float g_f1[(size_t)NGR * D];

// ---------------- small utility kernels ----------------
__global__ void k_embed(const int* __restrict__ x, const float* __restrict__ ae1,
                        const float* __restrict__ ae2, float* __restrict__ out, int n) {
    int idx = blockIdx.x * blockDim.x + threadIdx.x;
    if (idx >= n * D) return;
    int node = idx / D;
    int c = idx - node * D;
    out[idx] = ae1[x[node * 2] * D + c] + ae2[x[node * 2 + 1] * D + c];
}

__global__ void k_fill(float* p, float v, int n) {
    int i = blockIdx.x * blockDim.x + threadIdx.x;
    if (i < n) p[i] = v;
}

__global__ void k_degcount(const int* __restrict__ ei, float* __restrict__ deg, int E) {
    int i = blockIdx.x * blockDim.x + threadIdx.x;
    if (i < E) atomicAdd(&deg[ei[i]], 1.0f);
}

__global__ void k_degfin(float* __restrict__ deg, float* __restrict__ snorm, int n) {
    int i = blockIdx.x * blockDim.x + threadIdx.x;
    if (i >= n) return;
    float v = rsqrtf(deg[i]);   // deg >= 1 always (self-loop)
    deg[i] = v;
    snorm[i] = v * v;
}

__global__ void k_enorm(const int* __restrict__ ei, const float* __restrict__ dinv,
                        float* __restrict__ enorm, int E) {
    int i = blockIdx.x * blockDim.x + threadIdx.x;
    if (i < E) enorm[i] = dinv[ei[i]] * dinv[ei[E + i]];
}

// ---------------- GEMM: C[M,Nc] = oscale*(act(A)[M,K] @ B[Nc,K]^T + bias + e1 + e2) --------
// act(v)[k] = relu_opt(scale[k]*v + shift[k]);  BM=128, BN=64, BK=32, 8x4 micro via fma.rn.f32x2
__global__ __launch_bounds__(256) void k_gemm(
    const float* __restrict__ A, const float* __restrict__ B, float* __restrict__ C,
    int M, int Nc, int K,
    const float* __restrict__ bias, const float* __restrict__ e1, const float* __restrict__ e2,
    const float* __restrict__ scale, const float* __restrict__ shift,
    int relu, float oscale)
{
    __shared__ float As[32][130];  // [k][m] pad->even for LDS.64 pairs over m
    __shared__ float Bs[32][68];   // [k][n] pad->16B aligned rows for LDS.128

    const int tid = threadIdx.x;
    const int tx = tid & 15, ty = tid >> 4;
    const int m0 = blockIdx.y * 128, n0 = blockIdx.x * 64;

    unsigned long long acc[4][4];
#pragma unroll
    for (int i = 0; i < 4; i++)
#pragma unroll
        for (int j = 0; j < 4; j++) acc[i][j] = 0ull;

    const int nk = (K + 31) >> 5;
    for (int kt = 0; kt < nk; kt++) {
        const int k0 = kt << 5;
        // load A tile 128x32 (1024 float4)
#pragma unroll
        for (int i = 0; i < 4; i++) {
            int e = i * 256 + tid;
            int k4 = e & 7, r = e >> 3;
            int gm = m0 + r, gk = k0 + 4 * k4;
            float4 v = make_float4(0.f, 0.f, 0.f, 0.f);
            if (gm < M && gk < K) {   // K%4==0 so full float4 valid
                v = *(const float4*)(A + (long long)gm * K + gk);
                if (scale) {
                    v.x = fmaf(v.x, scale[gk], shift[gk]);
                    v.y = fmaf(v.y, scale[gk + 1], shift[gk + 1]);
                    v.z = fmaf(v.z, scale[gk + 2], shift[gk + 2]);
                    v.w = fmaf(v.w, scale[gk + 3], shift[gk + 3]);
                }
                if (relu) {
                    v.x = fmaxf(v.x, 0.f); v.y = fmaxf(v.y, 0.f);
                    v.z = fmaxf(v.z, 0.f); v.w = fmaxf(v.w, 0.f);
                }
            }
            As[4 * k4 + 0][r] = v.x; As[4 * k4 + 1][r] = v.y;
            As[4 * k4 + 2][r] = v.z; As[4 * k4 + 3][r] = v.w;
        }
        // load B tile 64x32 (512 float4)
#pragma unroll
        for (int i = 0; i < 2; i++) {
            int e = i * 256 + tid;
            int k4 = e & 7, r = e >> 3;
            int gn = n0 + r, gk = k0 + 4 * k4;
            float4 v = make_float4(0.f, 0.f, 0.f, 0.f);
            if (gn < Nc && gk < K)
                v = *(const float4*)(B + (long long)gn * K + gk);
            Bs[4 * k4 + 0][r] = v.x; Bs[4 * k4 + 1][r] = v.y;
            Bs[4 * k4 + 2][r] = v.z; Bs[4 * k4 + 3][r] = v.w;
        }
        __syncthreads();
#pragma unroll
        for (int kk = 0; kk < 32; kk++) {
            unsigned long long a2[4];
#pragma unroll
            for (int i = 0; i < 4; i++)
                a2[i] = *(const unsigned long long*)&As[kk][ty * 8 + 2 * i];
            float4 bv = *(const float4*)&Bs[kk][tx * 4];
            unsigned long long b2[4];
            {
                unsigned u0 = __float_as_uint(bv.x), u1 = __float_as_uint(bv.y);
                unsigned u2 = __float_as_uint(bv.z), u3 = __float_as_uint(bv.w);
                asm("mov.b64 %0, {%1,%1};" : "=l"(b2[0]) : "r"(u0));
                asm("mov.b64 %0, {%1,%1};" : "=l"(b2[1]) : "r"(u1));
                asm("mov.b64 %0, {%1,%1};" : "=l"(b2[2]) : "r"(u2));
                asm("mov.b64 %0, {%1,%1};" : "=l"(b2[3]) : "r"(u3));
            }
#pragma unroll
            for (int i = 0; i < 4; i++)
#pragma unroll
                for (int j = 0; j < 4; j++)
                    asm("fma.rn.f32x2 %0, %1, %2, %3;"
                        : "=l"(acc[i][j]) : "l"(a2[i]), "l"(b2[j]), "l"(acc[i][j]));
        }
        __syncthreads();
    }

    // epilogue
#pragma unroll
    for (int i = 0; i < 4; i++) {
#pragma unroll
        for (int j = 0; j < 4; j++) {
            int gn = n0 + tx * 4 + j;
            if (gn >= Nc) continue;
            float lo = __uint_as_float((unsigned)(acc[i][j] & 0xffffffffull));
            float hi = __uint_as_float((unsigned)(acc[i][j] >> 32));
            float add = 0.f;
            if (bias) add += bias[gn];
            if (e1) add += e1[gn] + e2[gn];
            int gm = m0 + ty * 8 + 2 * i;
            if (gm < M)     C[(long long)gm * Nc + gn] = (lo + add) * oscale;
            if (gm + 1 < M) C[(long long)(gm + 1) * Nc + gn] = (hi + add) * oscale;
        }
    }
}

// ---------------- scatter: AGG[dst] += norm * (T[src] + ee1[bt] + ee2[bd]) ----------------
// items [0,E) are edges; [E, E+N) are self loops (bt=4, bd=0). One warp per item.
__global__ void k_scatter(const float* __restrict__ T, float* __restrict__ AGG,
                          const int* __restrict__ ei, const int* __restrict__ ea,
                          const float* __restrict__ enorm, const float* __restrict__ snorm,
                          const float* __restrict__ ee1, const float* __restrict__ ee2,
                          int E, int N)
{
    int w = (blockIdx.x * blockDim.x + threadIdx.x) >> 5;
    int lane = threadIdx.x & 31;
    if (w >= E + N) return;
    int src, dst, bt, bd;
    float nrm;
    if (w < E) {
        src = ei[w]; dst = ei[E + w];
        bt = ea[2 * w]; bd = ea[2 * w + 1];
        nrm = enorm[w];
    } else {
        src = dst = w - E; bt = 4; bd = 0;
        nrm = snorm[w - E];
    }
    const float4* ts = (const float4*)(T + (long long)src * D);
    const float4* p1 = (const float4*)(ee1 + bt * D);
    const float4* p2 = (const float4*)(ee2 + bd * D);
    float* outp = AGG + (long long)dst * D;
    for (int idx = lane; idx < D4; idx += 32) {
        float4 v = ts[idx], a = p1[idx], b = p2[idx];
        float x = nrm * (v.x + a.x + b.x);
        float y = nrm * (v.y + a.y + b.y);
        float z = nrm * (v.z + a.z + b.z);
        float ww = nrm * (v.w + a.w + b.w);
        asm volatile("red.global.add.v4.f32 [%0], {%1,%2,%3,%4};"
                     :: "l"(outp + 4 * idx), "f"(x), "f"(y), "f"(z), "f"(ww) : "memory");
    }
}

// ---------------- BN stats / finalize ----------------
__global__ void k_bnstats(const float* __restrict__ A, float* __restrict__ st, int n) {
    int r0 = blockIdx.x * 256;
    int rend = min(r0 + 256, n);
    for (int c = threadIdx.x; c < D; c += 256) {
        float s = 0.f, q = 0.f;
#pragma unroll 4
        for (int r = r0; r < rend; r++) {
            float v = A[(long long)r * D + c];
            s += v;
            q = fmaf(v, v, q);
        }
        atomicAdd(&st[c], s);
        atomicAdd(&st[D + c], q);
    }
}

__global__ void k_bnfin(const float* __restrict__ st, const float* __restrict__ gamma,
                        const float* __restrict__ beta, float* __restrict__ sc,
                        float* __restrict__ sh, float invn) {
    int c = threadIdx.x;
    if (c >= D) return;
    float mean = st[c] * invn;
    float var = fmaxf(st[D + c] * invn - mean * mean, 0.f);
    float s = gamma[c] / sqrtf(var + 1e-5f);
    sc[c] = s;
    sh[c] = beta[c] - mean * s;
}

// ---------------- mean pooling ----------------
__global__ void k_pool(const float* __restrict__ A, const int* __restrict__ ids,
                       float* __restrict__ pool, float* __restrict__ cnt,
                       const float* __restrict__ scale, const float* __restrict__ shift, int n)
{
    int w = (blockIdx.x * blockDim.x + threadIdx.x) >> 5;
    int lane = threadIdx.x & 31;
    if (w >= n) return;
    int id = ids[w];
    if (lane == 0) atomicAdd(&cnt[id], 1.0f);
    const float4* ap = (const float4*)(A + (long long)w * D);
    float* op = pool + (long long)id * D;
    for (int idx = lane; idx < D4; idx += 32) {
        float4 v = ap[idx];
        if (scale) {
            int c = 4 * idx;
            v.x = fmaf(v.x, scale[c], shift[c]);
            v.y = fmaf(v.y, scale[c + 1], shift[c + 1]);
            v.z = fmaf(v.z, scale[c + 2], shift[c + 2]);
            v.w = fmaf(v.w, scale[c + 3], shift[c + 3]);
        }
        asm volatile("red.global.add.v4.f32 [%0], {%1,%2,%3,%4};"
                     :: "l"(op + 4 * idx), "f"(v.x), "f"(v.y), "f"(v.z), "f"(v.w) : "memory");
    }
}

__global__ void k_pooldiv(float* __restrict__ pool, const float* __restrict__ cnt, int total) {
    int i = blockIdx.x * blockDim.x + threadIdx.x;
    if (i < total) pool[i] /= fmaxf(cnt[i / D], 1.0f);
}

__global__ void k_mask(float* __restrict__ pool, const float* __restrict__ mask,
                       const float* __restrict__ memb, int total) {
    int i = blockIdx.x * blockDim.x + threadIdx.x;
    if (i < total && mask[i / D] > 0.5f) pool[i] = memb[i % D];
}

__global__ void k_l2norm(const float* __restrict__ A, float* __restrict__ out, int n) {
    int w = (blockIdx.x * blockDim.x + threadIdx.x) >> 5;
    int lane = threadIdx.x & 31;
    if (w >= n) return;
    const float4* ap = (const float4*)(A + (long long)w * D);
    float s = 0.f;
    for (int idx = lane; idx < D4; idx += 32) {
        float4 v = ap[idx];
        s += v.x * v.x + v.y * v.y + v.z * v.z + v.w * v.w;
    }
#pragma unroll
    for (int o = 16; o; o >>= 1) s += __shfl_xor_sync(0xffffffffu, s, o);
    float inv = 1.0f / fmaxf(sqrtf(s), 1e-12f);
    float4* op = (float4*)(out + (long long)w * D);
    for (int idx = lane; idx < D4; idx += 32) {
        float4 v = ap[idx];
        op[idx] = make_float4(v.x * inv, v.y * inv, v.z * inv, v.w * inv);
    }
}

// ---------------- host ----------------
static float* symaddr(const void* sym) {
    void* p = nullptr;
    cudaGetSymbolAddress(&p, sym);
    return (float*)p;
}

extern "C" void kernel_launch(void* const* d_in, const int* in_sizes, int n_in,
                              void* d_out, int out_size) {
    const int*   batch_x  = (const int*)d_in[0];
    const int*   batch_ei = (const int*)d_in[1];
    const int*   batch_ea = (const int*)d_in[2];
    const int*   batch_gid= (const int*)d_in[3];
    const int*   frag_x   = (const int*)d_in[4];
    const int*   frag_ei  = (const int*)d_in[5];
    const int*   frag_ea  = (const int*)d_in[6];
    const int*   frag_jid = (const int*)d_in[7];
    const int*   jct_gid  = (const int*)d_in[8];
    const float* jmask    = (const float*)d_in[9];
    const float* ae1      = (const float*)d_in[10];
    const float* ae2      = (const float*)d_in[11];
    const float* gW       = (const float*)d_in[12];
    const float* gb       = (const float*)d_in[13];
    const float* gee1     = (const float*)d_in[14];
    const float* gee2     = (const float*)d_in[15];
    const float* bng      = (const float*)d_in[16];
    const float* bnb      = (const float*)d_in[17];
    const float* jW       = (const float*)d_in[18];
    const float* jb       = (const float*)d_in[19];
    const float* jee1     = (const float*)d_in[20];
    const float* jee2     = (const float*)d_in[21];
    const float* memb     = (const float*)d_in[22];

    const int N  = in_sizes[0] / 2;
    const int E  = in_sizes[1] / 2;
    const int NJ = in_sizes[8];
    const int NG = 1024;

    float* buf0   = symaddr(g_buf0);
    float* buf1   = symaddr(g_buf1);
    float* degp   = symaddr(g_deg);
    float* snormp = symaddr(g_snorm);
    float* enormp = symaddr(g_enorm);
    float* statsp = symaddr(g_stats);
    float* scalep = symaddr(g_scale);
    float* shiftp = symaddr(g_shift);
    float* poolp  = symaddr(g_pool);
    float* cntp   = symaddr(g_cnt);
    float* t0p    = symaddr(g_t0);
    float* t1p    = symaddr(g_t1);
    float* f0p    = symaddr(g_f0);
    float* f1p    = symaddr(g_f1);

    auto run_gnn = [&](const int* x, const int* ei, const int* ea) {
        {
            long long tot = (long long)N * D;
            int g = (int)((tot + 255) / 256);
            k_embed<<<g, 256>>>(x, ae1, ae2, buf0, N);
        }
        k_fill<<<(N + 255) / 256, 256>>>(degp, 1.0f, N);   // self-loop contributes 1
        k_degcount<<<(E + 255) / 256, 256>>>(ei, degp, E);
        k_degfin<<<(N + 255) / 256, 256>>>(degp, snormp, N);
        k_enorm<<<(E + 255) / 256, 256>>>(ei, degp, enormp, E);

        for (int l = 0; l < 5; l++) {
            const float* sc = l ? scalep : nullptr;
            const float* sh = l ? shiftp : nullptr;
            dim3 grid((D + 63) / 64, (N + 127) / 128);
            // h_lin = act(buf0) @ W[l]^T + b[l]     (act = BN(l-1) + relu, identity for l=0)
            k_gemm<<<grid, 256>>>(buf0, gW + (long long)l * D * D, buf1, N, D, D,
                                  gb + l * D, nullptr, nullptr, sc, sh, l ? 1 : 0, 1.0f);
            cudaMemsetAsync(buf0, 0, (size_t)N * D * sizeof(float));
            int items = E + N;
            k_scatter<<<(items * 32 + 255) / 256, 256>>>(
                buf1, buf0, ei, ea, enormp, snormp,
                gee1 + (long long)l * 6 * D, gee2 + (long long)l * 3 * D, E, N);
            cudaMemsetAsync(statsp, 0, 2 * D * sizeof(float));
            k_bnstats<<<(N + 255) / 256, 256>>>(buf0, statsp, N);
            k_bnfin<<<1, D>>>(statsp, bng + l * D, bnb + l * D, scalep, shiftp, 1.0f / (float)N);
        }
        // buf0 now holds raw layer-4 aggregation; scale/shift hold layer-4 BN affine (no relu)
    };

    auto run_junction = [&](const float* inbuf, int M) {
        dim3 g1((D + 63) / 64, (M + 127) / 128);
        // conv0: out = in @ W0^T + b0 + (jee1[0][4] + jee2[0][0])
        k_gemm<<<g1, 256>>>(inbuf, jW, t0p, M, D, D,
                            jb, jee1 + 4 * D, jee2, nullptr, nullptr, 0, 1.0f);
        // conv1: out = relu(t0) @ W1^T + b1 + (jee1[1][4] + jee2[1][0])
        k_gemm<<<g1, 256>>>(t0p, jW + (long long)D * D, t1p, M, D, D,
                            jb + D, jee1 + (6 + 4) * D, jee2 + 3 * D, nullptr, nullptr, 1, 1.0f);
    };

    // ---------- branch 0: whole molecules ----------
    run_gnn(batch_x, batch_ei, batch_ea);
    cudaMemsetAsync(poolp, 0, (size_t)NG * D * sizeof(float));
    cudaMemsetAsync(cntp, 0, NG * sizeof(float));
    k_pool<<<(N * 32 + 255) / 256, 256>>>(buf0, batch_gid, poolp, cntp, scalep, shiftp, N);
    k_pooldiv<<<(NG * D + 255) / 256, 256>>>(poolp, cntp, NG * D);
    run_junction(poolp, NG);
    k_l2norm<<<(NG * 32 + 255) / 256, 256>>>(t1p, f0p, NG);

    // ---------- branch 1: fragments -> junctions ----------
    run_gnn(frag_x, frag_ei, frag_ea);
    cudaMemsetAsync(poolp, 0, (size_t)NJ * D * sizeof(float));
    cudaMemsetAsync(cntp, 0, NJ * sizeof(float));
    k_pool<<<(N * 32 + 255) / 256, 256>>>(buf0, frag_jid, poolp, cntp, scalep, shiftp, N);
    k_pooldiv<<<(NJ * D + 255) / 256, 256>>>(poolp, cntp, NJ * D);
    k_mask<<<(NJ * D + 255) / 256, 256>>>(poolp, jmask, memb, NJ * D);
    run_junction(poolp, NJ);
    cudaMemsetAsync(poolp, 0, (size_t)NG * D * sizeof(float));
    cudaMemsetAsync(cntp, 0, NG * sizeof(float));
    k_pool<<<(NJ * 32 + 255) / 256, 256>>>(t1p, jct_gid, poolp, cntp, nullptr, nullptr, NJ);
    k_pooldiv<<<(NG * D + 255) / 256, 256>>>(poolp, cntp, NG * D);
    k_l2norm<<<(NG * 32 + 255) / 256, 256>>>(poolp, f1p, NG);

    // ---------- logits = (f0 @ f1^T) / TEMP ----------
    {
        dim3 gl((NG + 63) / 64, (NG + 127) / 128);
        k_gemm<<<gl, 256>>>(f0p, f1p, (float*)d_out, NG, NG, D,
                            nullptr, nullptr, nullptr, nullptr, nullptr, 0, 25.0f);
    }
}

// round 9
// speedup vs baseline: 1.0352x; 1.0352x over previous
#include <cuda_runtime.h>
#include <cuda_bf16.h>
#include <cstdint>
#include <cstdio>

#define D    300
#define D4   75
#define MAXN 200000
#define MAXE 400000
#define NGR  1024
#define NJC  8192

#define KP    320                 // padded K for bf16 weight buffers
#define NPAD  384                 // padded N rows (3 tiles of 128)
#define WMAT  (NPAD * KP)         // elems per padded weight matrix
#define ASTR  40                  // smem row stride in bf16 (32 + 8 pad)

// ---------------- scratch (static device memory; no allocs) ----------------
__device__ __align__(16) float g_buf0[(size_t)MAXN * D + 16];
__device__ __align__(16) float g_buf1[(size_t)MAXN * D + 16];
__device__ float g_deg[MAXN];
__device__ float g_snorm[MAXN];
__device__ float g_enorm[MAXE];
__device__ float g_stats[2 * D];
__device__ float g_scale[D];
__device__ float g_shift[D];
__device__ __align__(16) float g_pool[(size_t)NJC * D];
__device__ float g_cnt[NJC];
__device__ __align__(16) float g_t0[(size_t)NJC * D];
__device__ __align__(16) float g_t1[(size_t)NJC * D];
__device__ __align__(16) float g_f0[(size_t)NGR * D];
__device__ __align__(16) float g_f1[(size_t)NGR * D];
// bf16 hi/lo split of the 7 weight matrices (5 gnn + 2 junction), zero-padded
__device__ __align__(16) __nv_bfloat16 g_wh[(size_t)7 * WMAT];
__device__ __align__(16) __nv_bfloat16 g_wl[(size_t)7 * WMAT];

// ====================== helpers ======================
__device__ __forceinline__ uint32_t smem_u32(const void* p) {
    uint32_t a;
    asm("{ .reg .u64 t; cvta.to.shared.u64 t, %1; cvt.u32.u64 %0, t; }" : "=r"(a) : "l"(p));
    return a;
}

#define LDMX4(r, addr) \
    asm volatile("ldmatrix.sync.aligned.m8n8.x4.shared.b16 {%0,%1,%2,%3}, [%4];" \
        : "=r"((r)[0]), "=r"((r)[1]), "=r"((r)[2]), "=r"((r)[3]) : "r"(addr))

__device__ __forceinline__ void mma16816(float* c, const uint32_t* a,
                                         uint32_t b0, uint32_t b1) {
    asm volatile(
        "mma.sync.aligned.m16n8k16.row.col.f32.bf16.bf16.f32 "
        "{%0,%1,%2,%3},{%4,%5,%6,%7},{%8,%9},{%0,%1,%2,%3};"
        : "+f"(c[0]), "+f"(c[1]), "+f"(c[2]), "+f"(c[3])
        : "r"(a[0]), "r"(a[1]), "r"(a[2]), "r"(a[3]), "r"(b0), "r"(b1));
}

__device__ __forceinline__ uint32_t pack_bf(float a, float b) {
    __nv_bfloat162 t = __floats2bfloat162_rn(a, b);
    return *(uint32_t*)&t;
}

// ======== tensor GEMM (mma.sync bf16 3-term split) ========
// C[M,Nc] = oscale*(act(A)[M,300] @ Wsplit^T + bias + e1 + e2)
// act(v)[k] = relu_opt(scale[k]*v + shift[k])
__global__ __launch_bounds__(256) void k_mma(
    const float* __restrict__ A, const __nv_bfloat16* __restrict__ Bh,
    const __nv_bfloat16* __restrict__ Bl, float* __restrict__ C,
    int M, int Nc,
    const float* __restrict__ bias, const float* __restrict__ e1, const float* __restrict__ e2,
    const float* __restrict__ scale, const float* __restrict__ shift, int relu, float oscale)
{
    __shared__ __nv_bfloat16 sAh_[128 * ASTR], sAl_[128 * ASTR];
    __shared__ __nv_bfloat16 sBh_[128 * ASTR], sBl_[128 * ASTR];

    const int tid = threadIdx.x, lane = tid & 31, warp = tid >> 5;
    const int m0 = blockIdx.y * 128, n0 = blockIdx.x * 128;
    const int warp_m = (warp & 1) * 64, warp_n = (warp >> 1) * 32;

    const uint32_t sAh = smem_u32(sAh_), sAl = smem_u32(sAl_);
    const uint32_t sBh = smem_u32(sBh_), sBl = smem_u32(sBl_);

    // ldmatrix address bases
    const int g = lane >> 3, r = lane & 7;
    const int aRowB = warp_m + (g & 1) * 8 + r;     // + mt*16
    const int aColB = (g >> 1) * 8;                 // + kh
    const int bRowB = warp_n + (g >> 1) * 8 + r;    // + bt*16
    const int bColB = (g & 1) * 8;                  // + kh

    float acc[4][4][4];
#pragma unroll
    for (int i = 0; i < 4; i++)
#pragma unroll
        for (int j = 0; j < 4; j++)
#pragma unroll
            for (int q = 0; q < 4; q++) acc[i][j][q] = 0.f;

    const int row = tid >> 1, half = tid & 1;
    const int gm = m0 + row;

    for (int kt = 0; kt < KP / 32; kt++) {
        const int k0 = kt * 32;
        // ---- stage A: act -> hi/lo split ----
        {
            const int gkb = k0 + half * 16;
            float x[16];
#pragma unroll
            for (int q = 0; q < 16; q += 4) {
                int k = gkb + q;
                if (gm < M && k + 3 < D) {
                    float4 v = *(const float4*)(A + (long long)gm * D + k);
                    x[q] = v.x; x[q + 1] = v.y; x[q + 2] = v.z; x[q + 3] = v.w;
                } else {
#pragma unroll
                    for (int j = 0; j < 4; j++)
                        x[q + j] = (gm < M && k + j < D) ? A[(long long)gm * D + k + j] : 0.f;
                }
            }
            uint32_t uh[8], ul[8];
#pragma unroll
            for (int q = 0; q < 16; q += 2) {
                float x0 = x[q], x1 = x[q + 1];
                int k = gkb + q;
                if (k < D && gm < M) {
                    if (scale) x0 = fmaf(x0, scale[k], shift[k]);
                    if (relu)  x0 = fmaxf(x0, 0.f);
                } else x0 = 0.f;
                if (k + 1 < D && gm < M) {
                    if (scale) x1 = fmaf(x1, scale[k + 1], shift[k + 1]);
                    if (relu)  x1 = fmaxf(x1, 0.f);
                } else x1 = 0.f;
                float h0 = __bfloat162float(__float2bfloat16_rn(x0));
                float h1 = __bfloat162float(__float2bfloat16_rn(x1));
                uh[q >> 1] = pack_bf(h0, h1);
                ul[q >> 1] = pack_bf(x0 - h0, x1 - h1);
            }
            uint32_t off = (uint32_t)(row * ASTR + half * 16) * 2;
            *(uint4*)((char*)sAh_ + off)      = make_uint4(uh[0], uh[1], uh[2], uh[3]);
            *(uint4*)((char*)sAh_ + off + 16) = make_uint4(uh[4], uh[5], uh[6], uh[7]);
            *(uint4*)((char*)sAl_ + off)      = make_uint4(ul[0], ul[1], ul[2], ul[3]);
            *(uint4*)((char*)sAl_ + off + 16) = make_uint4(ul[4], ul[5], ul[6], ul[7]);
        }
        // ---- stage B from padded pre-split bf16 ----
        {
            long long gi = (long long)(n0 + row) * KP + k0 + half * 16;
            uint4 h0 = *(const uint4*)(Bh + gi);
            uint4 h1 = *(const uint4*)(Bh + gi + 8);
            uint4 l0 = *(const uint4*)(Bl + gi);
            uint4 l1 = *(const uint4*)(Bl + gi + 8);
            uint32_t off = (uint32_t)(row * ASTR + half * 16) * 2;
            *(uint4*)((char*)sBh_ + off)      = h0;
            *(uint4*)((char*)sBh_ + off + 16) = h1;
            *(uint4*)((char*)sBl_ + off)      = l0;
            *(uint4*)((char*)sBl_ + off + 16) = l1;
        }
        __syncthreads();

#pragma unroll
        for (int kh = 0; kh < 32; kh += 16) {
            uint32_t ah[4][4], al[4][4];
#pragma unroll
            for (int mt = 0; mt < 4; mt++) {
                uint32_t off = (uint32_t)((aRowB + mt * 16) * ASTR + kh + aColB) * 2;
                LDMX4(ah[mt], sAh + off);
                LDMX4(al[mt], sAl + off);
            }
            uint32_t bh2[2][4], bl2[2][4];
#pragma unroll
            for (int bt = 0; bt < 2; bt++) {
                uint32_t off = (uint32_t)((bRowB + bt * 16) * ASTR + kh + bColB) * 2;
                LDMX4(bh2[bt], sBh + off);
                LDMX4(bl2[bt], sBl + off);
            }
#pragma unroll
            for (int mt = 0; mt < 4; mt++)
#pragma unroll
                for (int nt = 0; nt < 4; nt++) {
                    uint32_t bH0 = bh2[nt >> 1][(nt & 1) * 2];
                    uint32_t bH1 = bh2[nt >> 1][(nt & 1) * 2 + 1];
                    uint32_t bL0 = bl2[nt >> 1][(nt & 1) * 2];
                    uint32_t bL1 = bl2[nt >> 1][(nt & 1) * 2 + 1];
                    mma16816(acc[mt][nt], ah[mt], bH0, bH1);
                    mma16816(acc[mt][nt], al[mt], bH0, bH1);
                    mma16816(acc[mt][nt], ah[mt], bL0, bL1);
                }
        }
        __syncthreads();
    }

    // ---- epilogue ----
#pragma unroll
    for (int nt = 0; nt < 4; nt++) {
        int gn = n0 + warp_n + nt * 8 + (lane & 3) * 2;
        if (gn >= Nc) continue;
        float add0 = 0.f, add1 = 0.f;
        if (bias) { add0 += bias[gn]; add1 += bias[gn + 1]; }
        if (e1)   { add0 += e1[gn] + e2[gn]; add1 += e1[gn + 1] + e2[gn + 1]; }
#pragma unroll
        for (int mt = 0; mt < 4; mt++) {
            int gr0 = m0 + warp_m + mt * 16 + (lane >> 2);
            float* cbase = C + (long long)gr0 * Nc + gn;
            if (gr0 < M) {
                float2 o = make_float2((acc[mt][nt][0] + add0) * oscale,
                                       (acc[mt][nt][1] + add1) * oscale);
                *(float2*)cbase = o;
            }
            if (gr0 + 8 < M) {
                float2 o = make_float2((acc[mt][nt][2] + add0) * oscale,
                                       (acc[mt][nt][3] + add1) * oscale);
                *(float2*)(cbase + (long long)8 * Nc) = o;
            }
        }
    }
}

// ---- split fp32 weights into padded bf16 hi/lo ----
__global__ void k_wsplit(const float* __restrict__ W, __nv_bfloat16* __restrict__ bh,
                         __nv_bfloat16* __restrict__ bl, int nmat) {
    int idx = blockIdx.x * blockDim.x + threadIdx.x;
    if (idx >= nmat * WMAT) return;
    int m = idx / WMAT, rr = idx - m * WMAT;
    int n = rr / KP, k = rr - n * KP;
    float v = (n < D && k < D) ? W[(long long)m * D * D + n * D + k] : 0.f;
    __nv_bfloat16 h = __float2bfloat16_rn(v);
    bh[idx] = h;
    bl[idx] = __float2bfloat16_rn(v - __bfloat162float(h));
}

// ---------------- small utility kernels ----------------
__global__ void k_embed(const int* __restrict__ x, const float* __restrict__ ae1,
                        const float* __restrict__ ae2, float* __restrict__ out, int n) {
    int idx = blockIdx.x * blockDim.x + threadIdx.x;
    if (idx >= n * D) return;
    int node = idx / D;
    int c = idx - node * D;
    out[idx] = ae1[x[node * 2] * D + c] + ae2[x[node * 2 + 1] * D + c];
}

__global__ void k_fill(float* p, float v, int n) {
    int i = blockIdx.x * blockDim.x + threadIdx.x;
    if (i < n) p[i] = v;
}

__global__ void k_degcount(const int* __restrict__ ei, float* __restrict__ deg, int E) {
    int i = blockIdx.x * blockDim.x + threadIdx.x;
    if (i < E) atomicAdd(&deg[ei[i]], 1.0f);
}

__global__ void k_degfin(float* __restrict__ deg, float* __restrict__ snorm, int n) {
    int i = blockIdx.x * blockDim.x + threadIdx.x;
    if (i >= n) return;
    float v = rsqrtf(deg[i]);
    deg[i] = v;
    snorm[i] = v * v;
}

__global__ void k_enorm(const int* __restrict__ ei, const float* __restrict__ dinv,
                        float* __restrict__ enorm, int E) {
    int i = blockIdx.x * blockDim.x + threadIdx.x;
    if (i < E) enorm[i] = dinv[ei[i]] * dinv[ei[E + i]];
}

// ---------------- FFMA2 GEMM (kept for the tiny exact-fp32 logits GEMM) ----------------
__global__ __launch_bounds__(256) void k_gemm(
    const float* __restrict__ A, const float* __restrict__ B, float* __restrict__ C,
    int M, int Nc, int K,
    const float* __restrict__ bias, const float* __restrict__ e1, const float* __restrict__ e2,
    const float* __restrict__ scale, const float* __restrict__ shift,
    int relu, float oscale)
{
    __shared__ float As[32][130];
    __shared__ float Bs[32][68];

    const int tid = threadIdx.x;
    const int tx = tid & 15, ty = tid >> 4;
    const int m0 = blockIdx.y * 128, n0 = blockIdx.x * 64;

    unsigned long long acc[4][4];
#pragma unroll
    for (int i = 0; i < 4; i++)
#pragma unroll
        for (int j = 0; j < 4; j++) acc[i][j] = 0ull;

    const int nk = (K + 31) >> 5;
    for (int kt = 0; kt < nk; kt++) {
        const int k0 = kt << 5;
#pragma unroll
        for (int i = 0; i < 4; i++) {
            int e = i * 256 + tid;
            int k4 = e & 7, rr = e >> 3;
            int gmm = m0 + rr, gk = k0 + 4 * k4;
            float4 v = make_float4(0.f, 0.f, 0.f, 0.f);
            if (gmm < M && gk < K) {
                v = *(const float4*)(A + (long long)gmm * K + gk);
                if (scale) {
                    v.x = fmaf(v.x, scale[gk], shift[gk]);
                    v.y = fmaf(v.y, scale[gk + 1], shift[gk + 1]);
                    v.z = fmaf(v.z, scale[gk + 2], shift[gk + 2]);
                    v.w = fmaf(v.w, scale[gk + 3], shift[gk + 3]);
                }
                if (relu) {
                    v.x = fmaxf(v.x, 0.f); v.y = fmaxf(v.y, 0.f);
                    v.z = fmaxf(v.z, 0.f); v.w = fmaxf(v.w, 0.f);
                }
            }
            As[4 * k4 + 0][rr] = v.x; As[4 * k4 + 1][rr] = v.y;
            As[4 * k4 + 2][rr] = v.z; As[4 * k4 + 3][rr] = v.w;
        }
#pragma unroll
        for (int i = 0; i < 2; i++) {
            int e = i * 256 + tid;
            int k4 = e & 7, rr = e >> 3;
            int gn = n0 + rr, gk = k0 + 4 * k4;
            float4 v = make_float4(0.f, 0.f, 0.f, 0.f);
            if (gn < Nc && gk < K)
                v = *(const float4*)(B + (long long)gn * K + gk);
            Bs[4 * k4 + 0][rr] = v.x; Bs[4 * k4 + 1][rr] = v.y;
            Bs[4 * k4 + 2][rr] = v.z; Bs[4 * k4 + 3][rr] = v.w;
        }
        __syncthreads();
#pragma unroll
        for (int kk = 0; kk < 32; kk++) {
            unsigned long long a2[4];
#pragma unroll
            for (int i = 0; i < 4; i++)
                a2[i] = *(const unsigned long long*)&As[kk][ty * 8 + 2 * i];
            float4 bv = *(const float4*)&Bs[kk][tx * 4];
            unsigned long long b2[4];
            {
                unsigned u0 = __float_as_uint(bv.x), u1 = __float_as_uint(bv.y);
                unsigned u2 = __float_as_uint(bv.z), u3 = __float_as_uint(bv.w);
                asm("mov.b64 %0, {%1,%1};" : "=l"(b2[0]) : "r"(u0));
                asm("mov.b64 %0, {%1,%1};" : "=l"(b2[1]) : "r"(u1));
                asm("mov.b64 %0, {%1,%1};" : "=l"(b2[2]) : "r"(u2));
                asm("mov.b64 %0, {%1,%1};" : "=l"(b2[3]) : "r"(u3));
            }
#pragma unroll
            for (int i = 0; i < 4; i++)
#pragma unroll
                for (int j = 0; j < 4; j++)
                    asm("fma.rn.f32x2 %0, %1, %2, %3;"
                        : "=l"(acc[i][j]) : "l"(a2[i]), "l"(b2[j]), "l"(acc[i][j]));
        }
        __syncthreads();
    }

#pragma unroll
    for (int i = 0; i < 4; i++) {
#pragma unroll
        for (int j = 0; j < 4; j++) {
            int gn = n0 + tx * 4 + j;
            if (gn >= Nc) continue;
            float lo = __uint_as_float((unsigned)(acc[i][j] & 0xffffffffull));
            float hi = __uint_as_float((unsigned)(acc[i][j] >> 32));
            float add = 0.f;
            if (bias) add += bias[gn];
            if (e1) add += e1[gn] + e2[gn];
            int gmm = m0 + ty * 8 + 2 * i;
            if (gmm < M)     C[(long long)gmm * Nc + gn] = (lo + add) * oscale;
            if (gmm + 1 < M) C[(long long)(gmm + 1) * Nc + gn] = (hi + add) * oscale;
        }
    }
}

// ---------------- scatter ----------------
__global__ void k_scatter(const float* __restrict__ T, float* __restrict__ AGG,
                          const int* __restrict__ ei, const int* __restrict__ ea,
                          const float* __restrict__ enorm, const float* __restrict__ snorm,
                          const float* __restrict__ ee1, const float* __restrict__ ee2,
                          int E, int N)
{
    int w = (blockIdx.x * blockDim.x + threadIdx.x) >> 5;
    int lane = threadIdx.x & 31;
    if (w >= E + N) return;
    int src, dst, bt, bd;
    float nrm;
    if (w < E) {
        src = ei[w]; dst = ei[E + w];
        bt = ea[2 * w]; bd = ea[2 * w + 1];
        nrm = enorm[w];
    } else {
        src = dst = w - E; bt = 4; bd = 0;
        nrm = snorm[w - E];
    }
    const float4* ts = (const float4*)(T + (long long)src * D);
    const float4* p1 = (const float4*)(ee1 + bt * D);
    const float4* p2 = (const float4*)(ee2 + bd * D);
    float* outp = AGG + (long long)dst * D;
    for (int idx = lane; idx < D4; idx += 32) {
        float4 v = ts[idx], a = p1[idx], b = p2[idx];
        float x = nrm * (v.x + a.x + b.x);
        float y = nrm * (v.y + a.y + b.y);
        float z = nrm * (v.z + a.z + b.z);
        float ww = nrm * (v.w + a.w + b.w);
        asm volatile("red.global.add.v4.f32 [%0], {%1,%2,%3,%4};"
                     :: "l"(outp + 4 * idx), "f"(x), "f"(y), "f"(z), "f"(ww) : "memory");
    }
}

// ---------------- BN stats / finalize ----------------
__global__ void k_bnstats(const float* __restrict__ A, float* __restrict__ st, int n) {
    int r0 = blockIdx.x * 256;
    int rend = min(r0 + 256, n);
    for (int c = threadIdx.x; c < D; c += 256) {
        float s = 0.f, q = 0.f;
#pragma unroll 4
        for (int rr = r0; rr < rend; rr++) {
            float v = A[(long long)rr * D + c];
            s += v;
            q = fmaf(v, v, q);
        }
        atomicAdd(&st[c], s);
        atomicAdd(&st[D + c], q);
    }
}

__global__ void k_bnfin(const float* __restrict__ st, const float* __restrict__ gamma,
                        const float* __restrict__ beta, float* __restrict__ sc,
                        float* __restrict__ sh, float invn) {
    int c = threadIdx.x;
    if (c >= D) return;
    float mean = st[c] * invn;
    float var = fmaxf(st[D + c] * invn - mean * mean, 0.f);
    float s = gamma[c] / sqrtf(var + 1e-5f);
    sc[c] = s;
    sh[c] = beta[c] - mean * s;
}

// ---------------- mean pooling ----------------
__global__ void k_pool(const float* __restrict__ A, const int* __restrict__ ids,
                       float* __restrict__ pool, float* __restrict__ cnt,
                       const float* __restrict__ scale, const float* __restrict__ shift, int n)
{
    int w = (blockIdx.x * blockDim.x + threadIdx.x) >> 5;
    int lane = threadIdx.x & 31;
    if (w >= n) return;
    int id = ids[w];
    if (lane == 0) atomicAdd(&cnt[id], 1.0f);
    const float4* ap = (const float4*)(A + (long long)w * D);
    float* op = pool + (long long)id * D;
    for (int idx = lane; idx < D4; idx += 32) {
        float4 v = ap[idx];
        if (scale) {
            int c = 4 * idx;
            v.x = fmaf(v.x, scale[c], shift[c]);
            v.y = fmaf(v.y, scale[c + 1], shift[c + 1]);
            v.z = fmaf(v.z, scale[c + 2], shift[c + 2]);
            v.w = fmaf(v.w, scale[c + 3], shift[c + 3]);
        }
        asm volatile("red.global.add.v4.f32 [%0], {%1,%2,%3,%4};"
                     :: "l"(op + 4 * idx), "f"(v.x), "f"(v.y), "f"(v.z), "f"(v.w) : "memory");
    }
}

__global__ void k_pooldiv(float* __restrict__ pool, const float* __restrict__ cnt, int total) {
    int i = blockIdx.x * blockDim.x + threadIdx.x;
    if (i < total) pool[i] /= fmaxf(cnt[i / D], 1.0f);
}

__global__ void k_mask(float* __restrict__ pool, const float* __restrict__ mask,
                       const float* __restrict__ memb, int total) {
    int i = blockIdx.x * blockDim.x + threadIdx.x;
    if (i < total && mask[i / D] > 0.5f) pool[i] = memb[i % D];
}

__global__ void k_l2norm(const float* __restrict__ A, float* __restrict__ out, int n) {
    int w = (blockIdx.x * blockDim.x + threadIdx.x) >> 5;
    int lane = threadIdx.x & 31;
    if (w >= n) return;
    const float4* ap = (const float4*)(A + (long long)w * D);
    float s = 0.f;
    for (int idx = lane; idx < D4; idx += 32) {
        float4 v = ap[idx];
        s += v.x * v.x + v.y * v.y + v.z * v.z + v.w * v.w;
    }
#pragma unroll
    for (int o = 16; o; o >>= 1) s += __shfl_xor_sync(0xffffffffu, s, o);
    float inv = 1.0f / fmaxf(sqrtf(s), 1e-12f);
    float4* op = (float4*)(out + (long long)w * D);
    for (int idx = lane; idx < D4; idx += 32) {
        float4 v = ap[idx];
        op[idx] = make_float4(v.x * inv, v.y * inv, v.z * inv, v.w * inv);
    }
}

// ---------------- host ----------------
static float* symaddr(const void* sym) {
    void* p = nullptr;
    cudaGetSymbolAddress(&p, sym);
    return (float*)p;
}

extern "C" void kernel_launch(void* const* d_in, const int* in_sizes, int n_in,
                              void* d_out, int out_size) {
    const int*   batch_x  = (const int*)d_in[0];
    const int*   batch_ei = (const int*)d_in[1];
    const int*   batch_ea = (const int*)d_in[2];
    const int*   batch_gid= (const int*)d_in[3];
    const int*   frag_x   = (const int*)d_in[4];
    const int*   frag_ei  = (const int*)d_in[5];
    const int*   frag_ea  = (const int*)d_in[6];
    const int*   frag_jid = (const int*)d_in[7];
    const int*   jct_gid  = (const int*)d_in[8];
    const float* jmask    = (const float*)d_in[9];
    const float* ae1      = (const float*)d_in[10];
    const float* ae2      = (const float*)d_in[11];
    const float* gW       = (const float*)d_in[12];
    const float* gb       = (const float*)d_in[13];
    const float* gee1     = (const float*)d_in[14];
    const float* gee2     = (const float*)d_in[15];
    const float* bng      = (const float*)d_in[16];
    const float* bnb      = (const float*)d_in[17];
    const float* jW       = (const float*)d_in[18];
    const float* jb       = (const float*)d_in[19];
    const float* jee1     = (const float*)d_in[20];
    const float* jee2     = (const float*)d_in[21];
    const float* memb     = (const float*)d_in[22];

    const int N  = in_sizes[0] / 2;
    const int E  = in_sizes[1] / 2;
    const int NJ = in_sizes[8];
    const int NG = 1024;

    float* buf0   = symaddr(g_buf0);
    float* buf1   = symaddr(g_buf1);
    float* degp   = symaddr(g_deg);
    float* snormp = symaddr(g_snorm);
    float* enormp = symaddr(g_enorm);
    float* statsp = symaddr(g_stats);
    float* scalep = symaddr(g_scale);
    float* shiftp = symaddr(g_shift);
    float* poolp  = symaddr(g_pool);
    float* cntp   = symaddr(g_cnt);
    float* t0p    = symaddr(g_t0);
    float* t1p    = symaddr(g_t1);
    float* f0p    = symaddr(g_f0);
    float* f1p    = symaddr(g_f1);
    __nv_bfloat16* whp = (__nv_bfloat16*)symaddr(g_wh);
    __nv_bfloat16* wlp = (__nv_bfloat16*)symaddr(g_wl);

    // pre-split weights: gnn (5 mats) -> slots 0..4, jct (2 mats) -> slots 5..6
    k_wsplit<<<(5 * WMAT + 255) / 256, 256>>>(gW, whp, wlp, 5);
    k_wsplit<<<(2 * WMAT + 255) / 256, 256>>>(jW, whp + (size_t)5 * WMAT, wlp + (size_t)5 * WMAT, 2);

    auto tgemm = [&](const float* A, int mat, float* C, int M,
                     const float* bias, const float* e1, const float* e2,
                     const float* sc, const float* sh, int relu) {
        dim3 grid((D + 127) / 128, (M + 127) / 128);
        k_mma<<<grid, 256>>>(A, whp + (size_t)mat * WMAT, wlp + (size_t)mat * WMAT,
                             C, M, D, bias, e1, e2, sc, sh, relu, 1.0f);
    };

    auto run_gnn = [&](const int* x, const int* ei, const int* ea) {
        {
            long long tot = (long long)N * D;
            int g = (int)((tot + 255) / 256);
            k_embed<<<g, 256>>>(x, ae1, ae2, buf0, N);
        }
        k_fill<<<(N + 255) / 256, 256>>>(degp, 1.0f, N);
        k_degcount<<<(E + 255) / 256, 256>>>(ei, degp, E);
        k_degfin<<<(N + 255) / 256, 256>>>(degp, snormp, N);
        k_enorm<<<(E + 255) / 256, 256>>>(ei, degp, enormp, E);

        for (int l = 0; l < 5; l++) {
            const float* sc = l ? scalep : nullptr;
            const float* sh = l ? shiftp : nullptr;
            tgemm(buf0, l, buf1, N, gb + l * D, nullptr, nullptr, sc, sh, l ? 1 : 0);
            cudaMemsetAsync(buf0, 0, (size_t)N * D * sizeof(float));
            int items = E + N;
            k_scatter<<<(items * 32 + 255) / 256, 256>>>(
                buf1, buf0, ei, ea, enormp, snormp,
                gee1 + (long long)l * 6 * D, gee2 + (long long)l * 3 * D, E, N);
            cudaMemsetAsync(statsp, 0, 2 * D * sizeof(float));
            k_bnstats<<<(N + 255) / 256, 256>>>(buf0, statsp, N);
            k_bnfin<<<1, D>>>(statsp, bng + l * D, bnb + l * D, scalep, shiftp, 1.0f / (float)N);
        }
    };

    auto run_junction = [&](const float* inbuf, int M) {
        tgemm(inbuf, 5, t0p, M, jb, jee1 + 4 * D, jee2, nullptr, nullptr, 0);
        tgemm(t0p, 6, t1p, M, jb + D, jee1 + (6 + 4) * D, jee2 + 3 * D, nullptr, nullptr, 1);
    };

    // ---------- branch 0 ----------
    run_gnn(batch_x, batch_ei, batch_ea);
    cudaMemsetAsync(poolp, 0, (size_t)NG * D * sizeof(float));
    cudaMemsetAsync(cntp, 0, NG * sizeof(float));
    k_pool<<<(N * 32 + 255) / 256, 256>>>(buf0, batch_gid, poolp, cntp, scalep, shiftp, N);
    k_pooldiv<<<(NG * D + 255) / 256, 256>>>(poolp, cntp, NG * D);
    run_junction(poolp, NG);
    k_l2norm<<<(NG * 32 + 255) / 256, 256>>>(t1p, f0p, NG);

    // ---------- branch 1 ----------
    run_gnn(frag_x, frag_ei, frag_ea);
    cudaMemsetAsync(poolp, 0, (size_t)NJ * D * sizeof(float));
    cudaMemsetAsync(cntp, 0, NJ * sizeof(float));
    k_pool<<<(N * 32 + 255) / 256, 256>>>(buf0, frag_jid, poolp, cntp, scalep, shiftp, N);
    k_pooldiv<<<(NJ * D + 255) / 256, 256>>>(poolp, cntp, NJ * D);
    k_mask<<<(NJ * D + 255) / 256, 256>>>(poolp, jmask, memb, NJ * D);
    run_junction(poolp, NJ);
    cudaMemsetAsync(poolp, 0, (size_t)NG * D * sizeof(float));
    cudaMemsetAsync(cntp, 0, NG * sizeof(float));
    k_pool<<<(NJ * 32 + 255) / 256, 256>>>(t1p, jct_gid, poolp, cntp, nullptr, nullptr, NJ);
    k_pooldiv<<<(NG * D + 255) / 256, 256>>>(poolp, cntp, NG * D);
    k_l2norm<<<(NG * 32 + 255) / 256, 256>>>(poolp, f1p, NG);

    // ---------- logits ----------
    {
        dim3 gl((NG + 63) / 64, (NG + 127) / 128);
        k_gemm<<<gl, 256>>>(f0p, f1p, (float*)d_out, NG, NG, D,
                            nullptr, nullptr, nullptr, nullptr, nullptr, 0, 25.0f);
    }
}

// round 10
// speedup vs baseline: 1.1886x; 1.1482x over previous
#include <cuda_runtime.h>
#include <cuda_bf16.h>
#include <cstdint>
#include <cstdio>

#define D    300
#define D4   75
#define MAXN 200000
#define MAXE 400000
#define NGR  1024
#define NJC  8192

#define KP    320                 // padded K for bf16 weight buffers
#define NPAD  320                 // padded N rows (2x128 + 1x64)
#define WMAT  (NPAD * KP)         // elems per padded weight matrix
#define ASTRA 328                 // A smem row stride (bf16): 320 + 8
#define ASTRB 40                  // B smem row stride (bf16): 32 + 8

// dynamic smem bytes for k_mma: A hi/lo 128x328 + B hi/lo 128x40, bf16
#define MMA_SMEM ((2 * 128 * ASTRA + 2 * 128 * ASTRB) * 2)

// ---------------- scratch (static device memory; no allocs) ----------------
__device__ __align__(16) float g_buf0[(size_t)MAXN * D + 16];
__device__ __align__(16) float g_buf1[(size_t)MAXN * D + 16];
__device__ float g_deg[MAXN];
__device__ float g_snorm[MAXN];
__device__ float g_enorm[MAXE];
__device__ float g_stats[2 * D];
__device__ float g_scale[D];
__device__ float g_shift[D];
__device__ __align__(16) float g_pool[(size_t)NJC * D];
__device__ float g_cnt[NJC];
__device__ __align__(16) float g_t0[(size_t)NJC * D];
__device__ __align__(16) float g_t1[(size_t)NJC * D];
__device__ __align__(16) float g_f0[(size_t)NGR * D];
__device__ __align__(16) float g_f1[(size_t)NGR * D];
// bf16 hi/lo split of the 7 weight matrices (5 gnn + 2 junction), zero-padded
__device__ __align__(16) __nv_bfloat16 g_wh[(size_t)7 * WMAT];
__device__ __align__(16) __nv_bfloat16 g_wl[(size_t)7 * WMAT];
// CSR (dst-sorted) edge structures
__device__ int  g_rowptr[MAXN + 1];
__device__ int  g_cursor[MAXN];
__device__ int  g_bsum[256];
__device__ __align__(16) int4 g_epack[MAXE];   // {src, bt, bd, bitcast(norm)}

// ====================== helpers ======================
__device__ __forceinline__ uint32_t smem_u32(const void* p) {
    uint32_t a;
    asm("{ .reg .u64 t; cvta.to.shared.u64 t, %1; cvt.u32.u64 %0, t; }" : "=r"(a) : "l"(p));
    return a;
}

#define LDMX4(r, addr) \
    asm volatile("ldmatrix.sync.aligned.m8n8.x4.shared.b16 {%0,%1,%2,%3}, [%4];" \
        : "=r"((r)[0]), "=r"((r)[1]), "=r"((r)[2]), "=r"((r)[3]) : "r"(addr))

__device__ __forceinline__ void mma16816(float* c, const uint32_t* a,
                                         uint32_t b0, uint32_t b1) {
    asm volatile(
        "mma.sync.aligned.m16n8k16.row.col.f32.bf16.bf16.f32 "
        "{%0,%1,%2,%3},{%4,%5,%6,%7},{%8,%9},{%0,%1,%2,%3};"
        : "+f"(c[0]), "+f"(c[1]), "+f"(c[2]), "+f"(c[3])
        : "r"(a[0]), "r"(a[1]), "r"(a[2]), "r"(a[3]), "r"(b0), "r"(b1));
}

__device__ __forceinline__ uint32_t pack_bf(float a, float b) {
    __nv_bfloat162 t = __floats2bfloat162_rn(a, b);
    return *(uint32_t*)&t;
}

// ======== A-resident tensor GEMM (mma.sync bf16 3-term split) ========
// C[M,300] = oscale*(act(A)[M,300] @ Wsplit^T + bias + e1 + e2)
// act(v)[k] = relu_opt(scale[k]*v + shift[k]).  One CTA per 128 rows; A staged
// (with act + hi/lo split) ONCE into smem, then looped over n-tiles {128,128,64}.
__global__ __launch_bounds__(256) void k_mma(
    const float* __restrict__ A, const __nv_bfloat16* __restrict__ Bh,
    const __nv_bfloat16* __restrict__ Bl, float* __restrict__ C,
    int M, int Nc,
    const float* __restrict__ bias, const float* __restrict__ e1, const float* __restrict__ e2,
    const float* __restrict__ scale, const float* __restrict__ shift, int relu, float oscale)
{
    extern __shared__ char dsm[];
    __nv_bfloat16* sAh_ = (__nv_bfloat16*)dsm;
    __nv_bfloat16* sAl_ = sAh_ + 128 * ASTRA;
    __nv_bfloat16* sBh_ = sAl_ + 128 * ASTRA;
    __nv_bfloat16* sBl_ = sBh_ + 128 * ASTRB;

    const int tid = threadIdx.x, lane = tid & 31, warp = tid >> 5;
    const int m0 = blockIdx.x * 128;
    const int warp_m = (warp & 1) * 64;

    const uint32_t sAh = smem_u32(sAh_), sAl = smem_u32(sAl_);
    const uint32_t sBh = smem_u32(sBh_), sBl = smem_u32(sBl_);

    // ldmatrix address bases (validated layout from R9)
    const int g = lane >> 3, r = lane & 7;
    const int aRowB = warp_m + (g & 1) * 8 + r;     // + mt*16
    const int aColB = (g >> 1) * 8;                 // + k
    const int bRowG = (g >> 1) * 8 + r;             // + warp_n + bt*16
    const int bColB = (g & 1) * 8;                  // + k

    const int row = tid >> 1, half = tid & 1;
    const int gm = m0 + row;

    // ---- stage A once: all 10 k-tiles, act + hi/lo split ----
    for (int kt = 0; kt < 10; kt++) {
        const int gkb = kt * 32 + half * 16;
        float x[16];
#pragma unroll
        for (int q = 0; q < 16; q += 4) {
            int k = gkb + q;
            if (gm < M && k + 3 < D) {
                float4 v = *(const float4*)(A + (long long)gm * D + k);
                x[q] = v.x; x[q + 1] = v.y; x[q + 2] = v.z; x[q + 3] = v.w;
            } else {
#pragma unroll
                for (int j = 0; j < 4; j++)
                    x[q + j] = (gm < M && k + j < D) ? A[(long long)gm * D + k + j] : 0.f;
            }
        }
        uint32_t uh[8], ul[8];
#pragma unroll
        for (int q = 0; q < 16; q += 2) {
            float x0 = x[q], x1 = x[q + 1];
            int k = gkb + q;
            if (k < D && gm < M) {
                if (scale) x0 = fmaf(x0, scale[k], shift[k]);
                if (relu)  x0 = fmaxf(x0, 0.f);
            } else x0 = 0.f;
            if (k + 1 < D && gm < M) {
                if (scale) x1 = fmaf(x1, scale[k + 1], shift[k + 1]);
                if (relu)  x1 = fmaxf(x1, 0.f);
            } else x1 = 0.f;
            float h0 = __bfloat162float(__float2bfloat16_rn(x0));
            float h1 = __bfloat162float(__float2bfloat16_rn(x1));
            uh[q >> 1] = pack_bf(h0, h1);
            ul[q >> 1] = pack_bf(x0 - h0, x1 - h1);
        }
        uint32_t off = (uint32_t)(row * ASTRA + gkb) * 2;
        *(uint4*)((char*)sAh_ + off)      = make_uint4(uh[0], uh[1], uh[2], uh[3]);
        *(uint4*)((char*)sAh_ + off + 16) = make_uint4(uh[4], uh[5], uh[6], uh[7]);
        *(uint4*)((char*)sAl_ + off)      = make_uint4(ul[0], ul[1], ul[2], ul[3]);
        *(uint4*)((char*)sAl_ + off + 16) = make_uint4(ul[4], ul[5], ul[6], ul[7]);
    }
    __syncthreads();

    // ---- loop over n-tiles: widths {128, 128, 64} ----
    for (int nt = 0; nt < 3; nt++) {
        const int n0 = nt * 128;
        const int width = (nt < 2) ? 128 : 64;
        const int nb = (nt < 2) ? 2 : 1;                 // b ldmatrix tiles per warp
        const int warp_n = (warp >> 1) * ((nt < 2) ? 32 : 16);

        float acc[4][4][4];
#pragma unroll
        for (int i = 0; i < 4; i++)
#pragma unroll
            for (int j = 0; j < 4; j++)
#pragma unroll
                for (int q = 0; q < 4; q++) acc[i][j][q] = 0.f;

        for (int kt = 0; kt < 10; kt++) {
            const int k0 = kt * 32;
            // stage B k-tile (width rows x 32 k, hi+lo)
            for (int it = tid; it < width * 2; it += 256) {
                int rr = it >> 1, hh = it & 1;
                long long gi = (long long)(n0 + rr) * KP + k0 + hh * 16;
                uint4 h0 = *(const uint4*)(Bh + gi);
                uint4 h1 = *(const uint4*)(Bh + gi + 8);
                uint4 l0 = *(const uint4*)(Bl + gi);
                uint4 l1 = *(const uint4*)(Bl + gi + 8);
                uint32_t off = (uint32_t)(rr * ASTRB + hh * 16) * 2;
                *(uint4*)((char*)sBh_ + off)      = h0;
                *(uint4*)((char*)sBh_ + off + 16) = h1;
                *(uint4*)((char*)sBl_ + off)      = l0;
                *(uint4*)((char*)sBl_ + off + 16) = l1;
            }
            __syncthreads();

#pragma unroll
            for (int kh = 0; kh < 32; kh += 16) {
                uint32_t ah[4][4], al[4][4];
#pragma unroll
                for (int mt = 0; mt < 4; mt++) {
                    uint32_t off = (uint32_t)((aRowB + mt * 16) * ASTRA + k0 + kh + aColB) * 2;
                    LDMX4(ah[mt], sAh + off);
                    LDMX4(al[mt], sAl + off);
                }
                uint32_t bh2[2][4], bl2[2][4];
                for (int bt = 0; bt < nb; bt++) {
                    uint32_t off = (uint32_t)((warp_n + bt * 16 + bRowG) * ASTRB + kh + bColB) * 2;
                    LDMX4(bh2[bt], sBh + off);
                    LDMX4(bl2[bt], sBl + off);
                }
#pragma unroll
                for (int mt = 0; mt < 4; mt++)
                    for (int ns = 0; ns < nb * 2; ns++) {
                        uint32_t bH0 = bh2[ns >> 1][(ns & 1) * 2];
                        uint32_t bH1 = bh2[ns >> 1][(ns & 1) * 2 + 1];
                        uint32_t bL0 = bl2[ns >> 1][(ns & 1) * 2];
                        uint32_t bL1 = bl2[ns >> 1][(ns & 1) * 2 + 1];
                        mma16816(acc[mt][ns], ah[mt], bH0, bH1);
                        mma16816(acc[mt][ns], al[mt], bH0, bH1);
                        mma16816(acc[mt][ns], ah[mt], bL0, bL1);
                    }
            }
            __syncthreads();
        }

        // epilogue for this n-tile
        for (int ns = 0; ns < nb * 2; ns++) {
            int gn = n0 + warp_n + ns * 8 + (lane & 3) * 2;
            if (gn >= Nc) continue;
            float add0 = 0.f, add1 = 0.f;
            if (bias) { add0 += bias[gn]; add1 += bias[gn + 1]; }
            if (e1)   { add0 += e1[gn] + e2[gn]; add1 += e1[gn + 1] + e2[gn + 1]; }
#pragma unroll
            for (int mt = 0; mt < 4; mt++) {
                int gr0 = m0 + warp_m + mt * 16 + (lane >> 2);
                float* cbase = C + (long long)gr0 * Nc + gn;
                if (gr0 < M) {
                    float2 o = make_float2((acc[mt][ns][0] + add0) * oscale,
                                           (acc[mt][ns][1] + add1) * oscale);
                    *(float2*)cbase = o;
                }
                if (gr0 + 8 < M) {
                    float2 o = make_float2((acc[mt][ns][2] + add0) * oscale,
                                           (acc[mt][ns][3] + add1) * oscale);
                    *(float2*)(cbase + (long long)8 * Nc) = o;
                }
            }
        }
    }
}

// ---- split fp32 weights into padded bf16 hi/lo ----
__global__ void k_wsplit(const float* __restrict__ W, __nv_bfloat16* __restrict__ bh,
                         __nv_bfloat16* __restrict__ bl, int nmat) {
    int idx = blockIdx.x * blockDim.x + threadIdx.x;
    if (idx >= nmat * WMAT) return;
    int m = idx / WMAT, rr = idx - m * WMAT;
    int n = rr / KP, k = rr - n * KP;
    float v = (n < D && k < D) ? W[(long long)m * D * D + n * D + k] : 0.f;
    __nv_bfloat16 h = __float2bfloat16_rn(v);
    bh[idx] = h;
    bl[idx] = __float2bfloat16_rn(v - __bfloat162float(h));
}

// ---------------- small utility kernels ----------------
__global__ void k_embed(const int* __restrict__ x, const float* __restrict__ ae1,
                        const float* __restrict__ ae2, float* __restrict__ out, int n) {
    int idx = blockIdx.x * blockDim.x + threadIdx.x;
    if (idx >= n * D) return;
    int node = idx / D;
    int c = idx - node * D;
    out[idx] = ae1[x[node * 2] * D + c] + ae2[x[node * 2 + 1] * D + c];
}

__global__ void k_fill(float* p, float v, int n) {
    int i = blockIdx.x * blockDim.x + threadIdx.x;
    if (i < n) p[i] = v;
}

__global__ void k_degcount(const int* __restrict__ ei, float* __restrict__ deg, int E) {
    int i = blockIdx.x * blockDim.x + threadIdx.x;
    if (i < E) atomicAdd(&deg[ei[i]], 1.0f);
}

__global__ void k_degfin(float* __restrict__ deg, float* __restrict__ snorm, int n) {
    int i = blockIdx.x * blockDim.x + threadIdx.x;
    if (i >= n) return;
    float v = rsqrtf(deg[i]);
    deg[i] = v;
    snorm[i] = v * v;
}

__global__ void k_enorm(const int* __restrict__ ei, const float* __restrict__ dinv,
                        float* __restrict__ enorm, int E) {
    int i = blockIdx.x * blockDim.x + threadIdx.x;
    if (i < E) enorm[i] = dinv[ei[i]] * dinv[ei[E + i]];
}

// ---------------- CSR build ----------------
__global__ void k_hist(const int* __restrict__ ei, int* __restrict__ cnt, int E) {
    int i = blockIdx.x * blockDim.x + threadIdx.x;
    if (i < E) atomicAdd(&cnt[ei[E + i]], 1);
}

__global__ void k_scan1(const int* __restrict__ cnt, int* __restrict__ bsum, int N) {
    __shared__ int sh[256];
    int base = blockIdx.x * 2048 + threadIdx.x * 8;
    int s = 0;
#pragma unroll
    for (int i = 0; i < 8; i++) if (base + i < N) s += cnt[base + i];
    sh[threadIdx.x] = s;
    __syncthreads();
    for (int o = 128; o; o >>= 1) {
        if (threadIdx.x < o) sh[threadIdx.x] += sh[threadIdx.x + o];
        __syncthreads();
    }
    if (threadIdx.x == 0) bsum[blockIdx.x] = sh[0];
}

__global__ void k_scan2(int* __restrict__ bsum, int* __restrict__ rowptrN, int nb) {
    int running = 0;
    for (int i = 0; i < nb; i++) {
        int t = bsum[i];
        bsum[i] = running;
        running += t;
    }
    *rowptrN = running;
}

__global__ void k_scan3(const int* __restrict__ cnt, const int* __restrict__ bsum,
                        int* __restrict__ rowptr, int N) {
    __shared__ int wsum[8];
    int tid = threadIdx.x, lane = tid & 31, w = tid >> 5;
    int base = blockIdx.x * 2048 + tid * 8;
    int c[8];
    int s = 0;
#pragma unroll
    for (int i = 0; i < 8; i++) {
        c[i] = (base + i < N) ? cnt[base + i] : 0;
        s += c[i];
    }
    int inc = s;
    for (int o = 1; o < 32; o <<= 1) {
        int t = __shfl_up_sync(0xffffffffu, inc, o);
        if (lane >= o) inc += t;
    }
    if (lane == 31) wsum[w] = inc;
    __syncthreads();
    if (tid == 0) {
        int rr = 0;
        for (int i = 0; i < 8; i++) { int t = wsum[i]; wsum[i] = rr; rr += t; }
    }
    __syncthreads();
    int run = bsum[blockIdx.x] + wsum[w] + inc - s;
#pragma unroll
    for (int i = 0; i < 8; i++)
        if (base + i < N) { rowptr[base + i] = run; run += c[i]; }
}

__global__ void k_place(const int* __restrict__ ei, const int* __restrict__ ea,
                        const float* __restrict__ enorm, int* __restrict__ cursor,
                        int4* __restrict__ epack, int E) {
    int i = blockIdx.x * blockDim.x + threadIdx.x;
    if (i >= E) return;
    int dst = ei[E + i];
    int p = atomicAdd(&cursor[dst], 1);
    epack[p] = make_int4(ei[i], ea[2 * i], ea[2 * i + 1], __float_as_int(enorm[i]));
}

// ---------------- CSR gather-aggregate + fused BN stats ----------------
// One warp per node. AGG[dst] = snorm*(T[dst]+ee1[4]+ee2[0]) + sum_e norm*(T[src]+ee1[bt]+ee2[bd])
// Also accumulates per-column sum / sumsq into stats (for BN).
__global__ __launch_bounds__(256) void k_gather(
    const float* __restrict__ T, float* __restrict__ AGG,
    const int4* __restrict__ epack, const int* __restrict__ rowptr,
    const float* __restrict__ snorm,
    const float* __restrict__ ee1, const float* __restrict__ ee2,
    float* __restrict__ stats, int N)
{
    __shared__ float sst[2 * 304];
    for (int i = threadIdx.x; i < 2 * 304; i += 256) sst[i] = 0.f;
    __syncthreads();

    int lane = threadIdx.x & 31, w = threadIdx.x >> 5;
    int gw = blockIdx.x * 8 + w, nw = gridDim.x * 8;

    float lsum[12], lsq[12];
#pragma unroll
    for (int i = 0; i < 12; i++) { lsum[i] = 0.f; lsq[i] = 0.f; }

    const float4* s1 = (const float4*)(ee1 + 4 * D);
    const float4* s2 = (const float4*)(ee2);

    for (int node = gw; node < N; node += nw) {
        float4 acc[3];
        float sn = snorm[node];
        const float4* ts = (const float4*)(T + (size_t)node * D);
#pragma unroll
        for (int j = 0; j < 3; j++) {
            int idx = lane + 32 * j;
            if (idx < D4) {
                float4 v = ts[idx], a = s1[idx], b = s2[idx];
                acc[j] = make_float4(sn * (v.x + a.x + b.x), sn * (v.y + a.y + b.y),
                                     sn * (v.z + a.z + b.z), sn * (v.w + a.w + b.w));
            } else acc[j] = make_float4(0.f, 0.f, 0.f, 0.f);
        }
        int pend = rowptr[node + 1];
        for (int p = rowptr[node]; p < pend; p++) {
            int4 ep = epack[p];
            float nrm = __int_as_float(ep.w);
            const float4* tsrc = (const float4*)(T + (size_t)ep.x * D);
            const float4* p1 = (const float4*)(ee1 + ep.y * D);
            const float4* p2 = (const float4*)(ee2 + ep.z * D);
#pragma unroll
            for (int j = 0; j < 3; j++) {
                int idx = lane + 32 * j;
                if (idx < D4) {
                    float4 v = tsrc[idx], a = p1[idx], b = p2[idx];
                    acc[j].x += nrm * (v.x + a.x + b.x);
                    acc[j].y += nrm * (v.y + a.y + b.y);
                    acc[j].z += nrm * (v.z + a.z + b.z);
                    acc[j].w += nrm * (v.w + a.w + b.w);
                }
            }
        }
        float4* op = (float4*)(AGG + (size_t)node * D);
#pragma unroll
        for (int j = 0; j < 3; j++) {
            int idx = lane + 32 * j;
            if (idx < D4) {
                op[idx] = acc[j];
                lsum[4 * j + 0] += acc[j].x; lsq[4 * j + 0] = fmaf(acc[j].x, acc[j].x, lsq[4 * j + 0]);
                lsum[4 * j + 1] += acc[j].y; lsq[4 * j + 1] = fmaf(acc[j].y, acc[j].y, lsq[4 * j + 1]);
                lsum[4 * j + 2] += acc[j].z; lsq[4 * j + 2] = fmaf(acc[j].z, acc[j].z, lsq[4 * j + 2]);
                lsum[4 * j + 3] += acc[j].w; lsq[4 * j + 3] = fmaf(acc[j].w, acc[j].w, lsq[4 * j + 3]);
            }
        }
    }
    // flush local stats -> shared -> global
#pragma unroll
    for (int j = 0; j < 3; j++) {
        int idx = lane + 32 * j;
        if (idx < D4) {
#pragma unroll
            for (int q = 0; q < 4; q++) {
                int cc = idx * 4 + q;
                atomicAdd(&sst[cc], lsum[4 * j + q]);
                atomicAdd(&sst[304 + cc], lsq[4 * j + q]);
            }
        }
    }
    __syncthreads();
    for (int i = threadIdx.x; i < D; i += 256) {
        atomicAdd(&stats[i], sst[i]);
        atomicAdd(&stats[D + i], sst[304 + i]);
    }
}

__global__ void k_bnfin(const float* __restrict__ st, const float* __restrict__ gamma,
                        const float* __restrict__ beta, float* __restrict__ sc,
                        float* __restrict__ sh, float invn) {
    int c = threadIdx.x;
    if (c >= D) return;
    float mean = st[c] * invn;
    float var = fmaxf(st[D + c] * invn - mean * mean, 0.f);
    float s = gamma[c] / sqrtf(var + 1e-5f);
    sc[c] = s;
    sh[c] = beta[c] - mean * s;
}

// ---------------- mean pooling ----------------
__global__ void k_pool(const float* __restrict__ A, const int* __restrict__ ids,
                       float* __restrict__ pool, float* __restrict__ cnt,
                       const float* __restrict__ scale, const float* __restrict__ shift, int n)
{
    int w = (blockIdx.x * blockDim.x + threadIdx.x) >> 5;
    int lane = threadIdx.x & 31;
    if (w >= n) return;
    int id = ids[w];
    if (lane == 0) atomicAdd(&cnt[id], 1.0f);
    const float4* ap = (const float4*)(A + (long long)w * D);
    float* op = pool + (long long)id * D;
    for (int idx = lane; idx < D4; idx += 32) {
        float4 v = ap[idx];
        if (scale) {
            int c = 4 * idx;
            v.x = fmaf(v.x, scale[c], shift[c]);
            v.y = fmaf(v.y, scale[c + 1], shift[c + 1]);
            v.z = fmaf(v.z, scale[c + 2], shift[c + 2]);
            v.w = fmaf(v.w, scale[c + 3], shift[c + 3]);
        }
        asm volatile("red.global.add.v4.f32 [%0], {%1,%2,%3,%4};"
                     :: "l"(op + 4 * idx), "f"(v.x), "f"(v.y), "f"(v.z), "f"(v.w) : "memory");
    }
}

__global__ void k_pooldiv(float* __restrict__ pool, const float* __restrict__ cnt, int total) {
    int i = blockIdx.x * blockDim.x + threadIdx.x;
    if (i < total) pool[i] /= fmaxf(cnt[i / D], 1.0f);
}

__global__ void k_mask(float* __restrict__ pool, const float* __restrict__ mask,
                       const float* __restrict__ memb, int total) {
    int i = blockIdx.x * blockDim.x + threadIdx.x;
    if (i < total && mask[i / D] > 0.5f) pool[i] = memb[i % D];
}

__global__ void k_l2norm(const float* __restrict__ A, float* __restrict__ out, int n) {
    int w = (blockIdx.x * blockDim.x + threadIdx.x) >> 5;
    int lane = threadIdx.x & 31;
    if (w >= n) return;
    const float4* ap = (const float4*)(A + (long long)w * D);
    float s = 0.f;
    for (int idx = lane; idx < D4; idx += 32) {
        float4 v = ap[idx];
        s += v.x * v.x + v.y * v.y + v.z * v.z + v.w * v.w;
    }
#pragma unroll
    for (int o = 16; o; o >>= 1) s += __shfl_xor_sync(0xffffffffu, s, o);
    float inv = 1.0f / fmaxf(sqrtf(s), 1e-12f);
    float4* op = (float4*)(out + (long long)w * D);
    for (int idx = lane; idx < D4; idx += 32) {
        float4 v = ap[idx];
        op[idx] = make_float4(v.x * inv, v.y * inv, v.z * inv, v.w * inv);
    }
}

// ---------------- FFMA2 GEMM (exact fp32, logits only) ----------------
__global__ __launch_bounds__(256) void k_gemm(
    const float* __restrict__ A, const float* __restrict__ B, float* __restrict__ C,
    int M, int Nc, int K, float oscale)
{
    __shared__ float As[32][130];
    __shared__ float Bs[32][68];

    const int tid = threadIdx.x;
    const int tx = tid & 15, ty = tid >> 4;
    const int m0 = blockIdx.y * 128, n0 = blockIdx.x * 64;

    unsigned long long acc[4][4];
#pragma unroll
    for (int i = 0; i < 4; i++)
#pragma unroll
        for (int j = 0; j < 4; j++) acc[i][j] = 0ull;

    const int nk = (K + 31) >> 5;
    for (int kt = 0; kt < nk; kt++) {
        const int k0 = kt << 5;
#pragma unroll
        for (int i = 0; i < 4; i++) {
            int e = i * 256 + tid;
            int k4 = e & 7, rr = e >> 3;
            int gmm = m0 + rr, gk = k0 + 4 * k4;
            float4 v = make_float4(0.f, 0.f, 0.f, 0.f);
            if (gmm < M && gk < K)
                v = *(const float4*)(A + (long long)gmm * K + gk);
            As[4 * k4 + 0][rr] = v.x; As[4 * k4 + 1][rr] = v.y;
            As[4 * k4 + 2][rr] = v.z; As[4 * k4 + 3][rr] = v.w;
        }
#pragma unroll
        for (int i = 0; i < 2; i++) {
            int e = i * 256 + tid;
            int k4 = e & 7, rr = e >> 3;
            int gn = n0 + rr, gk = k0 + 4 * k4;
            float4 v = make_float4(0.f, 0.f, 0.f, 0.f);
            if (gn < Nc && gk < K)
                v = *(const float4*)(B + (long long)gn * K + gk);
            Bs[4 * k4 + 0][rr] = v.x; Bs[4 * k4 + 1][rr] = v.y;
            Bs[4 * k4 + 2][rr] = v.z; Bs[4 * k4 + 3][rr] = v.w;
        }
        __syncthreads();
#pragma unroll
        for (int kk = 0; kk < 32; kk++) {
            unsigned long long a2[4];
#pragma unroll
            for (int i = 0; i < 4; i++)
                a2[i] = *(const unsigned long long*)&As[kk][ty * 8 + 2 * i];
            float4 bv = *(const float4*)&Bs[kk][tx * 4];
            unsigned long long b2[4];
            {
                unsigned u0 = __float_as_uint(bv.x), u1 = __float_as_uint(bv.y);
                unsigned u2 = __float_as_uint(bv.z), u3 = __float_as_uint(bv.w);
                asm("mov.b64 %0, {%1,%1};" : "=l"(b2[0]) : "r"(u0));
                asm("mov.b64 %0, {%1,%1};" : "=l"(b2[1]) : "r"(u1));
                asm("mov.b64 %0, {%1,%1};" : "=l"(b2[2]) : "r"(u2));
                asm("mov.b64 %0, {%1,%1};" : "=l"(b2[3]) : "r"(u3));
            }
#pragma unroll
            for (int i = 0; i < 4; i++)
#pragma unroll
                for (int j = 0; j < 4; j++)
                    asm("fma.rn.f32x2 %0, %1, %2, %3;"
                        : "=l"(acc[i][j]) : "l"(a2[i]), "l"(b2[j]), "l"(acc[i][j]));
        }
        __syncthreads();
    }

#pragma unroll
    for (int i = 0; i < 4; i++) {
#pragma unroll
        for (int j = 0; j < 4; j++) {
            int gn = n0 + tx * 4 + j;
            if (gn >= Nc) continue;
            float lo = __uint_as_float((unsigned)(acc[i][j] & 0xffffffffull));
            float hi = __uint_as_float((unsigned)(acc[i][j] >> 32));
            int gmm = m0 + ty * 8 + 2 * i;
            if (gmm < M)     C[(long long)gmm * Nc + gn] = lo * oscale;
            if (gmm + 1 < M) C[(long long)(gmm + 1) * Nc + gn] = hi * oscale;
        }
    }
}

// ---------------- host ----------------
static float* symaddr(const void* sym) {
    void* p = nullptr;
    cudaGetSymbolAddress(&p, sym);
    return (float*)p;
}

extern "C" void kernel_launch(void* const* d_in, const int* in_sizes, int n_in,
                              void* d_out, int out_size) {
    const int*   batch_x  = (const int*)d_in[0];
    const int*   batch_ei = (const int*)d_in[1];
    const int*   batch_ea = (const int*)d_in[2];
    const int*   batch_gid= (const int*)d_in[3];
    const int*   frag_x   = (const int*)d_in[4];
    const int*   frag_ei  = (const int*)d_in[5];
    const int*   frag_ea  = (const int*)d_in[6];
    const int*   frag_jid = (const int*)d_in[7];
    const int*   jct_gid  = (const int*)d_in[8];
    const float* jmask    = (const float*)d_in[9];
    const float* ae1      = (const float*)d_in[10];
    const float* ae2      = (const float*)d_in[11];
    const float* gW       = (const float*)d_in[12];
    const float* gb       = (const float*)d_in[13];
    const float* gee1     = (const float*)d_in[14];
    const float* gee2     = (const float*)d_in[15];
    const float* bng      = (const float*)d_in[16];
    const float* bnb      = (const float*)d_in[17];
    const float* jW       = (const float*)d_in[18];
    const float* jb       = (const float*)d_in[19];
    const float* jee1     = (const float*)d_in[20];
    const float* jee2     = (const float*)d_in[21];
    const float* memb     = (const float*)d_in[22];

    const int N  = in_sizes[0] / 2;
    const int E  = in_sizes[1] / 2;
    const int NJ = in_sizes[8];
    const int NG = 1024;
    const int SB = (N + 2047) / 2048;

    float* buf0   = symaddr(g_buf0);
    float* buf1   = symaddr(g_buf1);
    float* degp   = symaddr(g_deg);
    float* snormp = symaddr(g_snorm);
    float* enormp = symaddr(g_enorm);
    float* statsp = symaddr(g_stats);
    float* scalep = symaddr(g_scale);
    float* shiftp = symaddr(g_shift);
    float* poolp  = symaddr(g_pool);
    float* cntp   = symaddr(g_cnt);
    float* t0p    = symaddr(g_t0);
    float* t1p    = symaddr(g_t1);
    float* f0p    = symaddr(g_f0);
    float* f1p    = symaddr(g_f1);
    int*   rowptr = (int*)symaddr(g_rowptr);
    int*   cursor = (int*)symaddr(g_cursor);
    int*   bsum   = (int*)symaddr(g_bsum);
    int4*  epack  = (int4*)symaddr(g_epack);
    __nv_bfloat16* whp = (__nv_bfloat16*)symaddr(g_wh);
    __nv_bfloat16* wlp = (__nv_bfloat16*)symaddr(g_wl);

    cudaFuncSetAttribute(k_mma, cudaFuncAttributeMaxDynamicSharedMemorySize, MMA_SMEM);

    // pre-split weights: gnn (5 mats) -> slots 0..4, jct (2 mats) -> slots 5..6
    k_wsplit<<<(5 * WMAT + 255) / 256, 256>>>(gW, whp, wlp, 5);
    k_wsplit<<<(2 * WMAT + 255) / 256, 256>>>(jW, whp + (size_t)5 * WMAT, wlp + (size_t)5 * WMAT, 2);

    auto tgemm = [&](const float* A, int mat, float* C, int M,
                     const float* bias, const float* e1, const float* e2,
                     const float* sc, const float* sh, int relu) {
        k_mma<<<(M + 127) / 128, 256, MMA_SMEM>>>(
            A, whp + (size_t)mat * WMAT, wlp + (size_t)mat * WMAT,
            C, M, D, bias, e1, e2, sc, sh, relu, 1.0f);
    };

    auto run_gnn = [&](const int* x, const int* ei, const int* ea) {
        {
            long long tot = (long long)N * D;
            k_embed<<<(int)((tot + 255) / 256), 256>>>(x, ae1, ae2, buf0, N);
        }
        k_fill<<<(N + 255) / 256, 256>>>(degp, 1.0f, N);
        k_degcount<<<(E + 255) / 256, 256>>>(ei, degp, E);
        k_degfin<<<(N + 255) / 256, 256>>>(degp, snormp, N);
        k_enorm<<<(E + 255) / 256, 256>>>(ei, degp, enormp, E);

        // CSR build (dst-sorted packed edges)
        cudaMemsetAsync(cursor, 0, (size_t)N * sizeof(int));
        k_hist<<<(E + 255) / 256, 256>>>(ei, cursor, E);
        k_scan1<<<SB, 256>>>(cursor, bsum, N);
        k_scan2<<<1, 1>>>(bsum, rowptr + N, SB);
        k_scan3<<<SB, 256>>>(cursor, bsum, rowptr, N);
        cudaMemcpyAsync(cursor, rowptr, (size_t)N * sizeof(int), cudaMemcpyDeviceToDevice);
        k_place<<<(E + 255) / 256, 256>>>(ei, ea, enormp, cursor, epack, E);

        for (int l = 0; l < 5; l++) {
            const float* sc = l ? scalep : nullptr;
            const float* sh = l ? shiftp : nullptr;
            tgemm(buf0, l, buf1, N, gb + l * D, nullptr, nullptr, sc, sh, l ? 1 : 0);
            cudaMemsetAsync(statsp, 0, 2 * D * sizeof(float));
            k_gather<<<592, 256>>>(buf1, buf0, epack, rowptr, snormp,
                                   gee1 + (long long)l * 6 * D, gee2 + (long long)l * 3 * D,
                                   statsp, N);
            k_bnfin<<<1, D>>>(statsp, bng + l * D, bnb + l * D, scalep, shiftp, 1.0f / (float)N);
        }
    };

    auto run_junction = [&](const float* inbuf, int M) {
        tgemm(inbuf, 5, t0p, M, jb, jee1 + 4 * D, jee2, nullptr, nullptr, 0);
        tgemm(t0p, 6, t1p, M, jb + D, jee1 + (6 + 4) * D, jee2 + 3 * D, nullptr, nullptr, 1);
    };

    // ---------- branch 0 ----------
    run_gnn(batch_x, batch_ei, batch_ea);
    cudaMemsetAsync(poolp, 0, (size_t)NG * D * sizeof(float));
    cudaMemsetAsync(cntp, 0, NG * sizeof(float));
    k_pool<<<(N * 32 + 255) / 256, 256>>>(buf0, batch_gid, poolp, cntp, scalep, shiftp, N);
    k_pooldiv<<<(NG * D + 255) / 256, 256>>>(poolp, cntp, NG * D);
    run_junction(poolp, NG);
    k_l2norm<<<(NG * 32 + 255) / 256, 256>>>(t1p, f0p, NG);

    // ---------- branch 1 ----------
    run_gnn(frag_x, frag_ei, frag_ea);
    cudaMemsetAsync(poolp, 0, (size_t)NJ * D * sizeof(float));
    cudaMemsetAsync(cntp, 0, NJ * sizeof(float));
    k_pool<<<(N * 32 + 255) / 256, 256>>>(buf0, frag_jid, poolp, cntp, scalep, shiftp, N);
    k_pooldiv<<<(NJ * D + 255) / 256, 256>>>(poolp, cntp, NJ * D);
    k_mask<<<(NJ * D + 255) / 256, 256>>>(poolp, jmask, memb, NJ * D);
    run_junction(poolp, NJ);
    cudaMemsetAsync(poolp, 0, (size_t)NG * D * sizeof(float));
    cudaMemsetAsync(cntp, 0, NG * sizeof(float));
    k_pool<<<(NJ * 32 + 255) / 256, 256>>>(t1p, jct_gid, poolp, cntp, nullptr, nullptr, NJ);
    k_pooldiv<<<(NG * D + 255) / 256, 256>>>(poolp, cntp, NG * D);
    k_l2norm<<<(NG * 32 + 255) / 256, 256>>>(poolp, f1p, NG);

    // ---------- logits = (f0 @ f1^T) / TEMP ----------
    {
        dim3 gl((NG + 63) / 64, (NG + 127) / 128);
        k_gemm<<<gl, 256>>>(f0p, f1p, (float*)d_out, NG, NG, D, 25.0f);
    }
}

// round 11
// speedup vs baseline: 1.5115x; 1.2716x over previous
#include <cuda_runtime.h>
#include <cuda_fp16.h>
#include <cstdint>
#include <cstdio>

#define D    300
#define D4   75
#define MAXN 200000
#define MAXE 400000
#define NGR  1024
#define NJC  8192

#define KP    320                 // padded K for fp16 weight buffers
#define NPAD  320                 // padded N rows (2x128 + 1x64)
#define WMAT  (NPAD * KP)         // elems per padded weight matrix
#define ASTRA 328                 // A smem row stride (fp16): 320 + 8
#define ASTRB 40                  // B smem row stride (fp16): 32 + 8

// dynamic smem for k_mma: A hi/lo 128x328 + B double-buffer 2x128x40, fp16
#define MMA_SMEM ((2 * 128 * ASTRA + 2 * 128 * ASTRB) * 2)

// ---------------- scratch (static device memory; no allocs) ----------------
__device__ __align__(16) float g_buf0[(size_t)MAXN * D + 16];
__device__ __align__(16) float g_buf1[(size_t)MAXN * D + 16];
__device__ float g_deg[MAXN];      // deg, then dinv
__device__ float g_snorm[MAXN];
__device__ float g_stats[2 * D];
__device__ float g_scale[D];
__device__ float g_shift[D];
__device__ __align__(16) float g_eec[18 * 300];   // per-layer combined edge emb
__device__ __align__(16) float g_pool[(size_t)NJC * D];
__device__ float g_cnt[NJC];
__device__ __align__(16) float g_t0[(size_t)NJC * D];
__device__ __align__(16) float g_t1[(size_t)NJC * D];
__device__ __align__(16) float g_f0[(size_t)NGR * D];
__device__ __align__(16) float g_f1[(size_t)NGR * D];
// fp16 weights (5 gnn + 2 junction), zero-padded
__device__ __align__(16) __half g_wh[(size_t)7 * WMAT];
// CSR (dst-sorted) edge structures
__device__ int  g_rowptr[MAXN + 1];
__device__ int  g_cursor[MAXN];
__device__ int  g_bsum[256];
__device__ __align__(8) int2 g_epack[MAXE];   // {src | comb<<18, bitcast(norm)}

// ====================== helpers ======================
__device__ __forceinline__ uint32_t smem_u32(const void* p) {
    uint32_t a;
    asm("{ .reg .u64 t; cvta.to.shared.u64 t, %1; cvt.u32.u64 %0, t; }" : "=r"(a) : "l"(p));
    return a;
}

#define LDMX4(r, addr) \
    asm volatile("ldmatrix.sync.aligned.m8n8.x4.shared.b16 {%0,%1,%2,%3}, [%4];" \
        : "=r"((r)[0]), "=r"((r)[1]), "=r"((r)[2]), "=r"((r)[3]) : "r"(addr))

__device__ __forceinline__ void mma16816(float* c, const uint32_t* a,
                                         uint32_t b0, uint32_t b1) {
    asm volatile(
        "mma.sync.aligned.m16n8k16.row.col.f32.f16.f16.f32 "
        "{%0,%1,%2,%3},{%4,%5,%6,%7},{%8,%9},{%0,%1,%2,%3};"
        : "+f"(c[0]), "+f"(c[1]), "+f"(c[2]), "+f"(c[3])
        : "r"(a[0]), "r"(a[1]), "r"(a[2]), "r"(a[3]), "r"(b0), "r"(b1));
}

__device__ __forceinline__ uint32_t pack_hf(float a, float b) {
    __half2 t = __floats2half2_rn(a, b);
    return *(uint32_t*)&t;
}

// ======== A-resident tensor GEMM (fp16 2-term split, B double-buffered) ========
// C[M,300] = oscale*((act(A)_hi + act(A)_lo)[M,300] @ Wh^T + bias + e1 + e2)
__global__ __launch_bounds__(256) void k_mma(
    const float* __restrict__ A, const __half* __restrict__ Bh,
    float* __restrict__ C, int M, int Nc,
    const float* __restrict__ bias, const float* __restrict__ e1, const float* __restrict__ e2,
    const float* __restrict__ scale, const float* __restrict__ shift, int relu, float oscale)
{
    extern __shared__ char dsm[];
    __half* sAh_ = (__half*)dsm;
    __half* sAl_ = sAh_ + 128 * ASTRA;
    __half* sBb_[2];
    sBb_[0] = sAl_ + 128 * ASTRA;
    sBb_[1] = sBb_[0] + 128 * ASTRB;

    const int tid = threadIdx.x, lane = tid & 31, warp = tid >> 5;
    const int m0 = blockIdx.x * 128;
    const int warp_m = (warp & 1) * 64;

    const uint32_t sAh = smem_u32(sAh_), sAl = smem_u32(sAl_);
    const uint32_t sB0 = smem_u32(sBb_[0]), sB1 = smem_u32(sBb_[1]);

    // ldmatrix address bases (layout validated R9/R10)
    const int g = lane >> 3, r = lane & 7;
    const int aRowB = warp_m + (g & 1) * 8 + r;     // + mt*16
    const int aColB = (g >> 1) * 8;                 // + k
    const int bRowG = (g >> 1) * 8 + r;             // + warp_n + bt*16
    const int bColB = (g & 1) * 8;                  // + k

    const int row = tid >> 1, half_ = tid & 1;
    const int gm = m0 + row;

    // ---- stage A once: all 10 k-tiles, act + fp16 hi/lo split ----
    for (int kt = 0; kt < 10; kt++) {
        const int gkb = kt * 32 + half_ * 16;
        float x[16];
#pragma unroll
        for (int q = 0; q < 16; q += 4) {
            int k = gkb + q;
            if (gm < M && k + 3 < D) {
                float4 v = *(const float4*)(A + (long long)gm * D + k);
                x[q] = v.x; x[q + 1] = v.y; x[q + 2] = v.z; x[q + 3] = v.w;
            } else {
#pragma unroll
                for (int j = 0; j < 4; j++)
                    x[q + j] = (gm < M && k + j < D) ? A[(long long)gm * D + k + j] : 0.f;
            }
        }
        uint32_t uh[8], ul[8];
#pragma unroll
        for (int q = 0; q < 16; q += 2) {
            float x0 = x[q], x1 = x[q + 1];
            int k = gkb + q;
            if (k < D && gm < M) {
                if (scale) x0 = fmaf(x0, scale[k], shift[k]);
                if (relu)  x0 = fmaxf(x0, 0.f);
            } else x0 = 0.f;
            if (k + 1 < D && gm < M) {
                if (scale) x1 = fmaf(x1, scale[k + 1], shift[k + 1]);
                if (relu)  x1 = fmaxf(x1, 0.f);
            } else x1 = 0.f;
            float h0 = __half2float(__float2half_rn(x0));
            float h1 = __half2float(__float2half_rn(x1));
            uh[q >> 1] = pack_hf(h0, h1);
            ul[q >> 1] = pack_hf(x0 - h0, x1 - h1);
        }
        uint32_t off = (uint32_t)(row * ASTRA + gkb) * 2;
        *(uint4*)((char*)sAh_ + off)      = make_uint4(uh[0], uh[1], uh[2], uh[3]);
        *(uint4*)((char*)sAh_ + off + 16) = make_uint4(uh[4], uh[5], uh[6], uh[7]);
        *(uint4*)((char*)sAl_ + off)      = make_uint4(ul[0], ul[1], ul[2], ul[3]);
        *(uint4*)((char*)sAl_ + off + 16) = make_uint4(ul[4], ul[5], ul[6], ul[7]);
    }

    // ---- loop over n-tiles: widths {128, 128, 64} ----
    for (int nt = 0; nt < 3; nt++) {
        const int n0 = nt * 128;
        const int width = (nt < 2) ? 128 : 64;
        const int nb = (nt < 2) ? 2 : 1;
        const int warp_n = (warp >> 1) * ((nt < 2) ? 32 : 16);
        const int items = width * 4;   // uint4 loads (16B = 8 fp16)

        float acc[4][4][4];
#pragma unroll
        for (int i = 0; i < 4; i++)
#pragma unroll
            for (int j = 0; j < 4; j++)
#pragma unroll
                for (int q = 0; q < 4; q++) acc[i][j][q] = 0.f;

        uint4 pre[2];
        // preload kt=0 B tile -> buf0
#pragma unroll
        for (int t = 0; t < 2; t++) {
            int item = tid + t * 256;
            if (item < items) {
                int rr = item >> 2, q = item & 3;
                pre[t] = *(const uint4*)(Bh + (size_t)(n0 + rr) * KP + q * 8);
            }
        }
#pragma unroll
        for (int t = 0; t < 2; t++) {
            int item = tid + t * 256;
            if (item < items) {
                int rr = item >> 2, q = item & 3;
                *(uint4*)((char*)sBb_[0] + (uint32_t)(rr * ASTRB + q * 8) * 2) = pre[t];
            }
        }
        __syncthreads();   // covers A staging (first pass) + buf0

        for (int kt = 0; kt < 10; kt++) {
            if (kt < 9) {
#pragma unroll
                for (int t = 0; t < 2; t++) {
                    int item = tid + t * 256;
                    if (item < items) {
                        int rr = item >> 2, q = item & 3;
                        pre[t] = *(const uint4*)(Bh + (size_t)(n0 + rr) * KP + (kt + 1) * 32 + q * 8);
                    }
                }
            }
            const uint32_t sBc = (kt & 1) ? sB1 : sB0;
            const int k0 = kt * 32;
#pragma unroll
            for (int kh = 0; kh < 32; kh += 16) {
                uint32_t ah[4][4], al[4][4];
#pragma unroll
                for (int mt = 0; mt < 4; mt++) {
                    uint32_t off = (uint32_t)((aRowB + mt * 16) * ASTRA + k0 + kh + aColB) * 2;
                    LDMX4(ah[mt], sAh + off);
                    LDMX4(al[mt], sAl + off);
                }
                uint32_t bh2[2][4];
                for (int bt = 0; bt < nb; bt++) {
                    uint32_t off = (uint32_t)((warp_n + bt * 16 + bRowG) * ASTRB + kh + bColB) * 2;
                    LDMX4(bh2[bt], sBc + off);
                }
#pragma unroll
                for (int mt = 0; mt < 4; mt++)
                    for (int ns = 0; ns < nb * 2; ns++) {
                        uint32_t b0 = bh2[ns >> 1][(ns & 1) * 2];
                        uint32_t b1 = bh2[ns >> 1][(ns & 1) * 2 + 1];
                        mma16816(acc[mt][ns], ah[mt], b0, b1);
                        mma16816(acc[mt][ns], al[mt], b0, b1);
                    }
            }
            if (kt < 9) {
                int nbuf = (kt + 1) & 1;
#pragma unroll
                for (int t = 0; t < 2; t++) {
                    int item = tid + t * 256;
                    if (item < items) {
                        int rr = item >> 2, q = item & 3;
                        *(uint4*)((char*)sBb_[nbuf] + (uint32_t)(rr * ASTRB + q * 8) * 2) = pre[t];
                    }
                }
            }
            __syncthreads();
        }

        // epilogue for this n-tile
        for (int ns = 0; ns < nb * 2; ns++) {
            int gn = n0 + warp_n + ns * 8 + (lane & 3) * 2;
            if (gn >= Nc) continue;
            float add0 = 0.f, add1 = 0.f;
            if (bias) { add0 += bias[gn]; add1 += bias[gn + 1]; }
            if (e1)   { add0 += e1[gn] + e2[gn]; add1 += e1[gn + 1] + e2[gn + 1]; }
#pragma unroll
            for (int mt = 0; mt < 4; mt++) {
                int gr0 = m0 + warp_m + mt * 16 + (lane >> 2);
                float* cbase = C + (long long)gr0 * Nc + gn;
                if (gr0 < M) {
                    float2 o = make_float2((acc[mt][ns][0] + add0) * oscale,
                                           (acc[mt][ns][1] + add1) * oscale);
                    *(float2*)cbase = o;
                }
                if (gr0 + 8 < M) {
                    float2 o = make_float2((acc[mt][ns][2] + add0) * oscale,
                                           (acc[mt][ns][3] + add1) * oscale);
                    *(float2*)(cbase + (long long)8 * Nc) = o;
                }
            }
        }
    }
}

// ---- convert fp32 weights into padded fp16 ----
__global__ void k_wh(const float* __restrict__ W, __half* __restrict__ wh, int nmat) {
    int idx = blockIdx.x * blockDim.x + threadIdx.x;
    if (idx >= nmat * WMAT) return;
    int m = idx / WMAT, rr = idx - m * WMAT;
    int n = rr / KP, k = rr - n * KP;
    float v = (n < D && k < D) ? W[(long long)m * D * D + n * D + k] : 0.f;
    wh[idx] = __float2half_rn(v);
}

// ---------------- small utility kernels ----------------
__global__ void k_embed(const int* __restrict__ x, const float* __restrict__ ae1,
                        const float* __restrict__ ae2, float* __restrict__ out, int n) {
    int idx = blockIdx.x * blockDim.x + threadIdx.x;
    if (idx >= n * D) return;
    int node = idx / D;
    int c = idx - node * D;
    out[idx] = ae1[x[node * 2] * D + c] + ae2[x[node * 2 + 1] * D + c];
}

__global__ void k_fill(float* p, float v, int n) {
    int i = blockIdx.x * blockDim.x + threadIdx.x;
    if (i < n) p[i] = v;
}

__global__ void k_degcount(const int* __restrict__ ei, float* __restrict__ deg, int E) {
    int i = blockIdx.x * blockDim.x + threadIdx.x;
    if (i < E) atomicAdd(&deg[ei[i]], 1.0f);
}

__global__ void k_degfin(float* __restrict__ deg, float* __restrict__ snorm, int n) {
    int i = blockIdx.x * blockDim.x + threadIdx.x;
    if (i >= n) return;
    float v = rsqrtf(deg[i]);
    deg[i] = v;          // dinv
    snorm[i] = v * v;
}

// combined edge-emb table: eec[bt*3+bd] = ee1[bt] + ee2[bd]
__global__ void k_eec(const float* __restrict__ ee1, const float* __restrict__ ee2,
                      float* __restrict__ eec) {
    int idx = blockIdx.x * blockDim.x + threadIdx.x;
    if (idx >= 18 * 300) return;
    int i = idx / 300, c = idx - i * 300;
    eec[idx] = ee1[(i / 3) * 300 + c] + ee2[(i % 3) * 300 + c];
}

// ---------------- CSR build ----------------
__global__ void k_hist(const int* __restrict__ ei, int* __restrict__ cnt, int E) {
    int i = blockIdx.x * blockDim.x + threadIdx.x;
    if (i < E) atomicAdd(&cnt[ei[E + i]], 1);
}

__global__ void k_scan1(const int* __restrict__ cnt, int* __restrict__ bsum, int N) {
    __shared__ int sh[256];
    int base = blockIdx.x * 2048 + threadIdx.x * 8;
    int s = 0;
#pragma unroll
    for (int i = 0; i < 8; i++) if (base + i < N) s += cnt[base + i];
    sh[threadIdx.x] = s;
    __syncthreads();
    for (int o = 128; o; o >>= 1) {
        if (threadIdx.x < o) sh[threadIdx.x] += sh[threadIdx.x + o];
        __syncthreads();
    }
    if (threadIdx.x == 0) bsum[blockIdx.x] = sh[0];
}

__global__ void k_scan2(int* __restrict__ bsum, int* __restrict__ rowptrN, int nb) {
    int running = 0;
    for (int i = 0; i < nb; i++) {
        int t = bsum[i];
        bsum[i] = running;
        running += t;
    }
    *rowptrN = running;
}

__global__ void k_scan3(const int* __restrict__ cnt, const int* __restrict__ bsum,
                        int* __restrict__ rowptr, int N) {
    __shared__ int wsum[8];
    int tid = threadIdx.x, lane = tid & 31, w = tid >> 5;
    int base = blockIdx.x * 2048 + tid * 8;
    int c[8];
    int s = 0;
#pragma unroll
    for (int i = 0; i < 8; i++) {
        c[i] = (base + i < N) ? cnt[base + i] : 0;
        s += c[i];
    }
    int inc = s;
    for (int o = 1; o < 32; o <<= 1) {
        int t = __shfl_up_sync(0xffffffffu, inc, o);
        if (lane >= o) inc += t;
    }
    if (lane == 31) wsum[w] = inc;
    __syncthreads();
    if (tid == 0) {
        int rr = 0;
        for (int i = 0; i < 8; i++) { int t = wsum[i]; wsum[i] = rr; rr += t; }
    }
    __syncthreads();
    int run = bsum[blockIdx.x] + wsum[w] + inc - s;
#pragma unroll
    for (int i = 0; i < 8; i++)
        if (base + i < N) { rowptr[base + i] = run; run += c[i]; }
}

__global__ void k_place(const int* __restrict__ ei, const int* __restrict__ ea,
                        const float* __restrict__ dinv, int* __restrict__ cursor,
                        int2* __restrict__ epack, int E) {
    int i = blockIdx.x * blockDim.x + threadIdx.x;
    if (i >= E) return;
    int src = ei[i], dst = ei[E + i];
    float nrm = dinv[src] * dinv[dst];
    int comb = ea[2 * i] * 3 + ea[2 * i + 1];
    int p = atomicAdd(&cursor[dst], 1);
    epack[p] = make_int2(src | (comb << 18), __float_as_int(nrm));
}

// ---------------- CSR gather-aggregate + fused BN stats ----------------
__global__ __launch_bounds__(256) void k_gather(
    const float* __restrict__ T, float* __restrict__ AGG,
    const int2* __restrict__ epack, const int* __restrict__ rowptr,
    const float* __restrict__ snorm, const float* __restrict__ eec,
    float* __restrict__ stats, int N)
{
    __shared__ float sst[2 * 304];
    for (int i = threadIdx.x; i < 2 * 304; i += 256) sst[i] = 0.f;
    __syncthreads();

    int lane = threadIdx.x & 31, w = threadIdx.x >> 5;
    int gw = blockIdx.x * 8 + w, nw = gridDim.x * 8;

    float lsum[12], lsq[12];
#pragma unroll
    for (int i = 0; i < 12; i++) { lsum[i] = 0.f; lsq[i] = 0.f; }

    const float4* e12 = (const float4*)(eec + 12 * 300);   // self-loop: bt=4, bd=0

    for (int node = gw; node < N; node += nw) {
        float4 acc[3];
        float sn = snorm[node];
        const float4* ts = (const float4*)(T + (size_t)node * D);
#pragma unroll
        for (int j = 0; j < 3; j++) {
            int idx = lane + 32 * j;
            if (idx < D4) {
                float4 v = ts[idx], a = e12[idx];
                acc[j] = make_float4(sn * (v.x + a.x), sn * (v.y + a.y),
                                     sn * (v.z + a.z), sn * (v.w + a.w));
            } else acc[j] = make_float4(0.f, 0.f, 0.f, 0.f);
        }
        int pend = rowptr[node + 1];
        for (int p = rowptr[node]; p < pend; p++) {
            int2 ep = epack[p];
            int src = ep.x & 0x3FFFF;
            int comb = ep.x >> 18;
            float nrm = __int_as_float(ep.y);
            const float4* tsrc = (const float4*)(T + (size_t)src * D);
            const float4* ec = (const float4*)(eec + comb * 300);
#pragma unroll
            for (int j = 0; j < 3; j++) {
                int idx = lane + 32 * j;
                if (idx < D4) {
                    float4 v = tsrc[idx], a = ec[idx];
                    acc[j].x += nrm * (v.x + a.x);
                    acc[j].y += nrm * (v.y + a.y);
                    acc[j].z += nrm * (v.z + a.z);
                    acc[j].w += nrm * (v.w + a.w);
                }
            }
        }
        float4* op = (float4*)(AGG + (size_t)node * D);
#pragma unroll
        for (int j = 0; j < 3; j++) {
            int idx = lane + 32 * j;
            if (idx < D4) {
                op[idx] = acc[j];
                lsum[4 * j + 0] += acc[j].x; lsq[4 * j + 0] = fmaf(acc[j].x, acc[j].x, lsq[4 * j + 0]);
                lsum[4 * j + 1] += acc[j].y; lsq[4 * j + 1] = fmaf(acc[j].y, acc[j].y, lsq[4 * j + 1]);
                lsum[4 * j + 2] += acc[j].z; lsq[4 * j + 2] = fmaf(acc[j].z, acc[j].z, lsq[4 * j + 2]);
                lsum[4 * j + 3] += acc[j].w; lsq[4 * j + 3] = fmaf(acc[j].w, acc[j].w, lsq[4 * j + 3]);
            }
        }
    }
#pragma unroll
    for (int j = 0; j < 3; j++) {
        int idx = lane + 32 * j;
        if (idx < D4) {
#pragma unroll
            for (int q = 0; q < 4; q++) {
                int cc = idx * 4 + q;
                atomicAdd(&sst[cc], lsum[4 * j + q]);
                atomicAdd(&sst[304 + cc], lsq[4 * j + q]);
            }
        }
    }
    __syncthreads();
    for (int i = threadIdx.x; i < D; i += 256) {
        atomicAdd(&stats[i], sst[i]);
        atomicAdd(&stats[D + i], sst[304 + i]);
    }
}

__global__ void k_bnfin(const float* __restrict__ st, const float* __restrict__ gamma,
                        const float* __restrict__ beta, float* __restrict__ sc,
                        float* __restrict__ sh, float invn) {
    int c = threadIdx.x;
    if (c >= D) return;
    float mean = st[c] * invn;
    float var = fmaxf(st[D + c] * invn - mean * mean, 0.f);
    float s = gamma[c] / sqrtf(var + 1e-5f);
    sc[c] = s;
    sh[c] = beta[c] - mean * s;
}

// ---------------- mean pooling ----------------
__global__ void k_pool(const float* __restrict__ A, const int* __restrict__ ids,
                       float* __restrict__ pool, float* __restrict__ cnt,
                       const float* __restrict__ scale, const float* __restrict__ shift, int n)
{
    int w = (blockIdx.x * blockDim.x + threadIdx.x) >> 5;
    int lane = threadIdx.x & 31;
    if (w >= n) return;
    int id = ids[w];
    if (lane == 0) atomicAdd(&cnt[id], 1.0f);
    const float4* ap = (const float4*)(A + (long long)w * D);
    float* op = pool + (long long)id * D;
    for (int idx = lane; idx < D4; idx += 32) {
        float4 v = ap[idx];
        if (scale) {
            int c = 4 * idx;
            v.x = fmaf(v.x, scale[c], shift[c]);
            v.y = fmaf(v.y, scale[c + 1], shift[c + 1]);
            v.z = fmaf(v.z, scale[c + 2], shift[c + 2]);
            v.w = fmaf(v.w, scale[c + 3], shift[c + 3]);
        }
        asm volatile("red.global.add.v4.f32 [%0], {%1,%2,%3,%4};"
                     :: "l"(op + 4 * idx), "f"(v.x), "f"(v.y), "f"(v.z), "f"(v.w) : "memory");
    }
}

__global__ void k_pooldiv(float* __restrict__ pool, const float* __restrict__ cnt, int total) {
    int i = blockIdx.x * blockDim.x + threadIdx.x;
    if (i < total) pool[i] /= fmaxf(cnt[i / D], 1.0f);
}

__global__ void k_mask(float* __restrict__ pool, const float* __restrict__ mask,
                       const float* __restrict__ memb, int total) {
    int i = blockIdx.x * blockDim.x + threadIdx.x;
    if (i < total && mask[i / D] > 0.5f) pool[i] = memb[i % D];
}

__global__ void k_l2norm(const float* __restrict__ A, float* __restrict__ out, int n) {
    int w = (blockIdx.x * blockDim.x + threadIdx.x) >> 5;
    int lane = threadIdx.x & 31;
    if (w >= n) return;
    const float4* ap = (const float4*)(A + (long long)w * D);
    float s = 0.f;
    for (int idx = lane; idx < D4; idx += 32) {
        float4 v = ap[idx];
        s += v.x * v.x + v.y * v.y + v.z * v.z + v.w * v.w;
    }
#pragma unroll
    for (int o = 16; o; o >>= 1) s += __shfl_xor_sync(0xffffffffu, s, o);
    float inv = 1.0f / fmaxf(sqrtf(s), 1e-12f);
    float4* op = (float4*)(out + (long long)w * D);
    for (int idx = lane; idx < D4; idx += 32) {
        float4 v = ap[idx];
        op[idx] = make_float4(v.x * inv, v.y * inv, v.z * inv, v.w * inv);
    }
}

// ---------------- FFMA2 GEMM (exact fp32, logits only) ----------------
__global__ __launch_bounds__(256) void k_gemm(
    const float* __restrict__ A, const float* __restrict__ B, float* __restrict__ C,
    int M, int Nc, int K, float oscale)
{
    __shared__ float As[32][130];
    __shared__ float Bs[32][68];

    const int tid = threadIdx.x;
    const int tx = tid & 15, ty = tid >> 4;
    const int m0 = blockIdx.y * 128, n0 = blockIdx.x * 64;

    unsigned long long acc[4][4];
#pragma unroll
    for (int i = 0; i < 4; i++)
#pragma unroll
        for (int j = 0; j < 4; j++) acc[i][j] = 0ull;

    const int nk = (K + 31) >> 5;
    for (int kt = 0; kt < nk; kt++) {
        const int k0 = kt << 5;
#pragma unroll
        for (int i = 0; i < 4; i++) {
            int e = i * 256 + tid;
            int k4 = e & 7, rr = e >> 3;
            int gmm = m0 + rr, gk = k0 + 4 * k4;
            float4 v = make_float4(0.f, 0.f, 0.f, 0.f);
            if (gmm < M && gk < K)
                v = *(const float4*)(A + (long long)gmm * K + gk);
            As[4 * k4 + 0][rr] = v.x; As[4 * k4 + 1][rr] = v.y;
            As[4 * k4 + 2][rr] = v.z; As[4 * k4 + 3][rr] = v.w;
        }
#pragma unroll
        for (int i = 0; i < 2; i++) {
            int e = i * 256 + tid;
            int k4 = e & 7, rr = e >> 3;
            int gn = n0 + rr, gk = k0 + 4 * k4;
            float4 v = make_float4(0.f, 0.f, 0.f, 0.f);
            if (gn < Nc && gk < K)
                v = *(const float4*)(B + (long long)gn * K + gk);
            Bs[4 * k4 + 0][rr] = v.x; Bs[4 * k4 + 1][rr] = v.y;
            Bs[4 * k4 + 2][rr] = v.z; Bs[4 * k4 + 3][rr] = v.w;
        }
        __syncthreads();
#pragma unroll
        for (int kk = 0; kk < 32; kk++) {
            unsigned long long a2[4];
#pragma unroll
            for (int i = 0; i < 4; i++)
                a2[i] = *(const unsigned long long*)&As[kk][ty * 8 + 2 * i];
            float4 bv = *(const float4*)&Bs[kk][tx * 4];
            unsigned long long b2[4];
            {
                unsigned u0 = __float_as_uint(bv.x), u1 = __float_as_uint(bv.y);
                unsigned u2 = __float_as_uint(bv.z), u3 = __float_as_uint(bv.w);
                asm("mov.b64 %0, {%1,%1};" : "=l"(b2[0]) : "r"(u0));
                asm("mov.b64 %0, {%1,%1};" : "=l"(b2[1]) : "r"(u1));
                asm("mov.b64 %0, {%1,%1};" : "=l"(b2[2]) : "r"(u2));
                asm("mov.b64 %0, {%1,%1};" : "=l"(b2[3]) : "r"(u3));
            }
#pragma unroll
            for (int i = 0; i < 4; i++)
#pragma unroll
                for (int j = 0; j < 4; j++)
                    asm("fma.rn.f32x2 %0, %1, %2, %3;"
                        : "=l"(acc[i][j]) : "l"(a2[i]), "l"(b2[j]), "l"(acc[i][j]));
        }
        __syncthreads();
    }

#pragma unroll
    for (int i = 0; i < 4; i++) {
#pragma unroll
        for (int j = 0; j < 4; j++) {
            int gn = n0 + tx * 4 + j;
            if (gn >= Nc) continue;
            float lo = __uint_as_float((unsigned)(acc[i][j] & 0xffffffffull));
            float hi = __uint_as_float((unsigned)(acc[i][j] >> 32));
            int gmm = m0 + ty * 8 + 2 * i;
            if (gmm < M)     C[(long long)gmm * Nc + gn] = lo * oscale;
            if (gmm + 1 < M) C[(long long)(gmm + 1) * Nc + gn] = hi * oscale;
        }
    }
}

// ---------------- host ----------------
static float* symaddr(const void* sym) {
    void* p = nullptr;
    cudaGetSymbolAddress(&p, sym);
    return (float*)p;
}

extern "C" void kernel_launch(void* const* d_in, const int* in_sizes, int n_in,
                              void* d_out, int out_size) {
    const int*   batch_x  = (const int*)d_in[0];
    const int*   batch_ei = (const int*)d_in[1];
    const int*   batch_ea = (const int*)d_in[2];
    const int*   batch_gid= (const int*)d_in[3];
    const int*   frag_x   = (const int*)d_in[4];
    const int*   frag_ei  = (const int*)d_in[5];
    const int*   frag_ea  = (const int*)d_in[6];
    const int*   frag_jid = (const int*)d_in[7];
    const int*   jct_gid  = (const int*)d_in[8];
    const float* jmask    = (const float*)d_in[9];
    const float* ae1      = (const float*)d_in[10];
    const float* ae2      = (const float*)d_in[11];
    const float* gW       = (const float*)d_in[12];
    const float* gb       = (const float*)d_in[13];
    const float* gee1     = (const float*)d_in[14];
    const float* gee2     = (const float*)d_in[15];
    const float* bng      = (const float*)d_in[16];
    const float* bnb      = (const float*)d_in[17];
    const float* jW       = (const float*)d_in[18];
    const float* jb       = (const float*)d_in[19];
    const float* jee1     = (const float*)d_in[20];
    const float* jee2     = (const float*)d_in[21];
    const float* memb     = (const float*)d_in[22];

    const int N  = in_sizes[0] / 2;
    const int E  = in_sizes[1] / 2;
    const int NJ = in_sizes[8];
    const int NG = 1024;
    const int SB = (N + 2047) / 2048;

    float* buf0   = symaddr(g_buf0);
    float* buf1   = symaddr(g_buf1);
    float* degp   = symaddr(g_deg);
    float* snormp = symaddr(g_snorm);
    float* statsp = symaddr(g_stats);
    float* scalep = symaddr(g_scale);
    float* shiftp = symaddr(g_shift);
    float* eecp   = symaddr(g_eec);
    float* poolp  = symaddr(g_pool);
    float* cntp   = symaddr(g_cnt);
    float* t0p    = symaddr(g_t0);
    float* t1p    = symaddr(g_t1);
    float* f0p    = symaddr(g_f0);
    float* f1p    = symaddr(g_f1);
    int*   rowptr = (int*)symaddr(g_rowptr);
    int*   cursor = (int*)symaddr(g_cursor);
    int*   bsum   = (int*)symaddr(g_bsum);
    int2*  epack  = (int2*)symaddr(g_epack);
    __half* whp   = (__half*)symaddr(g_wh);

    cudaFuncSetAttribute(k_mma, cudaFuncAttributeMaxDynamicSharedMemorySize, MMA_SMEM);

    // convert weights: gnn (5 mats) -> slots 0..4, jct (2 mats) -> slots 5..6
    k_wh<<<(5 * WMAT + 255) / 256, 256>>>(gW, whp, 5);
    k_wh<<<(2 * WMAT + 255) / 256, 256>>>(jW, whp + (size_t)5 * WMAT, 2);

    auto tgemm = [&](const float* A, int mat, float* C, int M,
                     const float* bias, const float* e1, const float* e2,
                     const float* sc, const float* sh, int relu) {
        k_mma<<<(M + 127) / 128, 256, MMA_SMEM>>>(
            A, whp + (size_t)mat * WMAT, C, M, D, bias, e1, e2, sc, sh, relu, 1.0f);
    };

    auto run_gnn = [&](const int* x, const int* ei, const int* ea) {
        {
            long long tot = (long long)N * D;
            k_embed<<<(int)((tot + 255) / 256), 256>>>(x, ae1, ae2, buf0, N);
        }
        k_fill<<<(N + 255) / 256, 256>>>(degp, 1.0f, N);      // self-loop in degree
        k_degcount<<<(E + 255) / 256, 256>>>(ei, degp, E);    // out-degree (src)
        k_degfin<<<(N + 255) / 256, 256>>>(degp, snormp, N);  // -> dinv, snorm

        // CSR build (dst-sorted packed edges, norm computed inline)
        cudaMemsetAsync(cursor, 0, (size_t)N * sizeof(int));
        k_hist<<<(E + 255) / 256, 256>>>(ei, cursor, E);
        k_scan1<<<SB, 256>>>(cursor, bsum, N);
        k_scan2<<<1, 1>>>(bsum, rowptr + N, SB);
        k_scan3<<<SB, 256>>>(cursor, bsum, rowptr, N);
        cudaMemcpyAsync(cursor, rowptr, (size_t)N * sizeof(int), cudaMemcpyDeviceToDevice);
        k_place<<<(E + 255) / 256, 256>>>(ei, ea, degp, cursor, epack, E);

        for (int l = 0; l < 5; l++) {
            const float* sc = l ? scalep : nullptr;
            const float* sh = l ? shiftp : nullptr;
            k_eec<<<(18 * 300 + 255) / 256, 256>>>(gee1 + (long long)l * 6 * D,
                                                   gee2 + (long long)l * 3 * D, eecp);
            tgemm(buf0, l, buf1, N, gb + l * D, nullptr, nullptr, sc, sh, l ? 1 : 0);
            cudaMemsetAsync(statsp, 0, 2 * D * sizeof(float));
            k_gather<<<592, 256>>>(buf1, buf0, epack, rowptr, snormp, eecp, statsp, N);
            k_bnfin<<<1, D>>>(statsp, bng + l * D, bnb + l * D, scalep, shiftp, 1.0f / (float)N);
        }
    };

    auto run_junction = [&](const float* inbuf, int M) {
        tgemm(inbuf, 5, t0p, M, jb, jee1 + 4 * D, jee2, nullptr, nullptr, 0);
        tgemm(t0p, 6, t1p, M, jb + D, jee1 + (6 + 4) * D, jee2 + 3 * D, nullptr, nullptr, 1);
    };

    // ---------- branch 0 ----------
    run_gnn(batch_x, batch_ei, batch_ea);
    cudaMemsetAsync(poolp, 0, (size_t)NG * D * sizeof(float));
    cudaMemsetAsync(cntp, 0, NG * sizeof(float));
    k_pool<<<(N * 32 + 255) / 256, 256>>>(buf0, batch_gid, poolp, cntp, scalep, shiftp, N);
    k_pooldiv<<<(NG * D + 255) / 256, 256>>>(poolp, cntp, NG * D);
    run_junction(poolp, NG);
    k_l2norm<<<(NG * 32 + 255) / 256, 256>>>(t1p, f0p, NG);

    // ---------- branch 1 ----------
    run_gnn(frag_x, frag_ei, frag_ea);
    cudaMemsetAsync(poolp, 0, (size_t)NJ * D * sizeof(float));
    cudaMemsetAsync(cntp, 0, NJ * sizeof(float));
    k_pool<<<(N * 32 + 255) / 256, 256>>>(buf0, frag_jid, poolp, cntp, scalep, shiftp, N);
    k_pooldiv<<<(NJ * D + 255) / 256, 256>>>(poolp, cntp, NJ * D);
    k_mask<<<(NJ * D + 255) / 256, 256>>>(poolp, jmask, memb, NJ * D);
    run_junction(poolp, NJ);
    cudaMemsetAsync(poolp, 0, (size_t)NG * D * sizeof(float));
    cudaMemsetAsync(cntp, 0, NG * sizeof(float));
    k_pool<<<(NJ * 32 + 255) / 256, 256>>>(t1p, jct_gid, poolp, cntp, nullptr, nullptr, NJ);
    k_pooldiv<<<(NG * D + 255) / 256, 256>>>(poolp, cntp, NG * D);
    k_l2norm<<<(NG * 32 + 255) / 256, 256>>>(poolp, f1p, NG);

    // ---------- logits = (f0 @ f1^T) / TEMP ----------
    {
        dim3 gl((NG + 63) / 64, (NG + 127) / 128);
        k_gemm<<<gl, 256>>>(f0p, f1p, (float*)d_out, NG, NG, D, 25.0f);
    }
}

// round 12
// speedup vs baseline: 1.9362x; 1.2810x over previous
#include <cuda_runtime.h>
#include <cuda_fp16.h>
#include <cstdint>
#include <cstdio>

#define D    300
#define D4   75
#define MAXN 200000
#define MAXE 400000
#define NGR  1024
#define NJC  8192

#define KP    320                 // padded K for fp16 weight buffers
#define NPAD  320                 // padded N rows (2x128 + 1x64)
#define WMAT  (NPAD * KP)         // elems per padded weight matrix
#define ASTRA 328                 // A smem row stride (fp16): 320 + 8
#define ASTRB 40                  // B smem row stride (fp16): 32 + 8

// dynamic smem for k_mma: A 128x328 + B double-buffer 2x128x40, fp16 -> 102 KB
#define MMA_SMEM ((128 * ASTRA + 2 * 128 * ASTRB) * 2)

// ---------------- scratch (static device memory; no allocs) ----------------
__device__ __align__(16) float g_buf0[(size_t)MAXN * D + 16];
__device__ __align__(16) float g_buf1[(size_t)MAXN * D + 16];
__device__ float g_deg[MAXN];      // deg, then dinv
__device__ float g_snorm[MAXN];
__device__ float g_stats[2 * D];
__device__ float g_scale[D];
__device__ float g_shift[D];
__device__ __align__(16) float g_eec[18 * 300];   // per-layer combined edge emb
__device__ __align__(16) float g_pool[(size_t)NJC * D];
__device__ float g_cnt[NJC];
__device__ __align__(16) float g_t0[(size_t)NJC * D];
__device__ __align__(16) float g_t1[(size_t)NJC * D];
__device__ __align__(16) float g_f0[(size_t)NGR * D];
__device__ __align__(16) float g_f1[(size_t)NGR * D];
// fp16 weights (5 gnn + 2 junction), zero-padded
__device__ __align__(16) __half g_wh[(size_t)7 * WMAT];
// CSR (dst-sorted) edge structures
__device__ int  g_rowptr[MAXN + 1];
__device__ int  g_cursor[MAXN];
__device__ int  g_bsum[256];
__device__ __align__(8) int2 g_epack[MAXE];   // {src | comb<<18, bitcast(norm)}

// ====================== helpers ======================
__device__ __forceinline__ uint32_t smem_u32(const void* p) {
    uint32_t a;
    asm("{ .reg .u64 t; cvta.to.shared.u64 t, %1; cvt.u32.u64 %0, t; }" : "=r"(a) : "l"(p));
    return a;
}

#define LDMX4(r, addr) \
    asm volatile("ldmatrix.sync.aligned.m8n8.x4.shared.b16 {%0,%1,%2,%3}, [%4];" \
        : "=r"((r)[0]), "=r"((r)[1]), "=r"((r)[2]), "=r"((r)[3]) : "r"(addr))

__device__ __forceinline__ void mma16816(float* c, const uint32_t* a,
                                         uint32_t b0, uint32_t b1) {
    asm volatile(
        "mma.sync.aligned.m16n8k16.row.col.f32.f16.f16.f32 "
        "{%0,%1,%2,%3},{%4,%5,%6,%7},{%8,%9},{%0,%1,%2,%3};"
        : "+f"(c[0]), "+f"(c[1]), "+f"(c[2]), "+f"(c[3])
        : "r"(a[0]), "r"(a[1]), "r"(a[2]), "r"(a[3]), "r"(b0), "r"(b1));
}

__device__ __forceinline__ uint32_t pack_hf(float a, float b) {
    __half2 t = __floats2half2_rn(a, b);
    return *(uint32_t*)&t;
}

// ======== A-resident tensor GEMM (pure fp16 mma.sync, B double-buffered) ========
// C[M,300] = oscale*(act(A)[M,300] @ Wh^T + bias + e1 + e2)
// act(v)[k] = relu_opt(scale[k]*v + shift[k]); if xidx != null, A-row is the
// fused atom embedding ae1[x0] + ae2[x1] (layer-0 embed fusion).
__global__ __launch_bounds__(256, 2) void k_mma(
    const float* __restrict__ A, const int* __restrict__ xidx,
    const float* __restrict__ ae1, const float* __restrict__ ae2,
    const __half* __restrict__ Bh,
    float* __restrict__ C, int M, int Nc,
    const float* __restrict__ bias, const float* __restrict__ e1, const float* __restrict__ e2,
    const float* __restrict__ scale, const float* __restrict__ shift, int relu, float oscale)
{
    extern __shared__ char dsm[];
    __half* sAh_ = (__half*)dsm;
    __half* sBb_[2];
    sBb_[0] = sAh_ + 128 * ASTRA;
    sBb_[1] = sBb_[0] + 128 * ASTRB;

    const int tid = threadIdx.x, lane = tid & 31, warp = tid >> 5;
    const int m0 = blockIdx.x * 128;
    const int warp_m = (warp & 1) * 64;

    const uint32_t sAh = smem_u32(sAh_);
    const uint32_t sB0 = smem_u32(sBb_[0]), sB1 = smem_u32(sBb_[1]);

    // ldmatrix address bases (layout validated R9-R11)
    const int g = lane >> 3, r = lane & 7;
    const int aRowB = warp_m + (g & 1) * 8 + r;     // + mt*16
    const int aColB = (g >> 1) * 8;                 // + k
    const int bRowG = (g >> 1) * 8 + r;             // + warp_n + bt*16
    const int bColB = (g & 1) * 8;                  // + k

    const int row = tid >> 1, half_ = tid & 1;
    const int gm = m0 + row;

    const float* arow1 = nullptr;
    const float* arow2 = nullptr;
    if (xidx) {
        int i1 = 0, i2 = 0;
        if (gm < M) { i1 = xidx[2 * gm]; i2 = xidx[2 * gm + 1]; }
        arow1 = ae1 + (size_t)i1 * D;
        arow2 = ae2 + (size_t)i2 * D;
    } else {
        arow1 = A + (long long)gm * D;
    }

    // ---- stage A once: all 10 k-tiles, act -> fp16 ----
    for (int kt = 0; kt < 10; kt++) {
        const int gkb = kt * 32 + half_ * 16;
        float x[16];
#pragma unroll
        for (int q = 0; q < 16; q += 4) {
            int k = gkb + q;
            if (gm < M && k + 3 < D) {
                if (xidx) {
                    float4 v1 = *(const float4*)(arow1 + k);
                    float4 v2 = *(const float4*)(arow2 + k);
                    x[q] = v1.x + v2.x; x[q + 1] = v1.y + v2.y;
                    x[q + 2] = v1.z + v2.z; x[q + 3] = v1.w + v2.w;
                } else {
                    float4 v = *(const float4*)(arow1 + k);
                    x[q] = v.x; x[q + 1] = v.y; x[q + 2] = v.z; x[q + 3] = v.w;
                }
            } else {
#pragma unroll
                for (int j = 0; j < 4; j++) {
                    int kk = k + j;
                    float xv = 0.f;
                    if (gm < M && kk < D)
                        xv = xidx ? (arow1[kk] + arow2[kk]) : arow1[kk];
                    x[q + j] = xv;
                }
            }
        }
        uint32_t uh[8];
#pragma unroll
        for (int q = 0; q < 16; q += 2) {
            float x0 = x[q], x1 = x[q + 1];
            int k = gkb + q;
            if (k < D && gm < M) {
                if (scale) x0 = fmaf(x0, scale[k], shift[k]);
                if (relu)  x0 = fmaxf(x0, 0.f);
            } else x0 = 0.f;
            if (k + 1 < D && gm < M) {
                if (scale) x1 = fmaf(x1, scale[k + 1], shift[k + 1]);
                if (relu)  x1 = fmaxf(x1, 0.f);
            } else x1 = 0.f;
            uh[q >> 1] = pack_hf(x0, x1);
        }
        uint32_t off = (uint32_t)(row * ASTRA + gkb) * 2;
        *(uint4*)((char*)sAh_ + off)      = make_uint4(uh[0], uh[1], uh[2], uh[3]);
        *(uint4*)((char*)sAh_ + off + 16) = make_uint4(uh[4], uh[5], uh[6], uh[7]);
    }

    // ---- loop over n-tiles: widths {128, 128, 64} ----
    for (int nt = 0; nt < 3; nt++) {
        const int n0 = nt * 128;
        const int width = (nt < 2) ? 128 : 64;
        const int nb = (nt < 2) ? 2 : 1;
        const int warp_n = (warp >> 1) * ((nt < 2) ? 32 : 16);
        const int items = width * 4;   // uint4 loads (16B = 8 fp16)

        float acc[4][4][4];
#pragma unroll
        for (int i = 0; i < 4; i++)
#pragma unroll
            for (int j = 0; j < 4; j++)
#pragma unroll
                for (int q = 0; q < 4; q++) acc[i][j][q] = 0.f;

        uint4 pre[2];
        // preload kt=0 B tile -> buf0
#pragma unroll
        for (int t = 0; t < 2; t++) {
            int item = tid + t * 256;
            if (item < items) {
                int rr = item >> 2, q = item & 3;
                pre[t] = *(const uint4*)(Bh + (size_t)(n0 + rr) * KP + q * 8);
            }
        }
#pragma unroll
        for (int t = 0; t < 2; t++) {
            int item = tid + t * 256;
            if (item < items) {
                int rr = item >> 2, q = item & 3;
                *(uint4*)((char*)sBb_[0] + (uint32_t)(rr * ASTRB + q * 8) * 2) = pre[t];
            }
        }
        __syncthreads();   // covers A staging (first pass) + buf0

        for (int kt = 0; kt < 10; kt++) {
            if (kt < 9) {
#pragma unroll
                for (int t = 0; t < 2; t++) {
                    int item = tid + t * 256;
                    if (item < items) {
                        int rr = item >> 2, q = item & 3;
                        pre[t] = *(const uint4*)(Bh + (size_t)(n0 + rr) * KP + (kt + 1) * 32 + q * 8);
                    }
                }
            }
            const uint32_t sBc = (kt & 1) ? sB1 : sB0;
            const int k0 = kt * 32;
#pragma unroll
            for (int kh = 0; kh < 32; kh += 16) {
                uint32_t ah[4][4];
#pragma unroll
                for (int mt = 0; mt < 4; mt++) {
                    uint32_t off = (uint32_t)((aRowB + mt * 16) * ASTRA + k0 + kh + aColB) * 2;
                    LDMX4(ah[mt], sAh + off);
                }
                uint32_t bh2[2][4];
                for (int bt = 0; bt < nb; bt++) {
                    uint32_t off = (uint32_t)((warp_n + bt * 16 + bRowG) * ASTRB + kh + bColB) * 2;
                    LDMX4(bh2[bt], sBc + off);
                }
#pragma unroll
                for (int mt = 0; mt < 4; mt++)
                    for (int ns = 0; ns < nb * 2; ns++) {
                        uint32_t b0 = bh2[ns >> 1][(ns & 1) * 2];
                        uint32_t b1 = bh2[ns >> 1][(ns & 1) * 2 + 1];
                        mma16816(acc[mt][ns], ah[mt], b0, b1);
                    }
            }
            if (kt < 9) {
                int nbuf = (kt + 1) & 1;
#pragma unroll
                for (int t = 0; t < 2; t++) {
                    int item = tid + t * 256;
                    if (item < items) {
                        int rr = item >> 2, q = item & 3;
                        *(uint4*)((char*)sBb_[nbuf] + (uint32_t)(rr * ASTRB + q * 8) * 2) = pre[t];
                    }
                }
            }
            __syncthreads();
        }

        // epilogue for this n-tile
        for (int ns = 0; ns < nb * 2; ns++) {
            int gn = n0 + warp_n + ns * 8 + (lane & 3) * 2;
            if (gn >= Nc) continue;
            float add0 = 0.f, add1 = 0.f;
            if (bias) { add0 += bias[gn]; add1 += bias[gn + 1]; }
            if (e1)   { add0 += e1[gn] + e2[gn]; add1 += e1[gn + 1] + e2[gn + 1]; }
#pragma unroll
            for (int mt = 0; mt < 4; mt++) {
                int gr0 = m0 + warp_m + mt * 16 + (lane >> 2);
                float* cbase = C + (long long)gr0 * Nc + gn;
                if (gr0 < M) {
                    float2 o = make_float2((acc[mt][ns][0] + add0) * oscale,
                                           (acc[mt][ns][1] + add1) * oscale);
                    *(float2*)cbase = o;
                }
                if (gr0 + 8 < M) {
                    float2 o = make_float2((acc[mt][ns][2] + add0) * oscale,
                                           (acc[mt][ns][3] + add1) * oscale);
                    *(float2*)(cbase + (long long)8 * Nc) = o;
                }
            }
        }
    }
}

// ---- convert fp32 weights into padded fp16 ----
__global__ void k_wh(const float* __restrict__ W, __half* __restrict__ wh, int nmat) {
    int idx = blockIdx.x * blockDim.x + threadIdx.x;
    if (idx >= nmat * WMAT) return;
    int m = idx / WMAT, rr = idx - m * WMAT;
    int n = rr / KP, k = rr - n * KP;
    float v = (n < D && k < D) ? W[(long long)m * D * D + n * D + k] : 0.f;
    wh[idx] = __float2half_rn(v);
}

// ---------------- small utility kernels ----------------
__global__ void k_fill(float* p, float v, int n) {
    int i = blockIdx.x * blockDim.x + threadIdx.x;
    if (i < n) p[i] = v;
}

__global__ void k_degcount(const int* __restrict__ ei, float* __restrict__ deg, int E) {
    int i = blockIdx.x * blockDim.x + threadIdx.x;
    if (i < E) atomicAdd(&deg[ei[i]], 1.0f);
}

__global__ void k_degfin(float* __restrict__ deg, float* __restrict__ snorm, int n) {
    int i = blockIdx.x * blockDim.x + threadIdx.x;
    if (i >= n) return;
    float v = rsqrtf(deg[i]);
    deg[i] = v;          // dinv
    snorm[i] = v * v;
}

// combined edge-emb table: eec[bt*3+bd] = ee1[bt] + ee2[bd]
__global__ void k_eec(const float* __restrict__ ee1, const float* __restrict__ ee2,
                      float* __restrict__ eec) {
    int idx = blockIdx.x * blockDim.x + threadIdx.x;
    if (idx >= 18 * 300) return;
    int i = idx / 300, c = idx - i * 300;
    eec[idx] = ee1[(i / 3) * 300 + c] + ee2[(i % 3) * 300 + c];
}

// ---------------- CSR build ----------------
__global__ void k_hist(const int* __restrict__ ei, int* __restrict__ cnt, int E) {
    int i = blockIdx.x * blockDim.x + threadIdx.x;
    if (i < E) atomicAdd(&cnt[ei[E + i]], 1);
}

__global__ void k_scan1(const int* __restrict__ cnt, int* __restrict__ bsum, int N) {
    __shared__ int sh[256];
    int base = blockIdx.x * 2048 + threadIdx.x * 8;
    int s = 0;
#pragma unroll
    for (int i = 0; i < 8; i++) if (base + i < N) s += cnt[base + i];
    sh[threadIdx.x] = s;
    __syncthreads();
    for (int o = 128; o; o >>= 1) {
        if (threadIdx.x < o) sh[threadIdx.x] += sh[threadIdx.x + o];
        __syncthreads();
    }
    if (threadIdx.x == 0) bsum[blockIdx.x] = sh[0];
}

__global__ void k_scan2(int* __restrict__ bsum, int* __restrict__ rowptrN, int nb) {
    int running = 0;
    for (int i = 0; i < nb; i++) {
        int t = bsum[i];
        bsum[i] = running;
        running += t;
    }
    *rowptrN = running;
}

__global__ void k_scan3(const int* __restrict__ cnt, const int* __restrict__ bsum,
                        int* __restrict__ rowptr, int N) {
    __shared__ int wsum[8];
    int tid = threadIdx.x, lane = tid & 31, w = tid >> 5;
    int base = blockIdx.x * 2048 + tid * 8;
    int c[8];
    int s = 0;
#pragma unroll
    for (int i = 0; i < 8; i++) {
        c[i] = (base + i < N) ? cnt[base + i] : 0;
        s += c[i];
    }
    int inc = s;
    for (int o = 1; o < 32; o <<= 1) {
        int t = __shfl_up_sync(0xffffffffu, inc, o);
        if (lane >= o) inc += t;
    }
    if (lane == 31) wsum[w] = inc;
    __syncthreads();
    if (tid == 0) {
        int rr = 0;
        for (int i = 0; i < 8; i++) { int t = wsum[i]; wsum[i] = rr; rr += t; }
    }
    __syncthreads();
    int run = bsum[blockIdx.x] + wsum[w] + inc - s;
#pragma unroll
    for (int i = 0; i < 8; i++)
        if (base + i < N) { rowptr[base + i] = run; run += c[i]; }
}

__global__ void k_place(const int* __restrict__ ei, const int* __restrict__ ea,
                        const float* __restrict__ dinv, int* __restrict__ cursor,
                        int2* __restrict__ epack, int E) {
    int i = blockIdx.x * blockDim.x + threadIdx.x;
    if (i >= E) return;
    int src = ei[i], dst = ei[E + i];
    float nrm = dinv[src] * dinv[dst];
    int comb = ea[2 * i] * 3 + ea[2 * i + 1];
    int p = atomicAdd(&cursor[dst], 1);
    epack[p] = make_int2(src | (comb << 18), __float_as_int(nrm));
}

// ---------------- CSR gather-aggregate + fused BN stats ----------------
__global__ __launch_bounds__(256) void k_gather(
    const float* __restrict__ T, float* __restrict__ AGG,
    const int2* __restrict__ epack, const int* __restrict__ rowptr,
    const float* __restrict__ snorm, const float* __restrict__ eec,
    float* __restrict__ stats, int N)
{
    __shared__ float sst[2 * 304];
    for (int i = threadIdx.x; i < 2 * 304; i += 256) sst[i] = 0.f;
    __syncthreads();

    int lane = threadIdx.x & 31, w = threadIdx.x >> 5;
    int gw = blockIdx.x * 8 + w, nw = gridDim.x * 8;

    float lsum[12], lsq[12];
#pragma unroll
    for (int i = 0; i < 12; i++) { lsum[i] = 0.f; lsq[i] = 0.f; }

    const float4* e12 = (const float4*)(eec + 12 * 300);   // self-loop: bt=4, bd=0

    for (int node = gw; node < N; node += nw) {
        float4 acc[3];
        float sn = snorm[node];
        const float4* ts = (const float4*)(T + (size_t)node * D);
#pragma unroll
        for (int j = 0; j < 3; j++) {
            int idx = lane + 32 * j;
            if (idx < D4) {
                float4 v = ts[idx], a = e12[idx];
                acc[j] = make_float4(sn * (v.x + a.x), sn * (v.y + a.y),
                                     sn * (v.z + a.z), sn * (v.w + a.w));
            } else acc[j] = make_float4(0.f, 0.f, 0.f, 0.f);
        }
        int pend = rowptr[node + 1];
        for (int p = rowptr[node]; p < pend; p++) {
            int2 ep = epack[p];
            int src = ep.x & 0x3FFFF;
            int comb = ep.x >> 18;
            float nrm = __int_as_float(ep.y);
            const float4* tsrc = (const float4*)(T + (size_t)src * D);
            const float4* ec = (const float4*)(eec + comb * 300);
#pragma unroll
            for (int j = 0; j < 3; j++) {
                int idx = lane + 32 * j;
                if (idx < D4) {
                    float4 v = tsrc[idx], a = ec[idx];
                    acc[j].x += nrm * (v.x + a.x);
                    acc[j].y += nrm * (v.y + a.y);
                    acc[j].z += nrm * (v.z + a.z);
                    acc[j].w += nrm * (v.w + a.w);
                }
            }
        }
        float4* op = (float4*)(AGG + (size_t)node * D);
#pragma unroll
        for (int j = 0; j < 3; j++) {
            int idx = lane + 32 * j;
            if (idx < D4) {
                op[idx] = acc[j];
                lsum[4 * j + 0] += acc[j].x; lsq[4 * j + 0] = fmaf(acc[j].x, acc[j].x, lsq[4 * j + 0]);
                lsum[4 * j + 1] += acc[j].y; lsq[4 * j + 1] = fmaf(acc[j].y, acc[j].y, lsq[4 * j + 1]);
                lsum[4 * j + 2] += acc[j].z; lsq[4 * j + 2] = fmaf(acc[j].z, acc[j].z, lsq[4 * j + 2]);
                lsum[4 * j + 3] += acc[j].w; lsq[4 * j + 3] = fmaf(acc[j].w, acc[j].w, lsq[4 * j + 3]);
            }
        }
    }
#pragma unroll
    for (int j = 0; j < 3; j++) {
        int idx = lane + 32 * j;
        if (idx < D4) {
#pragma unroll
            for (int q = 0; q < 4; q++) {
                int cc = idx * 4 + q;
                atomicAdd(&sst[cc], lsum[4 * j + q]);
                atomicAdd(&sst[304 + cc], lsq[4 * j + q]);
            }
        }
    }
    __syncthreads();
    for (int i = threadIdx.x; i < D; i += 256) {
        atomicAdd(&stats[i], sst[i]);
        atomicAdd(&stats[D + i], sst[304 + i]);
    }
}

__global__ void k_bnfin(const float* __restrict__ st, const float* __restrict__ gamma,
                        const float* __restrict__ beta, float* __restrict__ sc,
                        float* __restrict__ sh, float invn) {
    int c = threadIdx.x;
    if (c >= D) return;
    float mean = st[c] * invn;
    float var = fmaxf(st[D + c] * invn - mean * mean, 0.f);
    float s = gamma[c] / sqrtf(var + 1e-5f);
    sc[c] = s;
    sh[c] = beta[c] - mean * s;
}

// ---------------- mean pooling ----------------
__global__ void k_pool(const float* __restrict__ A, const int* __restrict__ ids,
                       float* __restrict__ pool, float* __restrict__ cnt,
                       const float* __restrict__ scale, const float* __restrict__ shift, int n)
{
    int w = (blockIdx.x * blockDim.x + threadIdx.x) >> 5;
    int lane = threadIdx.x & 31;
    if (w >= n) return;
    int id = ids[w];
    if (lane == 0) atomicAdd(&cnt[id], 1.0f);
    const float4* ap = (const float4*)(A + (long long)w * D);
    float* op = pool + (long long)id * D;
    for (int idx = lane; idx < D4; idx += 32) {
        float4 v = ap[idx];
        if (scale) {
            int c = 4 * idx;
            v.x = fmaf(v.x, scale[c], shift[c]);
            v.y = fmaf(v.y, scale[c + 1], shift[c + 1]);
            v.z = fmaf(v.z, scale[c + 2], shift[c + 2]);
            v.w = fmaf(v.w, scale[c + 3], shift[c + 3]);
        }
        asm volatile("red.global.add.v4.f32 [%0], {%1,%2,%3,%4};"
                     :: "l"(op + 4 * idx), "f"(v.x), "f"(v.y), "f"(v.z), "f"(v.w) : "memory");
    }
}

__global__ void k_pooldiv(float* __restrict__ pool, const float* __restrict__ cnt, int total) {
    int i = blockIdx.x * blockDim.x + threadIdx.x;
    if (i < total) pool[i] /= fmaxf(cnt[i / D], 1.0f);
}

__global__ void k_mask(float* __restrict__ pool, const float* __restrict__ mask,
                       const float* __restrict__ memb, int total) {
    int i = blockIdx.x * blockDim.x + threadIdx.x;
    if (i < total && mask[i / D] > 0.5f) pool[i] = memb[i % D];
}

__global__ void k_l2norm(const float* __restrict__ A, float* __restrict__ out, int n) {
    int w = (blockIdx.x * blockDim.x + threadIdx.x) >> 5;
    int lane = threadIdx.x & 31;
    if (w >= n) return;
    const float4* ap = (const float4*)(A + (long long)w * D);
    float s = 0.f;
    for (int idx = lane; idx < D4; idx += 32) {
        float4 v = ap[idx];
        s += v.x * v.x + v.y * v.y + v.z * v.z + v.w * v.w;
    }
#pragma unroll
    for (int o = 16; o; o >>= 1) s += __shfl_xor_sync(0xffffffffu, s, o);
    float inv = 1.0f / fmaxf(sqrtf(s), 1e-12f);
    float4* op = (float4*)(out + (long long)w * D);
    for (int idx = lane; idx < D4; idx += 32) {
        float4 v = ap[idx];
        op[idx] = make_float4(v.x * inv, v.y * inv, v.z * inv, v.w * inv);
    }
}

// ---------------- FFMA2 GEMM (exact fp32, logits only) ----------------
__global__ __launch_bounds__(256) void k_gemm(
    const float* __restrict__ A, const float* __restrict__ B, float* __restrict__ C,
    int M, int Nc, int K, float oscale)
{
    __shared__ float As[32][130];
    __shared__ float Bs[32][68];

    const int tid = threadIdx.x;
    const int tx = tid & 15, ty = tid >> 4;
    const int m0 = blockIdx.y * 128, n0 = blockIdx.x * 64;

    unsigned long long acc[4][4];
#pragma unroll
    for (int i = 0; i < 4; i++)
#pragma unroll
        for (int j = 0; j < 4; j++) acc[i][j] = 0ull;

    const int nk = (K + 31) >> 5;
    for (int kt = 0; kt < nk; kt++) {
        const int k0 = kt << 5;
#pragma unroll
        for (int i = 0; i < 4; i++) {
            int e = i * 256 + tid;
            int k4 = e & 7, rr = e >> 3;
            int gmm = m0 + rr, gk = k0 + 4 * k4;
            float4 v = make_float4(0.f, 0.f, 0.f, 0.f);
            if (gmm < M && gk < K)
                v = *(const float4*)(A + (long long)gmm * K + gk);
            As[4 * k4 + 0][rr] = v.x; As[4 * k4 + 1][rr] = v.y;
            As[4 * k4 + 2][rr] = v.z; As[4 * k4 + 3][rr] = v.w;
        }
#pragma unroll
        for (int i = 0; i < 2; i++) {
            int e = i * 256 + tid;
            int k4 = e & 7, rr = e >> 3;
            int gn = n0 + rr, gk = k0 + 4 * k4;
            float4 v = make_float4(0.f, 0.f, 0.f, 0.f);
            if (gn < Nc && gk < K)
                v = *(const float4*)(B + (long long)gn * K + gk);
            Bs[4 * k4 + 0][rr] = v.x; Bs[4 * k4 + 1][rr] = v.y;
            Bs[4 * k4 + 2][rr] = v.z; Bs[4 * k4 + 3][rr] = v.w;
        }
        __syncthreads();
#pragma unroll
        for (int kk = 0; kk < 32; kk++) {
            unsigned long long a2[4];
#pragma unroll
            for (int i = 0; i < 4; i++)
                a2[i] = *(const unsigned long long*)&As[kk][ty * 8 + 2 * i];
            float4 bv = *(const float4*)&Bs[kk][tx * 4];
            unsigned long long b2[4];
            {
                unsigned u0 = __float_as_uint(bv.x), u1 = __float_as_uint(bv.y);
                unsigned u2 = __float_as_uint(bv.z), u3 = __float_as_uint(bv.w);
                asm("mov.b64 %0, {%1,%1};" : "=l"(b2[0]) : "r"(u0));
                asm("mov.b64 %0, {%1,%1};" : "=l"(b2[1]) : "r"(u1));
                asm("mov.b64 %0, {%1,%1};" : "=l"(b2[2]) : "r"(u2));
                asm("mov.b64 %0, {%1,%1};" : "=l"(b2[3]) : "r"(u3));
            }
#pragma unroll
            for (int i = 0; i < 4; i++)
#pragma unroll
                for (int j = 0; j < 4; j++)
                    asm("fma.rn.f32x2 %0, %1, %2, %3;"
                        : "=l"(acc[i][j]) : "l"(a2[i]), "l"(b2[j]), "l"(acc[i][j]));
        }
        __syncthreads();
    }

#pragma unroll
    for (int i = 0; i < 4; i++) {
#pragma unroll
        for (int j = 0; j < 4; j++) {
            int gn = n0 + tx * 4 + j;
            if (gn >= Nc) continue;
            float lo = __uint_as_float((unsigned)(acc[i][j] & 0xffffffffull));
            float hi = __uint_as_float((unsigned)(acc[i][j] >> 32));
            int gmm = m0 + ty * 8 + 2 * i;
            if (gmm < M)     C[(long long)gmm * Nc + gn] = lo * oscale;
            if (gmm + 1 < M) C[(long long)(gmm + 1) * Nc + gn] = hi * oscale;
        }
    }
}

// ---------------- host ----------------
static float* symaddr(const void* sym) {
    void* p = nullptr;
    cudaGetSymbolAddress(&p, sym);
    return (float*)p;
}

extern "C" void kernel_launch(void* const* d_in, const int* in_sizes, int n_in,
                              void* d_out, int out_size) {
    const int*   batch_x  = (const int*)d_in[0];
    const int*   batch_ei = (const int*)d_in[1];
    const int*   batch_ea = (const int*)d_in[2];
    const int*   batch_gid= (const int*)d_in[3];
    const int*   frag_x   = (const int*)d_in[4];
    const int*   frag_ei  = (const int*)d_in[5];
    const int*   frag_ea  = (const int*)d_in[6];
    const int*   frag_jid = (const int*)d_in[7];
    const int*   jct_gid  = (const int*)d_in[8];
    const float* jmask    = (const float*)d_in[9];
    const float* ae1      = (const float*)d_in[10];
    const float* ae2      = (const float*)d_in[11];
    const float* gW       = (const float*)d_in[12];
    const float* gb       = (const float*)d_in[13];
    const float* gee1     = (const float*)d_in[14];
    const float* gee2     = (const float*)d_in[15];
    const float* bng      = (const float*)d_in[16];
    const float* bnb      = (const float*)d_in[17];
    const float* jW       = (const float*)d_in[18];
    const float* jb       = (const float*)d_in[19];
    const float* jee1     = (const float*)d_in[20];
    const float* jee2     = (const float*)d_in[21];
    const float* memb     = (const float*)d_in[22];

    const int N  = in_sizes[0] / 2;
    const int E  = in_sizes[1] / 2;
    const int NJ = in_sizes[8];
    const int NG = 1024;
    const int SB = (N + 2047) / 2048;

    float* buf0   = symaddr(g_buf0);
    float* buf1   = symaddr(g_buf1);
    float* degp   = symaddr(g_deg);
    float* snormp = symaddr(g_snorm);
    float* statsp = symaddr(g_stats);
    float* scalep = symaddr(g_scale);
    float* shiftp = symaddr(g_shift);
    float* eecp   = symaddr(g_eec);
    float* poolp  = symaddr(g_pool);
    float* cntp   = symaddr(g_cnt);
    float* t0p    = symaddr(g_t0);
    float* t1p    = symaddr(g_t1);
    float* f0p    = symaddr(g_f0);
    float* f1p    = symaddr(g_f1);
    int*   rowptr = (int*)symaddr(g_rowptr);
    int*   cursor = (int*)symaddr(g_cursor);
    int*   bsum   = (int*)symaddr(g_bsum);
    int2*  epack  = (int2*)symaddr(g_epack);
    __half* whp   = (__half*)symaddr(g_wh);

    cudaFuncSetAttribute(k_mma, cudaFuncAttributeMaxDynamicSharedMemorySize, MMA_SMEM);

    // convert weights: gnn (5 mats) -> slots 0..4, jct (2 mats) -> slots 5..6
    k_wh<<<(5 * WMAT + 255) / 256, 256>>>(gW, whp, 5);
    k_wh<<<(2 * WMAT + 255) / 256, 256>>>(jW, whp + (size_t)5 * WMAT, 2);

    auto tgemm = [&](const float* A, const int* xidx, int mat, float* C, int M,
                     const float* bias, const float* e1, const float* e2,
                     const float* sc, const float* sh, int relu) {
        k_mma<<<(M + 127) / 128, 256, MMA_SMEM>>>(
            A, xidx, ae1, ae2, whp + (size_t)mat * WMAT,
            C, M, D, bias, e1, e2, sc, sh, relu, 1.0f);
    };

    auto run_gnn = [&](const int* x, const int* ei, const int* ea) {
        k_fill<<<(N + 255) / 256, 256>>>(degp, 1.0f, N);      // self-loop in degree
        k_degcount<<<(E + 255) / 256, 256>>>(ei, degp, E);    // out-degree (src)
        k_degfin<<<(N + 255) / 256, 256>>>(degp, snormp, N);  // -> dinv, snorm

        // CSR build (dst-sorted packed edges, norm computed inline)
        cudaMemsetAsync(cursor, 0, (size_t)N * sizeof(int));
        k_hist<<<(E + 255) / 256, 256>>>(ei, cursor, E);
        k_scan1<<<SB, 256>>>(cursor, bsum, N);
        k_scan2<<<1, 1>>>(bsum, rowptr + N, SB);
        k_scan3<<<SB, 256>>>(cursor, bsum, rowptr, N);
        cudaMemcpyAsync(cursor, rowptr, (size_t)N * sizeof(int), cudaMemcpyDeviceToDevice);
        k_place<<<(E + 255) / 256, 256>>>(ei, ea, degp, cursor, epack, E);

        for (int l = 0; l < 5; l++) {
            const float* sc = l ? scalep : nullptr;
            const float* sh = l ? shiftp : nullptr;
            k_eec<<<(18 * 300 + 255) / 256, 256>>>(gee1 + (long long)l * 6 * D,
                                                   gee2 + (long long)l * 3 * D, eecp);
            // l=0: embed fused into GEMM A-staging
            tgemm(l ? buf0 : nullptr, l ? nullptr : x, l, buf1, N,
                  gb + l * D, nullptr, nullptr, sc, sh, l ? 1 : 0);
            cudaMemsetAsync(statsp, 0, 2 * D * sizeof(float));
            k_gather<<<592, 256>>>(buf1, buf0, epack, rowptr, snormp, eecp, statsp, N);
            k_bnfin<<<1, D>>>(statsp, bng + l * D, bnb + l * D, scalep, shiftp, 1.0f / (float)N);
        }
    };

    auto run_junction = [&](const float* inbuf, int M) {
        tgemm(inbuf, nullptr, 5, t0p, M, jb, jee1 + 4 * D, jee2, nullptr, nullptr, 0);
        tgemm(t0p, nullptr, 6, t1p, M, jb + D, jee1 + (6 + 4) * D, jee2 + 3 * D,
              nullptr, nullptr, 1);
    };

    // ---------- branch 0 ----------
    run_gnn(batch_x, batch_ei, batch_ea);
    cudaMemsetAsync(poolp, 0, (size_t)NG * D * sizeof(float));
    cudaMemsetAsync(cntp, 0, NG * sizeof(float));
    k_pool<<<(N * 32 + 255) / 256, 256>>>(buf0, batch_gid, poolp, cntp, scalep, shiftp, N);
    k_pooldiv<<<(NG * D + 255) / 256, 256>>>(poolp, cntp, NG * D);
    run_junction(poolp, NG);
    k_l2norm<<<(NG * 32 + 255) / 256, 256>>>(t1p, f0p, NG);

    // ---------- branch 1 ----------
    run_gnn(frag_x, frag_ei, frag_ea);
    cudaMemsetAsync(poolp, 0, (size_t)NJ * D * sizeof(float));
    cudaMemsetAsync(cntp, 0, NJ * sizeof(float));
    k_pool<<<(N * 32 + 255) / 256, 256>>>(buf0, frag_jid, poolp, cntp, scalep, shiftp, N);
    k_pooldiv<<<(NJ * D + 255) / 256, 256>>>(poolp, cntp, NJ * D);
    k_mask<<<(NJ * D + 255) / 256, 256>>>(poolp, jmask, memb, NJ * D);
    run_junction(poolp, NJ);
    cudaMemsetAsync(poolp, 0, (size_t)NG * D * sizeof(float));
    cudaMemsetAsync(cntp, 0, NG * sizeof(float));
    k_pool<<<(NJ * 32 + 255) / 256, 256>>>(t1p, jct_gid, poolp, cntp, nullptr, nullptr, NJ);
    k_pooldiv<<<(NG * D + 255) / 256, 256>>>(poolp, cntp, NG * D);
    k_l2norm<<<(NG * 32 + 255) / 256, 256>>>(poolp, f1p, NG);

    // ---------- logits = (f0 @ f1^T) / TEMP ----------
    {
        dim3 gl((NG + 63) / 64, (NG + 127) / 128);
        k_gemm<<<gl, 256>>>(f0p, f1p, (float*)d_out, NG, NG, D, 25.0f);
    }
}

// round 13
// speedup vs baseline: 2.1414x; 1.1059x over previous
#include <cuda_runtime.h>
#include <cuda_fp16.h>
#include <cstdint>
#include <cstdio>

#define D    300
#define D4   75
#define HS   304                  // fp16 buffer row stride (halves); 608 B, 16B-aligned
#define HI4  38                   // uint4 (8-half) items per fp16 row
#define MAXN 200000
#define MAXE 400000
#define NGR  1024
#define NJC  8192

#define KP    320                 // padded K for fp16 weight buffers
#define NPAD  320                 // padded N rows (2x128 + 1x64)
#define WMAT  (NPAD * KP)         // elems per padded weight matrix
#define ASTRA 328                 // A smem row stride (fp16): 320 + 8
#define ASTRB 40                  // B smem row stride (fp16): 32 + 8

// dynamic smem for k_mma: A 128x328 + B double-buffer 2x128x40, fp16 -> 102 KB
#define MMA_SMEM ((128 * ASTRA + 2 * 128 * ASTRB) * 2)

// ---------------- scratch (static device memory; no allocs) ----------------
// fp16 node buffers (pads [300,304) are never written -> stay zero-initialized)
__device__ __align__(16) __half g_buf0h[(size_t)MAXN * HS + 32];
__device__ __align__(16) __half g_buf1h[(size_t)MAXN * HS + 32];
__device__ float g_deg[MAXN];      // deg, then dinv
__device__ float g_snorm[MAXN];
__device__ float g_stats[2 * D];
__device__ float g_scale[D];
__device__ float g_shift[D];
__device__ __align__(16) float g_eec[18 * HS];    // combined edge emb, padded rows
__device__ __align__(16) float g_pool[(size_t)NJC * D];
__device__ float g_cnt[NJC];
__device__ __align__(16) float g_t0[(size_t)NJC * D];
__device__ __align__(16) float g_t1[(size_t)NJC * D];
__device__ __align__(16) float g_f0[(size_t)NGR * D];
__device__ __align__(16) float g_f1[(size_t)NGR * D];
// fp16 weights (5 gnn + 2 junction), zero-padded
__device__ __align__(16) __half g_wh[(size_t)7 * WMAT];
// CSR (dst-sorted) edge structures
__device__ int  g_rowptr[MAXN + 1];
__device__ int  g_cursor[MAXN];
__device__ int  g_bsum[256];
__device__ __align__(8) int2 g_epack[MAXE];   // {src | comb<<18, bitcast(norm)}

// ====================== helpers ======================
__device__ __forceinline__ uint32_t smem_u32(const void* p) {
    uint32_t a;
    asm("{ .reg .u64 t; cvta.to.shared.u64 t, %1; cvt.u32.u64 %0, t; }" : "=r"(a) : "l"(p));
    return a;
}

#define LDMX4(r, addr) \
    asm volatile("ldmatrix.sync.aligned.m8n8.x4.shared.b16 {%0,%1,%2,%3}, [%4];" \
        : "=r"((r)[0]), "=r"((r)[1]), "=r"((r)[2]), "=r"((r)[3]) : "r"(addr))

__device__ __forceinline__ void mma16816(float* c, const uint32_t* a,
                                         uint32_t b0, uint32_t b1) {
    asm volatile(
        "mma.sync.aligned.m16n8k16.row.col.f32.f16.f16.f32 "
        "{%0,%1,%2,%3},{%4,%5,%6,%7},{%8,%9},{%0,%1,%2,%3};"
        : "+f"(c[0]), "+f"(c[1]), "+f"(c[2]), "+f"(c[3])
        : "r"(a[0]), "r"(a[1]), "r"(a[2]), "r"(a[3]), "r"(b0), "r"(b1));
}

__device__ __forceinline__ uint32_t pack_hf(float a, float b) {
    __half2 t = __floats2half2_rn(a, b);
    return *(uint32_t*)&t;
}
__device__ __forceinline__ void unpack8(uint4 u, float* f) {
    __half2* h = (__half2*)&u;
#pragma unroll
    for (int i = 0; i < 4; i++) {
        float2 v = __half22float2(h[i]);
        f[2 * i] = v.x; f[2 * i + 1] = v.y;
    }
}

// ======== A-resident tensor GEMM (pure fp16 mma.sync, B double-buffered) ========
// C = oscale*(act(A)[M,300] @ Wh^T + bias + e1 + e2)
// A source: Ah (fp16, stride HS) | xidx (fused embed) | A (fp32, stride D)
// C sink:   C16 (fp16, stride HS) | C (fp32, stride Nc)
__global__ __launch_bounds__(256, 2) void k_mma(
    const float* __restrict__ A, const __half* __restrict__ Ah,
    const int* __restrict__ xidx,
    const float* __restrict__ ae1, const float* __restrict__ ae2,
    const __half* __restrict__ Bh,
    float* __restrict__ C, __half* __restrict__ C16, int M, int Nc,
    const float* __restrict__ bias, const float* __restrict__ e1, const float* __restrict__ e2,
    const float* __restrict__ scale, const float* __restrict__ shift, int relu, float oscale)
{
    extern __shared__ char dsm[];
    __half* sAh_ = (__half*)dsm;
    __half* sBb_[2];
    sBb_[0] = sAh_ + 128 * ASTRA;
    sBb_[1] = sBb_[0] + 128 * ASTRB;

    const int tid = threadIdx.x, lane = tid & 31, warp = tid >> 5;
    const int m0 = blockIdx.x * 128;
    const int warp_m = (warp & 1) * 64;

    const uint32_t sAh = smem_u32(sAh_);
    const uint32_t sB0 = smem_u32(sBb_[0]), sB1 = smem_u32(sBb_[1]);

    const int g = lane >> 3, r = lane & 7;
    const int aRowB = warp_m + (g & 1) * 8 + r;
    const int aColB = (g >> 1) * 8;
    const int bRowG = (g >> 1) * 8 + r;
    const int bColB = (g & 1) * 8;

    const int row = tid >> 1, half_ = tid & 1;
    const int gm = m0 + row;

    const float* arow1 = nullptr;
    const float* arow2 = nullptr;
    if (xidx) {
        int i1 = 0, i2 = 0;
        if (gm < M) { i1 = xidx[2 * gm]; i2 = xidx[2 * gm + 1]; }
        arow1 = ae1 + (size_t)i1 * D;
        arow2 = ae2 + (size_t)i2 * D;
    } else if (A) {
        arow1 = A + (long long)gm * D;
    }

    // ---- stage A once: all 10 k-tiles, act -> fp16 ----
    for (int kt = 0; kt < 10; kt++) {
        const int gkb = kt * 32 + half_ * 16;
        float x[16];
        if (Ah) {
            if (gm < M && gkb < HS) {
                const char* base = (const char*)(Ah + (size_t)gm * HS) + gkb * 2;
                uint4 u0 = *(const uint4*)base;
                uint4 u1 = *(const uint4*)(base + 16);
                unpack8(u0, x);
                unpack8(u1, x + 8);
            } else {
#pragma unroll
                for (int q = 0; q < 16; q++) x[q] = 0.f;
            }
        } else {
#pragma unroll
            for (int q = 0; q < 16; q += 4) {
                int k = gkb + q;
                if (gm < M && k + 3 < D) {
                    if (xidx) {
                        float4 v1 = *(const float4*)(arow1 + k);
                        float4 v2 = *(const float4*)(arow2 + k);
                        x[q] = v1.x + v2.x; x[q + 1] = v1.y + v2.y;
                        x[q + 2] = v1.z + v2.z; x[q + 3] = v1.w + v2.w;
                    } else {
                        float4 v = *(const float4*)(arow1 + k);
                        x[q] = v.x; x[q + 1] = v.y; x[q + 2] = v.z; x[q + 3] = v.w;
                    }
                } else {
#pragma unroll
                    for (int j = 0; j < 4; j++) {
                        int kk = k + j;
                        float xv = 0.f;
                        if (gm < M && kk < D)
                            xv = xidx ? (arow1[kk] + arow2[kk]) : arow1[kk];
                        x[q + j] = xv;
                    }
                }
            }
        }
        uint32_t uh[8];
#pragma unroll
        for (int q = 0; q < 16; q += 2) {
            float x0 = x[q], x1 = x[q + 1];
            int k = gkb + q;
            if (k < D && gm < M) {
                if (scale) x0 = fmaf(x0, scale[k], shift[k]);
                if (relu)  x0 = fmaxf(x0, 0.f);
            } else x0 = 0.f;
            if (k + 1 < D && gm < M) {
                if (scale) x1 = fmaf(x1, scale[k + 1], shift[k + 1]);
                if (relu)  x1 = fmaxf(x1, 0.f);
            } else x1 = 0.f;
            uh[q >> 1] = pack_hf(x0, x1);
        }
        uint32_t off = (uint32_t)(row * ASTRA + gkb) * 2;
        *(uint4*)((char*)sAh_ + off)      = make_uint4(uh[0], uh[1], uh[2], uh[3]);
        *(uint4*)((char*)sAh_ + off + 16) = make_uint4(uh[4], uh[5], uh[6], uh[7]);
    }

    // ---- loop over n-tiles: widths {128, 128, 64} ----
    for (int nt = 0; nt < 3; nt++) {
        const int n0 = nt * 128;
        const int width = (nt < 2) ? 128 : 64;
        const int nb = (nt < 2) ? 2 : 1;
        const int warp_n = (warp >> 1) * ((nt < 2) ? 32 : 16);
        const int items = width * 4;

        float acc[4][4][4];
#pragma unroll
        for (int i = 0; i < 4; i++)
#pragma unroll
            for (int j = 0; j < 4; j++)
#pragma unroll
                for (int q = 0; q < 4; q++) acc[i][j][q] = 0.f;

        uint4 pre[2];
#pragma unroll
        for (int t = 0; t < 2; t++) {
            int item = tid + t * 256;
            if (item < items) {
                int rr = item >> 2, q = item & 3;
                pre[t] = *(const uint4*)(Bh + (size_t)(n0 + rr) * KP + q * 8);
            }
        }
#pragma unroll
        for (int t = 0; t < 2; t++) {
            int item = tid + t * 256;
            if (item < items) {
                int rr = item >> 2, q = item & 3;
                *(uint4*)((char*)sBb_[0] + (uint32_t)(rr * ASTRB + q * 8) * 2) = pre[t];
            }
        }
        __syncthreads();

        for (int kt = 0; kt < 10; kt++) {
            if (kt < 9) {
#pragma unroll
                for (int t = 0; t < 2; t++) {
                    int item = tid + t * 256;
                    if (item < items) {
                        int rr = item >> 2, q = item & 3;
                        pre[t] = *(const uint4*)(Bh + (size_t)(n0 + rr) * KP + (kt + 1) * 32 + q * 8);
                    }
                }
            }
            const uint32_t sBc = (kt & 1) ? sB1 : sB0;
            const int k0 = kt * 32;
#pragma unroll
            for (int kh = 0; kh < 32; kh += 16) {
                uint32_t ah[4][4];
#pragma unroll
                for (int mt = 0; mt < 4; mt++) {
                    uint32_t off = (uint32_t)((aRowB + mt * 16) * ASTRA + k0 + kh + aColB) * 2;
                    LDMX4(ah[mt], sAh + off);
                }
                uint32_t bh2[2][4];
                for (int bt = 0; bt < nb; bt++) {
                    uint32_t off = (uint32_t)((warp_n + bt * 16 + bRowG) * ASTRB + kh + bColB) * 2;
                    LDMX4(bh2[bt], sBc + off);
                }
#pragma unroll
                for (int mt = 0; mt < 4; mt++)
                    for (int ns = 0; ns < nb * 2; ns++) {
                        uint32_t b0 = bh2[ns >> 1][(ns & 1) * 2];
                        uint32_t b1 = bh2[ns >> 1][(ns & 1) * 2 + 1];
                        mma16816(acc[mt][ns], ah[mt], b0, b1);
                    }
            }
            if (kt < 9) {
                int nbuf = (kt + 1) & 1;
#pragma unroll
                for (int t = 0; t < 2; t++) {
                    int item = tid + t * 256;
                    if (item < items) {
                        int rr = item >> 2, q = item & 3;
                        *(uint4*)((char*)sBb_[nbuf] + (uint32_t)(rr * ASTRB + q * 8) * 2) = pre[t];
                    }
                }
            }
            __syncthreads();
        }

        // epilogue for this n-tile
        for (int ns = 0; ns < nb * 2; ns++) {
            int gn = n0 + warp_n + ns * 8 + (lane & 3) * 2;
            if (gn >= Nc) continue;
            float add0 = 0.f, add1 = 0.f;
            if (bias) { add0 += bias[gn]; add1 += bias[gn + 1]; }
            if (e1)   { add0 += e1[gn] + e2[gn]; add1 += e1[gn + 1] + e2[gn + 1]; }
#pragma unroll
            for (int mt = 0; mt < 4; mt++) {
                int gr0 = m0 + warp_m + mt * 16 + (lane >> 2);
#pragma unroll
                for (int hh = 0; hh < 2; hh++) {
                    int gr = gr0 + hh * 8;
                    if (gr >= M) continue;
                    float o0 = (acc[mt][ns][2 * hh] + add0) * oscale;
                    float o1 = (acc[mt][ns][2 * hh + 1] + add1) * oscale;
                    if (C16) {
                        *(uint32_t*)((char*)(C16 + (size_t)gr * HS) + gn * 2) = pack_hf(o0, o1);
                    } else {
                        *(float2*)(C + (long long)gr * Nc + gn) = make_float2(o0, o1);
                    }
                }
            }
        }
    }
}

// ---- convert fp32 weights into padded fp16 ----
__global__ void k_wh(const float* __restrict__ W, __half* __restrict__ wh, int nmat) {
    int idx = blockIdx.x * blockDim.x + threadIdx.x;
    if (idx >= nmat * WMAT) return;
    int m = idx / WMAT, rr = idx - m * WMAT;
    int n = rr / KP, k = rr - n * KP;
    float v = (n < D && k < D) ? W[(long long)m * D * D + n * D + k] : 0.f;
    wh[idx] = __float2half_rn(v);
}

// ---------------- small utility kernels ----------------
__global__ void k_fill(float* p, float v, int n) {
    int i = blockIdx.x * blockDim.x + threadIdx.x;
    if (i < n) p[i] = v;
}

__global__ void k_degcount(const int* __restrict__ ei, float* __restrict__ deg, int E) {
    int i = blockIdx.x * blockDim.x + threadIdx.x;
    if (i < E) atomicAdd(&deg[ei[i]], 1.0f);
}

__global__ void k_degfin(float* __restrict__ deg, float* __restrict__ snorm, int n) {
    int i = blockIdx.x * blockDim.x + threadIdx.x;
    if (i >= n) return;
    float v = rsqrtf(deg[i]);
    deg[i] = v;
    snorm[i] = v * v;
}

// combined edge-emb table: eec[(bt*3+bd)*HS + c] = ee1[bt][c] + ee2[bd][c] (pad 0)
__global__ void k_eec(const float* __restrict__ ee1, const float* __restrict__ ee2,
                      float* __restrict__ eec) {
    int idx = blockIdx.x * blockDim.x + threadIdx.x;
    if (idx >= 18 * HS) return;
    int i = idx / HS, c = idx - i * HS;
    eec[idx] = (c < D) ? ee1[(i / 3) * D + c] + ee2[(i % 3) * D + c] : 0.f;
}

// ---------------- CSR build ----------------
__global__ void k_hist(const int* __restrict__ ei, int* __restrict__ cnt, int E) {
    int i = blockIdx.x * blockDim.x + threadIdx.x;
    if (i < E) atomicAdd(&cnt[ei[E + i]], 1);
}

__global__ void k_scan1(const int* __restrict__ cnt, int* __restrict__ bsum, int N) {
    __shared__ int sh[256];
    int base = blockIdx.x * 2048 + threadIdx.x * 8;
    int s = 0;
#pragma unroll
    for (int i = 0; i < 8; i++) if (base + i < N) s += cnt[base + i];
    sh[threadIdx.x] = s;
    __syncthreads();
    for (int o = 128; o; o >>= 1) {
        if (threadIdx.x < o) sh[threadIdx.x] += sh[threadIdx.x + o];
        __syncthreads();
    }
    if (threadIdx.x == 0) bsum[blockIdx.x] = sh[0];
}

__global__ void k_scan2(int* __restrict__ bsum, int* __restrict__ rowptrN, int nb) {
    int running = 0;
    for (int i = 0; i < nb; i++) {
        int t = bsum[i];
        bsum[i] = running;
        running += t;
    }
    *rowptrN = running;
}

__global__ void k_scan3(const int* __restrict__ cnt, const int* __restrict__ bsum,
                        int* __restrict__ rowptr, int N) {
    __shared__ int wsum[8];
    int tid = threadIdx.x, lane = tid & 31, w = tid >> 5;
    int base = blockIdx.x * 2048 + tid * 8;
    int c[8];
    int s = 0;
#pragma unroll
    for (int i = 0; i < 8; i++) {
        c[i] = (base + i < N) ? cnt[base + i] : 0;
        s += c[i];
    }
    int inc = s;
    for (int o = 1; o < 32; o <<= 1) {
        int t = __shfl_up_sync(0xffffffffu, inc, o);
        if (lane >= o) inc += t;
    }
    if (lane == 31) wsum[w] = inc;
    __syncthreads();
    if (tid == 0) {
        int rr = 0;
        for (int i = 0; i < 8; i++) { int t = wsum[i]; wsum[i] = rr; rr += t; }
    }
    __syncthreads();
    int run = bsum[blockIdx.x] + wsum[w] + inc - s;
#pragma unroll
    for (int i = 0; i < 8; i++)
        if (base + i < N) { rowptr[base + i] = run; run += c[i]; }
}

__global__ void k_place(const int* __restrict__ ei, const int* __restrict__ ea,
                        const float* __restrict__ dinv, int* __restrict__ cursor,
                        int2* __restrict__ epack, int E) {
    int i = blockIdx.x * blockDim.x + threadIdx.x;
    if (i >= E) return;
    int src = ei[i], dst = ei[E + i];
    float nrm = dinv[src] * dinv[dst];
    int comb = ea[2 * i] * 3 + ea[2 * i + 1];
    int p = atomicAdd(&cursor[dst], 1);
    epack[p] = make_int2(src | (comb << 18), __float_as_int(nrm));
}

// ---------------- CSR gather-aggregate (fp16 buffers) + fused BN stats ----------------
__global__ __launch_bounds__(256) void k_gather(
    const __half* __restrict__ T, __half* __restrict__ AGG,
    const int2* __restrict__ epack, const int* __restrict__ rowptr,
    const float* __restrict__ snorm, const float* __restrict__ eec,
    float* __restrict__ stats, int N)
{
    __shared__ float sst[2 * HS];
    for (int i = threadIdx.x; i < 2 * HS; i += 256) sst[i] = 0.f;
    __syncthreads();

    int lane = threadIdx.x & 31, w = threadIdx.x >> 5;
    int gw = blockIdx.x * 8 + w, nw = gridDim.x * 8;

    float lsum[16], lsq[16];
#pragma unroll
    for (int i = 0; i < 16; i++) { lsum[i] = 0.f; lsq[i] = 0.f; }

    const float* e12 = eec + 12 * HS;   // self-loop: bt=4, bd=0

    for (int node = gw; node < N; node += nw) {
        float acc[16];
        float sn = snorm[node];
        const uint4* ts = (const uint4*)(T + (size_t)node * HS);
#pragma unroll
        for (int s = 0; s < 2; s++) {
            int it = lane + 32 * s;
            if (it < HI4) {
                float f[8];
                unpack8(ts[it], f);
                const float4 a0 = *(const float4*)(e12 + it * 8);
                const float4 a1 = *(const float4*)(e12 + it * 8 + 4);
                acc[8 * s + 0] = sn * (f[0] + a0.x);
                acc[8 * s + 1] = sn * (f[1] + a0.y);
                acc[8 * s + 2] = sn * (f[2] + a0.z);
                acc[8 * s + 3] = sn * (f[3] + a0.w);
                acc[8 * s + 4] = sn * (f[4] + a1.x);
                acc[8 * s + 5] = sn * (f[5] + a1.y);
                acc[8 * s + 6] = sn * (f[6] + a1.z);
                acc[8 * s + 7] = sn * (f[7] + a1.w);
            } else {
#pragma unroll
                for (int q = 0; q < 8; q++) acc[8 * s + q] = 0.f;
            }
        }
        int pend = rowptr[node + 1];
        for (int p = rowptr[node]; p < pend; p++) {
            int2 ep = epack[p];
            int src = ep.x & 0x3FFFF;
            int comb = ep.x >> 18;
            float nrm = __int_as_float(ep.y);
            const uint4* tsrc = (const uint4*)(T + (size_t)src * HS);
            const float* ecb = eec + comb * HS;
#pragma unroll
            for (int s = 0; s < 2; s++) {
                int it = lane + 32 * s;
                if (it < HI4) {
                    float f[8];
                    unpack8(tsrc[it], f);
                    const float4 a0 = *(const float4*)(ecb + it * 8);
                    const float4 a1 = *(const float4*)(ecb + it * 8 + 4);
                    acc[8 * s + 0] += nrm * (f[0] + a0.x);
                    acc[8 * s + 1] += nrm * (f[1] + a0.y);
                    acc[8 * s + 2] += nrm * (f[2] + a0.z);
                    acc[8 * s + 3] += nrm * (f[3] + a0.w);
                    acc[8 * s + 4] += nrm * (f[4] + a1.x);
                    acc[8 * s + 5] += nrm * (f[5] + a1.y);
                    acc[8 * s + 6] += nrm * (f[6] + a1.z);
                    acc[8 * s + 7] += nrm * (f[7] + a1.w);
                }
            }
        }
        uint4* op = (uint4*)(AGG + (size_t)node * HS);
#pragma unroll
        for (int s = 0; s < 2; s++) {
            int it = lane + 32 * s;
            if (it < HI4) {
                uint4 u;
                u.x = pack_hf(acc[8 * s + 0], acc[8 * s + 1]);
                u.y = pack_hf(acc[8 * s + 2], acc[8 * s + 3]);
                u.z = pack_hf(acc[8 * s + 4], acc[8 * s + 5]);
                u.w = pack_hf(acc[8 * s + 6], acc[8 * s + 7]);
                op[it] = u;
#pragma unroll
                for (int q = 0; q < 8; q++) {
                    float v = acc[8 * s + q];
                    lsum[8 * s + q] += v;
                    lsq[8 * s + q] = fmaf(v, v, lsq[8 * s + q]);
                }
            }
        }
    }
    // flush local stats -> shared -> global
#pragma unroll
    for (int s = 0; s < 2; s++) {
        int it = lane + 32 * s;
        if (it < HI4) {
#pragma unroll
            for (int q = 0; q < 8; q++) {
                int cc = it * 8 + q;
                atomicAdd(&sst[cc], lsum[8 * s + q]);
                atomicAdd(&sst[HS + cc], lsq[8 * s + q]);
            }
        }
    }
    __syncthreads();
    for (int i = threadIdx.x; i < D; i += 256) {
        atomicAdd(&stats[i], sst[i]);
        atomicAdd(&stats[D + i], sst[HS + i]);
    }
}

__global__ void k_bnfin(const float* __restrict__ st, const float* __restrict__ gamma,
                        const float* __restrict__ beta, float* __restrict__ sc,
                        float* __restrict__ sh, float invn) {
    int c = threadIdx.x;
    if (c >= D) return;
    float mean = st[c] * invn;
    float var = fmaxf(st[D + c] * invn - mean * mean, 0.f);
    float s = gamma[c] / sqrtf(var + 1e-5f);
    sc[c] = s;
    sh[c] = beta[c] - mean * s;
}

// ---------------- mean pooling: fp16 source (GNN output) ----------------
__global__ void k_poolh(const __half* __restrict__ A, const int* __restrict__ ids,
                        float* __restrict__ pool, float* __restrict__ cnt,
                        const float* __restrict__ scale, const float* __restrict__ shift, int n)
{
    int w = (blockIdx.x * blockDim.x + threadIdx.x) >> 5;
    int lane = threadIdx.x & 31;
    if (w >= n) return;
    int id = ids[w];
    if (lane == 0) atomicAdd(&cnt[id], 1.0f);
    const uint4* ap = (const uint4*)(A + (size_t)w * HS);
    float* op = pool + (size_t)id * D;
    for (int it = lane; it < HI4; it += 32) {
        float f[8];
        unpack8(ap[it], f);
        int c = it * 8;
#pragma unroll
        for (int q = 0; q < 8; q++) {
            if (c + q < D) f[q] = fmaf(f[q], scale[c + q], shift[c + q]);
        }
        asm volatile("red.global.add.v4.f32 [%0], {%1,%2,%3,%4};"
                     :: "l"(op + c), "f"(f[0]), "f"(f[1]), "f"(f[2]), "f"(f[3]) : "memory");
        if (it < HI4 - 1)   // last item's upper quad is pad (cols 300..303)
            asm volatile("red.global.add.v4.f32 [%0], {%1,%2,%3,%4};"
                         :: "l"(op + c + 4), "f"(f[4]), "f"(f[5]), "f"(f[6]), "f"(f[7]) : "memory");
    }
}

// ---------------- mean pooling: fp32 source (junction output) ----------------
__global__ void k_poolf(const float* __restrict__ A, const int* __restrict__ ids,
                        float* __restrict__ pool, float* __restrict__ cnt, int n)
{
    int w = (blockIdx.x * blockDim.x + threadIdx.x) >> 5;
    int lane = threadIdx.x & 31;
    if (w >= n) return;
    int id = ids[w];
    if (lane == 0) atomicAdd(&cnt[id], 1.0f);
    const float4* ap = (const float4*)(A + (long long)w * D);
    float* op = pool + (long long)id * D;
    for (int idx = lane; idx < D4; idx += 32) {
        float4 v = ap[idx];
        asm volatile("red.global.add.v4.f32 [%0], {%1,%2,%3,%4};"
                     :: "l"(op + 4 * idx), "f"(v.x), "f"(v.y), "f"(v.z), "f"(v.w) : "memory");
    }
}

__global__ void k_pooldiv(float* __restrict__ pool, const float* __restrict__ cnt, int total) {
    int i = blockIdx.x * blockDim.x + threadIdx.x;
    if (i < total) pool[i] /= fmaxf(cnt[i / D], 1.0f);
}

__global__ void k_mask(float* __restrict__ pool, const float* __restrict__ mask,
                       const float* __restrict__ memb, int total) {
    int i = blockIdx.x * blockDim.x + threadIdx.x;
    if (i < total && mask[i / D] > 0.5f) pool[i] = memb[i % D];
}

__global__ void k_l2norm(const float* __restrict__ A, float* __restrict__ out, int n) {
    int w = (blockIdx.x * blockDim.x + threadIdx.x) >> 5;
    int lane = threadIdx.x & 31;
    if (w >= n) return;
    const float4* ap = (const float4*)(A + (long long)w * D);
    float s = 0.f;
    for (int idx = lane; idx < D4; idx += 32) {
        float4 v = ap[idx];
        s += v.x * v.x + v.y * v.y + v.z * v.z + v.w * v.w;
    }
#pragma unroll
    for (int o = 16; o; o >>= 1) s += __shfl_xor_sync(0xffffffffu, s, o);
    float inv = 1.0f / fmaxf(sqrtf(s), 1e-12f);
    float4* op = (float4*)(out + (long long)w * D);
    for (int idx = lane; idx < D4; idx += 32) {
        float4 v = ap[idx];
        op[idx] = make_float4(v.x * inv, v.y * inv, v.z * inv, v.w * inv);
    }
}

// ---------------- FFMA2 GEMM (exact fp32, logits only) ----------------
__global__ __launch_bounds__(256) void k_gemm(
    const float* __restrict__ A, const float* __restrict__ B, float* __restrict__ C,
    int M, int Nc, int K, float oscale)
{
    __shared__ float As[32][130];
    __shared__ float Bs[32][68];

    const int tid = threadIdx.x;
    const int tx = tid & 15, ty = tid >> 4;
    const int m0 = blockIdx.y * 128, n0 = blockIdx.x * 64;

    unsigned long long acc[4][4];
#pragma unroll
    for (int i = 0; i < 4; i++)
#pragma unroll
        for (int j = 0; j < 4; j++) acc[i][j] = 0ull;

    const int nk = (K + 31) >> 5;
    for (int kt = 0; kt < nk; kt++) {
        const int k0 = kt << 5;
#pragma unroll
        for (int i = 0; i < 4; i++) {
            int e = i * 256 + tid;
            int k4 = e & 7, rr = e >> 3;
            int gmm = m0 + rr, gk = k0 + 4 * k4;
            float4 v = make_float4(0.f, 0.f, 0.f, 0.f);
            if (gmm < M && gk < K)
                v = *(const float4*)(A + (long long)gmm * K + gk);
            As[4 * k4 + 0][rr] = v.x; As[4 * k4 + 1][rr] = v.y;
            As[4 * k4 + 2][rr] = v.z; As[4 * k4 + 3][rr] = v.w;
        }
#pragma unroll
        for (int i = 0; i < 2; i++) {
            int e = i * 256 + tid;
            int k4 = e & 7, rr = e >> 3;
            int gn = n0 + rr, gk = k0 + 4 * k4;
            float4 v = make_float4(0.f, 0.f, 0.f, 0.f);
            if (gn < Nc && gk < K)
                v = *(const float4*)(B + (long long)gn * K + gk);
            Bs[4 * k4 + 0][rr] = v.x; Bs[4 * k4 + 1][rr] = v.y;
            Bs[4 * k4 + 2][rr] = v.z; Bs[4 * k4 + 3][rr] = v.w;
        }
        __syncthreads();
#pragma unroll
        for (int kk = 0; kk < 32; kk++) {
            unsigned long long a2[4];
#pragma unroll
            for (int i = 0; i < 4; i++)
                a2[i] = *(const unsigned long long*)&As[kk][ty * 8 + 2 * i];
            float4 bv = *(const float4*)&Bs[kk][tx * 4];
            unsigned long long b2[4];
            {
                unsigned u0 = __float_as_uint(bv.x), u1 = __float_as_uint(bv.y);
                unsigned u2 = __float_as_uint(bv.z), u3 = __float_as_uint(bv.w);
                asm("mov.b64 %0, {%1,%1};" : "=l"(b2[0]) : "r"(u0));
                asm("mov.b64 %0, {%1,%1};" : "=l"(b2[1]) : "r"(u1));
                asm("mov.b64 %0, {%1,%1};" : "=l"(b2[2]) : "r"(u2));
                asm("mov.b64 %0, {%1,%1};" : "=l"(b2[3]) : "r"(u3));
            }
#pragma unroll
            for (int i = 0; i < 4; i++)
#pragma unroll
                for (int j = 0; j < 4; j++)
                    asm("fma.rn.f32x2 %0, %1, %2, %3;"
                        : "=l"(acc[i][j]) : "l"(a2[i]), "l"(b2[j]), "l"(acc[i][j]));
        }
        __syncthreads();
    }

#pragma unroll
    for (int i = 0; i < 4; i++) {
#pragma unroll
        for (int j = 0; j < 4; j++) {
            int gn = n0 + tx * 4 + j;
            if (gn >= Nc) continue;
            float lo = __uint_as_float((unsigned)(acc[i][j] & 0xffffffffull));
            float hi = __uint_as_float((unsigned)(acc[i][j] >> 32));
            int gmm = m0 + ty * 8 + 2 * i;
            if (gmm < M)     C[(long long)gmm * Nc + gn] = lo * oscale;
            if (gmm + 1 < M) C[(long long)(gmm + 1) * Nc + gn] = hi * oscale;
        }
    }
}

// ---------------- host ----------------
static float* symaddr(const void* sym) {
    void* p = nullptr;
    cudaGetSymbolAddress(&p, sym);
    return (float*)p;
}

extern "C" void kernel_launch(void* const* d_in, const int* in_sizes, int n_in,
                              void* d_out, int out_size) {
    const int*   batch_x  = (const int*)d_in[0];
    const int*   batch_ei = (const int*)d_in[1];
    const int*   batch_ea = (const int*)d_in[2];
    const int*   batch_gid= (const int*)d_in[3];
    const int*   frag_x   = (const int*)d_in[4];
    const int*   frag_ei  = (const int*)d_in[5];
    const int*   frag_ea  = (const int*)d_in[6];
    const int*   frag_jid = (const int*)d_in[7];
    const int*   jct_gid  = (const int*)d_in[8];
    const float* jmask    = (const float*)d_in[9];
    const float* ae1      = (const float*)d_in[10];
    const float* ae2      = (const float*)d_in[11];
    const float* gW       = (const float*)d_in[12];
    const float* gb       = (const float*)d_in[13];
    const float* gee1     = (const float*)d_in[14];
    const float* gee2     = (const float*)d_in[15];
    const float* bng      = (const float*)d_in[16];
    const float* bnb      = (const float*)d_in[17];
    const float* jW       = (const float*)d_in[18];
    const float* jb       = (const float*)d_in[19];
    const float* jee1     = (const float*)d_in[20];
    const float* jee2     = (const float*)d_in[21];
    const float* memb     = (const float*)d_in[22];

    const int N  = in_sizes[0] / 2;
    const int E  = in_sizes[1] / 2;
    const int NJ = in_sizes[8];
    const int NG = 1024;
    const int SB = (N + 2047) / 2048;

    __half* buf0h = (__half*)symaddr(g_buf0h);
    __half* buf1h = (__half*)symaddr(g_buf1h);
    float* degp   = symaddr(g_deg);
    float* snormp = symaddr(g_snorm);
    float* statsp = symaddr(g_stats);
    float* scalep = symaddr(g_scale);
    float* shiftp = symaddr(g_shift);
    float* eecp   = symaddr(g_eec);
    float* poolp  = symaddr(g_pool);
    float* cntp   = symaddr(g_cnt);
    float* t0p    = symaddr(g_t0);
    float* t1p    = symaddr(g_t1);
    float* f0p    = symaddr(g_f0);
    float* f1p    = symaddr(g_f1);
    int*   rowptr = (int*)symaddr(g_rowptr);
    int*   cursor = (int*)symaddr(g_cursor);
    int*   bsum   = (int*)symaddr(g_bsum);
    int2*  epack  = (int2*)symaddr(g_epack);
    __half* whp   = (__half*)symaddr(g_wh);

    cudaFuncSetAttribute(k_mma, cudaFuncAttributeMaxDynamicSharedMemorySize, MMA_SMEM);

    // convert weights: gnn (5 mats) -> slots 0..4, jct (2 mats) -> slots 5..6
    k_wh<<<(5 * WMAT + 255) / 256, 256>>>(gW, whp, 5);
    k_wh<<<(2 * WMAT + 255) / 256, 256>>>(jW, whp + (size_t)5 * WMAT, 2);

    // GNN layer GEMM: fp16 in (or fused embed), fp16 out
    auto tgemm16 = [&](const __half* Ah, const int* xidx, int mat, __half* C16, int M,
                       const float* bias, const float* sc, const float* sh, int relu) {
        k_mma<<<(M + 127) / 128, 256, MMA_SMEM>>>(
            nullptr, Ah, xidx, ae1, ae2, whp + (size_t)mat * WMAT,
            nullptr, C16, M, D, bias, nullptr, nullptr, sc, sh, relu, 1.0f);
    };
    // Junction GEMM: fp32 in, fp32 out
    auto tgemm32 = [&](const float* A, int mat, float* C, int M,
                       const float* bias, const float* e1, const float* e2, int relu) {
        k_mma<<<(M + 127) / 128, 256, MMA_SMEM>>>(
            A, nullptr, nullptr, ae1, ae2, whp + (size_t)mat * WMAT,
            C, nullptr, M, D, bias, e1, e2, nullptr, nullptr, relu, 1.0f);
    };

    auto run_gnn = [&](const int* x, const int* ei, const int* ea) {
        k_fill<<<(N + 255) / 256, 256>>>(degp, 1.0f, N);      // self-loop in degree
        k_degcount<<<(E + 255) / 256, 256>>>(ei, degp, E);
        k_degfin<<<(N + 255) / 256, 256>>>(degp, snormp, N);  // -> dinv, snorm

        // CSR build (dst-sorted packed edges, norm computed inline)
        cudaMemsetAsync(cursor, 0, (size_t)N * sizeof(int));
        k_hist<<<(E + 255) / 256, 256>>>(ei, cursor, E);
        k_scan1<<<SB, 256>>>(cursor, bsum, N);
        k_scan2<<<1, 1>>>(bsum, rowptr + N, SB);
        k_scan3<<<SB, 256>>>(cursor, bsum, rowptr, N);
        cudaMemcpyAsync(cursor, rowptr, (size_t)N * sizeof(int), cudaMemcpyDeviceToDevice);
        k_place<<<(E + 255) / 256, 256>>>(ei, ea, degp, cursor, epack, E);

        for (int l = 0; l < 5; l++) {
            const float* sc = l ? scalep : nullptr;
            const float* sh = l ? shiftp : nullptr;
            k_eec<<<(18 * HS + 255) / 256, 256>>>(gee1 + (long long)l * 6 * D,
                                                  gee2 + (long long)l * 3 * D, eecp);
            tgemm16(l ? buf0h : nullptr, l ? nullptr : x, l, buf1h, N,
                    gb + l * D, sc, sh, l ? 1 : 0);
            cudaMemsetAsync(statsp, 0, 2 * D * sizeof(float));
            k_gather<<<592, 256>>>(buf1h, buf0h, epack, rowptr, snormp, eecp, statsp, N);
            k_bnfin<<<1, D>>>(statsp, bng + l * D, bnb + l * D, scalep, shiftp, 1.0f / (float)N);
        }
    };

    auto run_junction = [&](const float* inbuf, int M) {
        tgemm32(inbuf, 5, t0p, M, jb, jee1 + 4 * D, jee2, 0);
        tgemm32(t0p, 6, t1p, M, jb + D, jee1 + (6 + 4) * D, jee2 + 3 * D, 1);
    };

    // ---------- branch 0 ----------
    run_gnn(batch_x, batch_ei, batch_ea);
    cudaMemsetAsync(poolp, 0, (size_t)NG * D * sizeof(float));
    cudaMemsetAsync(cntp, 0, NG * sizeof(float));
    k_poolh<<<(N * 32 + 255) / 256, 256>>>(buf0h, batch_gid, poolp, cntp, scalep, shiftp, N);
    k_pooldiv<<<(NG * D + 255) / 256, 256>>>(poolp, cntp, NG * D);
    run_junction(poolp, NG);
    k_l2norm<<<(NG * 32 + 255) / 256, 256>>>(t1p, f0p, NG);

    // ---------- branch 1 ----------
    run_gnn(frag_x, frag_ei, frag_ea);
    cudaMemsetAsync(poolp, 0, (size_t)NJ * D * sizeof(float));
    cudaMemsetAsync(cntp, 0, NJ * sizeof(float));
    k_poolh<<<(N * 32 + 255) / 256, 256>>>(buf0h, frag_jid, poolp, cntp, scalep, shiftp, N);
    k_pooldiv<<<(NJ * D + 255) / 256, 256>>>(poolp, cntp, NJ * D);
    k_mask<<<(NJ * D + 255) / 256, 256>>>(poolp, jmask, memb, NJ * D);
    run_junction(poolp, NJ);
    cudaMemsetAsync(poolp, 0, (size_t)NG * D * sizeof(float));
    cudaMemsetAsync(cntp, 0, NG * sizeof(float));
    k_poolf<<<(NJ * 32 + 255) / 256, 256>>>(t1p, jct_gid, poolp, cntp, NJ);
    k_pooldiv<<<(NG * D + 255) / 256, 256>>>(poolp, cntp, NG * D);
    k_l2norm<<<(NG * 32 + 255) / 256, 256>>>(poolp, f1p, NG);

    // ---------- logits = (f0 @ f1^T) / TEMP ----------
    {
        dim3 gl((NG + 63) / 64, (NG + 127) / 128);
        k_gemm<<<gl, 256>>>(f0p, f1p, (float*)d_out, NG, NG, D, 25.0f);
    }
}

// round 14
// speedup vs baseline: 2.2838x; 1.0665x over previous
#include <cuda_runtime.h>
#include <cuda_fp16.h>
#include <cstdint>
#include <cstdio>

#define D    300
#define D4   75
#define HS   304                  // fp16 buffer row stride (halves); 608 B, 16B-aligned
#define HI4  38                   // uint4 (8-half) items per fp16 row
#define MAXN 200000
#define MAXE 400000
#define NGR  1024
#define NJC  8192

#define KP    320
#define NPAD  320
#define WMAT  (NPAD * KP)
#define ASTRA 328
#define ASTRB 40

#define MMA_SMEM ((128 * ASTRA + 2 * 128 * ASTRB) * 2)

// ---------------- scratch (static device memory; no allocs) ----------------
__device__ __align__(16) __half g_buf0h[(size_t)MAXN * HS + 32];
__device__ __align__(16) __half g_buf1h[(size_t)MAXN * HS + 32];
__device__ float g_deg[MAXN];      // dinv
__device__ float g_snorm[MAXN];
__device__ float g_stats[2 * D];   // zero at start of every replay (bnfin restores)
__device__ float g_scale[D];
__device__ float g_shift[D];
__device__ __align__(16) float g_pool[(size_t)NJC * D];
__device__ float g_cnt[NJC];
__device__ __align__(16) float g_t0[(size_t)NJC * D];
__device__ __align__(16) float g_t1[(size_t)NJC * D];
__device__ __align__(16) float g_f0[(size_t)NGR * D];
__device__ __align__(16) float g_f1[(size_t)NGR * D];
__device__ __align__(16) __half g_wh[(size_t)7 * WMAT];
__device__ int  g_rowptr[MAXN + 1];
__device__ int  g_cursor[MAXN];
__device__ int  g_ideg[MAXN];
__device__ int  g_bsum[256];
__device__ __align__(8) int2 g_epack[MAXE];   // {src | comb<<18, bitcast(norm)}

// ====================== helpers ======================
__device__ __forceinline__ uint32_t smem_u32(const void* p) {
    uint32_t a;
    asm("{ .reg .u64 t; cvta.to.shared.u64 t, %1; cvt.u32.u64 %0, t; }" : "=r"(a) : "l"(p));
    return a;
}

#define LDMX4(r, addr) \
    asm volatile("ldmatrix.sync.aligned.m8n8.x4.shared.b16 {%0,%1,%2,%3}, [%4];" \
        : "=r"((r)[0]), "=r"((r)[1]), "=r"((r)[2]), "=r"((r)[3]) : "r"(addr))

__device__ __forceinline__ void mma16816(float* c, const uint32_t* a,
                                         uint32_t b0, uint32_t b1) {
    asm volatile(
        "mma.sync.aligned.m16n8k16.row.col.f32.f16.f16.f32 "
        "{%0,%1,%2,%3},{%4,%5,%6,%7},{%8,%9},{%0,%1,%2,%3};"
        : "+f"(c[0]), "+f"(c[1]), "+f"(c[2]), "+f"(c[3])
        : "r"(a[0]), "r"(a[1]), "r"(a[2]), "r"(a[3]), "r"(b0), "r"(b1));
}

__device__ __forceinline__ uint32_t pack_hf(float a, float b) {
    __half2 t = __floats2half2_rn(a, b);
    return *(uint32_t*)&t;
}
__device__ __forceinline__ void unpack8(uint4 u, float* f) {
    __half2* h = (__half2*)&u;
#pragma unroll
    for (int i = 0; i < 4; i++) {
        float2 v = __half22float2(h[i]);
        f[2 * i] = v.x; f[2 * i + 1] = v.y;
    }
}
// acc[0..7] += nrm * (halves(u) + ec[c..c+7])
__device__ __forceinline__ void acc8(float* a, uint4 u, const float* ec, int c, float nrm) {
    float f[8];
    unpack8(u, f);
    float4 a0 = *(const float4*)(ec + c);
    float4 a1 = *(const float4*)(ec + c + 4);
    a[0] += nrm * (f[0] + a0.x); a[1] += nrm * (f[1] + a0.y);
    a[2] += nrm * (f[2] + a0.z); a[3] += nrm * (f[3] + a0.w);
    a[4] += nrm * (f[4] + a1.x); a[5] += nrm * (f[5] + a1.y);
    a[6] += nrm * (f[6] + a1.z); a[7] += nrm * (f[7] + a1.w);
}

// ======== A-resident tensor GEMM (pure fp16 mma.sync, B double-buffered) ========
// A source: Ah (fp16) | xidx (fused embed) | A (fp32).  C sink: C16 | C.
// Optional A-row transforms: x = rmask? memb[k] : x / max(rdivc[row],1);
// then x = relu_opt(scale*x + shift).
// gridDim.y==3 -> blockIdx.y selects the n-tile (junction GEMMs); else all 3.
__global__ __launch_bounds__(256, 2) void k_mma(
    const float* __restrict__ A, const __half* __restrict__ Ah,
    const int* __restrict__ xidx,
    const float* __restrict__ ae1, const float* __restrict__ ae2,
    const __half* __restrict__ Bh,
    float* __restrict__ C, __half* __restrict__ C16, int M, int Nc,
    const float* __restrict__ bias, const float* __restrict__ e1, const float* __restrict__ e2,
    const float* __restrict__ scale, const float* __restrict__ shift, int relu, float oscale,
    const float* __restrict__ rdivc, const float* __restrict__ rmask,
    const float* __restrict__ memb)
{
    extern __shared__ char dsm[];
    __half* sAh_ = (__half*)dsm;
    __half* sBb_[2];
    sBb_[0] = sAh_ + 128 * ASTRA;
    sBb_[1] = sBb_[0] + 128 * ASTRB;

    const int tid = threadIdx.x, lane = tid & 31, warp = tid >> 5;
    const int m0 = blockIdx.x * 128;
    const int warp_m = (warp & 1) * 64;

    const uint32_t sAh = smem_u32(sAh_);
    const uint32_t sB0 = smem_u32(sBb_[0]), sB1 = smem_u32(sBb_[1]);

    const int g = lane >> 3, r = lane & 7;
    const int aRowB = warp_m + (g & 1) * 8 + r;
    const int aColB = (g >> 1) * 8;
    const int bRowG = (g >> 1) * 8 + r;
    const int bColB = (g & 1) * 8;

    const int row = tid >> 1, half_ = tid & 1;
    const int gm = m0 + row;

    const float* arow1 = nullptr;
    const float* arow2 = nullptr;
    if (xidx) {
        int i1 = 0, i2 = 0;
        if (gm < M) { i1 = xidx[2 * gm]; i2 = xidx[2 * gm + 1]; }
        arow1 = ae1 + (size_t)i1 * D;
        arow2 = ae2 + (size_t)i2 * D;
    } else if (A) {
        arow1 = A + (long long)gm * D;
    }
    float rinv = 1.f;
    bool msk = false;
    if (rdivc && gm < M) rinv = 1.f / fmaxf(rdivc[gm], 1.f);
    if (rmask && gm < M) msk = rmask[gm] > 0.5f;

    // ---- stage A once: all 10 k-tiles, transforms -> fp16 ----
    for (int kt = 0; kt < 10; kt++) {
        const int gkb = kt * 32 + half_ * 16;
        float x[16];
        if (Ah) {
            if (gm < M && gkb < HS) {
                const char* base = (const char*)(Ah + (size_t)gm * HS) + gkb * 2;
                uint4 u0 = *(const uint4*)base;
                uint4 u1 = *(const uint4*)(base + 16);
                unpack8(u0, x);
                unpack8(u1, x + 8);
            } else {
#pragma unroll
                for (int q = 0; q < 16; q++) x[q] = 0.f;
            }
        } else {
#pragma unroll
            for (int q = 0; q < 16; q += 4) {
                int k = gkb + q;
                if (gm < M && k + 3 < D) {
                    if (xidx) {
                        float4 v1 = *(const float4*)(arow1 + k);
                        float4 v2 = *(const float4*)(arow2 + k);
                        x[q] = v1.x + v2.x; x[q + 1] = v1.y + v2.y;
                        x[q + 2] = v1.z + v2.z; x[q + 3] = v1.w + v2.w;
                    } else {
                        float4 v = *(const float4*)(arow1 + k);
                        x[q] = v.x; x[q + 1] = v.y; x[q + 2] = v.z; x[q + 3] = v.w;
                    }
                } else {
#pragma unroll
                    for (int j = 0; j < 4; j++) {
                        int kk = k + j;
                        float xv = 0.f;
                        if (gm < M && kk < D)
                            xv = xidx ? (arow1[kk] + arow2[kk]) : arow1[kk];
                        x[q + j] = xv;
                    }
                }
            }
        }
        uint32_t uh[8];
#pragma unroll
        for (int q = 0; q < 16; q += 2) {
            float x0 = x[q], x1 = x[q + 1];
            int k = gkb + q;
            if (k < D && gm < M) {
                x0 = msk ? memb[k] : x0 * rinv;
                if (scale) x0 = fmaf(x0, scale[k], shift[k]);
                if (relu)  x0 = fmaxf(x0, 0.f);
            } else x0 = 0.f;
            if (k + 1 < D && gm < M) {
                x1 = msk ? memb[k + 1] : x1 * rinv;
                if (scale) x1 = fmaf(x1, scale[k + 1], shift[k + 1]);
                if (relu)  x1 = fmaxf(x1, 0.f);
            } else x1 = 0.f;
            uh[q >> 1] = pack_hf(x0, x1);
        }
        uint32_t off = (uint32_t)(row * ASTRA + gkb) * 2;
        *(uint4*)((char*)sAh_ + off)      = make_uint4(uh[0], uh[1], uh[2], uh[3]);
        *(uint4*)((char*)sAh_ + off + 16) = make_uint4(uh[4], uh[5], uh[6], uh[7]);
    }

    // ---- n-tiles: widths {128, 128, 64}; gridDim.y==3 -> one tile per CTA ----
    int ntb = 0, nte = 2;
    if (gridDim.y > 1) { ntb = nte = (int)blockIdx.y; }
    for (int nt = ntb; nt <= nte; nt++) {
        const int n0 = nt * 128;
        const int width = (nt < 2) ? 128 : 64;
        const int nb = (nt < 2) ? 2 : 1;
        const int warp_n = (warp >> 1) * ((nt < 2) ? 32 : 16);
        const int items = width * 4;

        float acc[4][4][4];
#pragma unroll
        for (int i = 0; i < 4; i++)
#pragma unroll
            for (int j = 0; j < 4; j++)
#pragma unroll
                for (int q = 0; q < 4; q++) acc[i][j][q] = 0.f;

        uint4 pre[2];
#pragma unroll
        for (int t = 0; t < 2; t++) {
            int item = tid + t * 256;
            if (item < items) {
                int rr = item >> 2, q = item & 3;
                pre[t] = *(const uint4*)(Bh + (size_t)(n0 + rr) * KP + q * 8);
            }
        }
#pragma unroll
        for (int t = 0; t < 2; t++) {
            int item = tid + t * 256;
            if (item < items) {
                int rr = item >> 2, q = item & 3;
                *(uint4*)((char*)sBb_[0] + (uint32_t)(rr * ASTRB + q * 8) * 2) = pre[t];
            }
        }
        __syncthreads();

        for (int kt = 0; kt < 10; kt++) {
            if (kt < 9) {
#pragma unroll
                for (int t = 0; t < 2; t++) {
                    int item = tid + t * 256;
                    if (item < items) {
                        int rr = item >> 2, q = item & 3;
                        pre[t] = *(const uint4*)(Bh + (size_t)(n0 + rr) * KP + (kt + 1) * 32 + q * 8);
                    }
                }
            }
            const uint32_t sBc = (kt & 1) ? sB1 : sB0;
            const int k0 = kt * 32;
#pragma unroll
            for (int kh = 0; kh < 32; kh += 16) {
                uint32_t ah[4][4];
#pragma unroll
                for (int mt = 0; mt < 4; mt++) {
                    uint32_t off = (uint32_t)((aRowB + mt * 16) * ASTRA + k0 + kh + aColB) * 2;
                    LDMX4(ah[mt], sAh + off);
                }
                uint32_t bh2[2][4];
                for (int bt = 0; bt < nb; bt++) {
                    uint32_t off = (uint32_t)((warp_n + bt * 16 + bRowG) * ASTRB + kh + bColB) * 2;
                    LDMX4(bh2[bt], sBc + off);
                }
#pragma unroll
                for (int mt = 0; mt < 4; mt++)
                    for (int ns = 0; ns < nb * 2; ns++) {
                        uint32_t b0 = bh2[ns >> 1][(ns & 1) * 2];
                        uint32_t b1 = bh2[ns >> 1][(ns & 1) * 2 + 1];
                        mma16816(acc[mt][ns], ah[mt], b0, b1);
                    }
            }
            if (kt < 9) {
                int nbuf = (kt + 1) & 1;
#pragma unroll
                for (int t = 0; t < 2; t++) {
                    int item = tid + t * 256;
                    if (item < items) {
                        int rr = item >> 2, q = item & 3;
                        *(uint4*)((char*)sBb_[nbuf] + (uint32_t)(rr * ASTRB + q * 8) * 2) = pre[t];
                    }
                }
            }
            __syncthreads();
        }

        for (int ns = 0; ns < nb * 2; ns++) {
            int gn = n0 + warp_n + ns * 8 + (lane & 3) * 2;
            if (gn >= Nc) continue;
            float add0 = 0.f, add1 = 0.f;
            if (bias) { add0 += bias[gn]; add1 += bias[gn + 1]; }
            if (e1)   { add0 += e1[gn] + e2[gn]; add1 += e1[gn + 1] + e2[gn + 1]; }
#pragma unroll
            for (int mt = 0; mt < 4; mt++) {
                int gr0 = m0 + warp_m + mt * 16 + (lane >> 2);
#pragma unroll
                for (int hh = 0; hh < 2; hh++) {
                    int gr = gr0 + hh * 8;
                    if (gr >= M) continue;
                    float o0 = (acc[mt][ns][2 * hh] + add0) * oscale;
                    float o1 = (acc[mt][ns][2 * hh + 1] + add1) * oscale;
                    if (C16) {
                        *(uint32_t*)((char*)(C16 + (size_t)gr * HS) + gn * 2) = pack_hf(o0, o1);
                    } else {
                        *(float2*)(C + (long long)gr * Nc + gn) = make_float2(o0, o1);
                    }
                }
            }
        }
    }
}

// ---- convert fp32 weights into padded fp16 ----
__global__ void k_wh(const float* __restrict__ W, __half* __restrict__ wh, int nmat) {
    int idx = blockIdx.x * blockDim.x + threadIdx.x;
    if (idx >= nmat * WMAT) return;
    int m = idx / WMAT, rr = idx - m * WMAT;
    int n = rr / KP, k = rr - n * KP;
    float v = (n < D && k < D) ? W[(long long)m * D * D + n * D + k] : 0.f;
    wh[idx] = __float2half_rn(v);
}

// ---------------- degree + histogram in one pass ----------------
__global__ void k_count(const int* __restrict__ ei, int* __restrict__ ideg,
                        int* __restrict__ cnt, int E) {
    int i = blockIdx.x * blockDim.x + threadIdx.x;
    if (i < E) {
        atomicAdd(&ideg[ei[i]], 1);
        atomicAdd(&cnt[ei[E + i]], 1);
    }
}

__global__ void k_degfin(const int* __restrict__ ideg, float* __restrict__ dinv,
                         float* __restrict__ snorm, int n) {
    int i = blockIdx.x * blockDim.x + threadIdx.x;
    if (i >= n) return;
    float v = rsqrtf((float)(1 + ideg[i]));   // self-loop adds 1
    dinv[i] = v;
    snorm[i] = v * v;
}

// ---------------- CSR build ----------------
__global__ void k_scan1(const int* __restrict__ cnt, int* __restrict__ bsum, int N) {
    __shared__ int sh[256];
    int base = blockIdx.x * 2048 + threadIdx.x * 8;
    int s = 0;
#pragma unroll
    for (int i = 0; i < 8; i++) if (base + i < N) s += cnt[base + i];
    sh[threadIdx.x] = s;
    __syncthreads();
    for (int o = 128; o; o >>= 1) {
        if (threadIdx.x < o) sh[threadIdx.x] += sh[threadIdx.x + o];
        __syncthreads();
    }
    if (threadIdx.x == 0) bsum[blockIdx.x] = sh[0];
}

__global__ void k_scan2(int* __restrict__ bsum, int* __restrict__ rowptrN, int nb) {
    int running = 0;
    for (int i = 0; i < nb; i++) {
        int t = bsum[i];
        bsum[i] = running;
        running += t;
    }
    *rowptrN = running;
}

__global__ void k_scan3(const int* __restrict__ cnt, const int* __restrict__ bsum,
                        int* __restrict__ rowptr, int* __restrict__ cursor, int N) {
    __shared__ int wsum[8];
    int tid = threadIdx.x, lane = tid & 31, w = tid >> 5;
    int base = blockIdx.x * 2048 + tid * 8;
    int c[8];
    int s = 0;
#pragma unroll
    for (int i = 0; i < 8; i++) {
        c[i] = (base + i < N) ? cnt[base + i] : 0;
        s += c[i];
    }
    int inc = s;
    for (int o = 1; o < 32; o <<= 1) {
        int t = __shfl_up_sync(0xffffffffu, inc, o);
        if (lane >= o) inc += t;
    }
    if (lane == 31) wsum[w] = inc;
    __syncthreads();
    if (tid == 0) {
        int rr = 0;
        for (int i = 0; i < 8; i++) { int t = wsum[i]; wsum[i] = rr; rr += t; }
    }
    __syncthreads();
    int run = bsum[blockIdx.x] + wsum[w] + inc - s;
#pragma unroll
    for (int i = 0; i < 8; i++)
        if (base + i < N) { rowptr[base + i] = run; cursor[base + i] = run; run += c[i]; }
}

__global__ void k_place(const int* __restrict__ ei, const int* __restrict__ ea,
                        const float* __restrict__ dinv, int* __restrict__ cursor,
                        int2* __restrict__ epack, int E) {
    int i = blockIdx.x * blockDim.x + threadIdx.x;
    if (i >= E) return;
    int src = ei[i], dst = ei[E + i];
    float nrm = dinv[src] * dinv[dst];
    int comb = ea[2 * i] * 3 + ea[2 * i + 1];
    int p = atomicAdd(&cursor[dst], 1);
    epack[p] = make_int2(src | (comb << 18), __float_as_int(nrm));
}

// ---------------- CSR gather-aggregate (fp16 buffers, smem eec) + BN stats ----------------
__global__ __launch_bounds__(256) void k_gather(
    const __half* __restrict__ T, __half* __restrict__ AGG,
    const int2* __restrict__ epack, const int* __restrict__ rowptr,
    const float* __restrict__ snorm,
    const float* __restrict__ ee1, const float* __restrict__ ee2,
    float* __restrict__ stats, int N)
{
    __shared__ __align__(16) float seec[18 * HS];
    __shared__ float sst[2 * HS];
    for (int i = threadIdx.x; i < 18 * HS; i += 256) {
        int rr = i / HS, c = i - rr * HS;
        seec[i] = (c < D) ? ee1[(rr / 3) * D + c] + ee2[(rr % 3) * D + c] : 0.f;
    }
    for (int i = threadIdx.x; i < 2 * HS; i += 256) sst[i] = 0.f;
    __syncthreads();

    const int lane = threadIdx.x & 31, w = threadIdx.x >> 5;
    const int gw = blockIdx.x * 8 + w, nw = gridDim.x * 8;
    const bool hi = lane < (HI4 - 32);     // lane < 6: owns item lane+32
    const int c0 = lane * 8, c1 = (lane + 32) * 8;

    float lsum[16], lsq[16];
#pragma unroll
    for (int i = 0; i < 16; i++) { lsum[i] = 0.f; lsq[i] = 0.f; }

    const float* e12 = seec + 12 * HS;   // self-loop: bt=4, bd=0

    for (int node = gw; node < N; node += nw) {
        float acc[16];
#pragma unroll
        for (int q = 0; q < 16; q++) acc[q] = 0.f;
        float sn = snorm[node];
        const uint4* ts = (const uint4*)(T + (size_t)node * HS);
        acc8(acc, ts[lane], e12, c0, sn);
        if (hi) acc8(acc + 8, ts[lane + 32], e12, c1, sn);

        int p = rowptr[node], pend = rowptr[node + 1];
        for (; p + 2 <= pend; p += 2) {
            int2 e0 = epack[p], e1 = epack[p + 1];
            const uint4* t0 = (const uint4*)(T + (size_t)(e0.x & 0x3FFFF) * HS);
            const uint4* t1 = (const uint4*)(T + (size_t)(e1.x & 0x3FFFF) * HS);
            float n0 = __int_as_float(e0.y), n1 = __int_as_float(e1.y);
            const float* ec0 = seec + (e0.x >> 18) * HS;
            const float* ec1 = seec + (e1.x >> 18) * HS;
            uint4 u0a = t0[lane], u1a = t1[lane];
            uint4 u0b, u1b;
            if (hi) { u0b = t0[lane + 32]; u1b = t1[lane + 32]; }
            acc8(acc, u0a, ec0, c0, n0);
            acc8(acc, u1a, ec1, c0, n1);
            if (hi) {
                acc8(acc + 8, u0b, ec0, c1, n0);
                acc8(acc + 8, u1b, ec1, c1, n1);
            }
        }
        if (p < pend) {
            int2 e0 = epack[p];
            const uint4* t0 = (const uint4*)(T + (size_t)(e0.x & 0x3FFFF) * HS);
            float n0 = __int_as_float(e0.y);
            const float* ec0 = seec + (e0.x >> 18) * HS;
            acc8(acc, t0[lane], ec0, c0, n0);
            if (hi) acc8(acc + 8, t0[lane + 32], ec0, c1, n0);
        }

        uint4* op = (uint4*)(AGG + (size_t)node * HS);
        {
            uint4 u;
            u.x = pack_hf(acc[0], acc[1]); u.y = pack_hf(acc[2], acc[3]);
            u.z = pack_hf(acc[4], acc[5]); u.w = pack_hf(acc[6], acc[7]);
            op[lane] = u;
        }
        if (hi) {
            uint4 u;
            u.x = pack_hf(acc[8], acc[9]);  u.y = pack_hf(acc[10], acc[11]);
            u.z = pack_hf(acc[12], acc[13]); u.w = pack_hf(acc[14], acc[15]);
            op[lane + 32] = u;
        }
#pragma unroll
        for (int q = 0; q < 16; q++) {
            lsum[q] += acc[q];
            lsq[q] = fmaf(acc[q], acc[q], lsq[q]);
        }
    }
    // flush local stats -> shared -> global
#pragma unroll
    for (int q = 0; q < 8; q++) {
        atomicAdd(&sst[c0 + q], lsum[q]);
        atomicAdd(&sst[HS + c0 + q], lsq[q]);
    }
    if (hi) {
#pragma unroll
        for (int q = 0; q < 8; q++) {
            atomicAdd(&sst[c1 + q], lsum[8 + q]);
            atomicAdd(&sst[HS + c1 + q], lsq[8 + q]);
        }
    }
    __syncthreads();
    for (int i = threadIdx.x; i < D; i += 256) {
        atomicAdd(&stats[i], sst[i]);
        atomicAdd(&stats[D + i], sst[HS + i]);
    }
}

// reads stats, computes BN affine, then ZEROES stats (replay-safe reset)
__global__ void k_bnfin(float* __restrict__ st, const float* __restrict__ gamma,
                        const float* __restrict__ beta, float* __restrict__ sc,
                        float* __restrict__ sh, float invn) {
    int c = threadIdx.x;
    if (c >= D) return;
    float mean = st[c] * invn;
    float var = fmaxf(st[D + c] * invn - mean * mean, 0.f);
    float s = gamma[c] / sqrtf(var + 1e-5f);
    sc[c] = s;
    sh[c] = beta[c] - mean * s;
    st[c] = 0.f;
    st[D + c] = 0.f;
}

// ---------------- mean pooling (sums; division folded downstream) ----------------
__global__ void k_poolh(const __half* __restrict__ A, const int* __restrict__ ids,
                        float* __restrict__ pool, float* __restrict__ cnt,
                        const float* __restrict__ scale, const float* __restrict__ shift, int n)
{
    int w = (blockIdx.x * blockDim.x + threadIdx.x) >> 5;
    int lane = threadIdx.x & 31;
    if (w >= n) return;
    int id = ids[w];
    if (lane == 0) atomicAdd(&cnt[id], 1.0f);
    const uint4* ap = (const uint4*)(A + (size_t)w * HS);
    float* op = pool + (size_t)id * D;
    for (int it = lane; it < HI4; it += 32) {
        float f[8];
        unpack8(ap[it], f);
        int c = it * 8;
#pragma unroll
        for (int q = 0; q < 8; q++) {
            if (c + q < D) f[q] = fmaf(f[q], scale[c + q], shift[c + q]);
        }
        asm volatile("red.global.add.v4.f32 [%0], {%1,%2,%3,%4};"
                     :: "l"(op + c), "f"(f[0]), "f"(f[1]), "f"(f[2]), "f"(f[3]) : "memory");
        if (it < HI4 - 1)
            asm volatile("red.global.add.v4.f32 [%0], {%1,%2,%3,%4};"
                         :: "l"(op + c + 4), "f"(f[4]), "f"(f[5]), "f"(f[6]), "f"(f[7]) : "memory");
    }
}

__global__ void k_poolf(const float* __restrict__ A, const int* __restrict__ ids,
                        float* __restrict__ pool, float* __restrict__ cnt, int n)
{
    int w = (blockIdx.x * blockDim.x + threadIdx.x) >> 5;
    int lane = threadIdx.x & 31;
    if (w >= n) return;
    int id = ids[w];
    if (lane == 0) atomicAdd(&cnt[id], 1.0f);
    const float4* ap = (const float4*)(A + (long long)w * D);
    float* op = pool + (long long)id * D;
    for (int idx = lane; idx < D4; idx += 32) {
        float4 v = ap[idx];
        asm volatile("red.global.add.v4.f32 [%0], {%1,%2,%3,%4};"
                     :: "l"(op + 4 * idx), "f"(v.x), "f"(v.y), "f"(v.z), "f"(v.w) : "memory");
    }
}

__global__ void k_l2norm(const float* __restrict__ A, float* __restrict__ out, int n) {
    int w = (blockIdx.x * blockDim.x + threadIdx.x) >> 5;
    int lane = threadIdx.x & 31;
    if (w >= n) return;
    const float4* ap = (const float4*)(A + (long long)w * D);
    float s = 0.f;
    for (int idx = lane; idx < D4; idx += 32) {
        float4 v = ap[idx];
        s += v.x * v.x + v.y * v.y + v.z * v.z + v.w * v.w;
    }
#pragma unroll
    for (int o = 16; o; o >>= 1) s += __shfl_xor_sync(0xffffffffu, s, o);
    float inv = 1.0f / fmaxf(sqrtf(s), 1e-12f);
    float4* op = (float4*)(out + (long long)w * D);
    for (int idx = lane; idx < D4; idx += 32) {
        float4 v = ap[idx];
        op[idx] = make_float4(v.x * inv, v.y * inv, v.z * inv, v.w * inv);
    }
}

// ---------------- FFMA2 GEMM (exact fp32, logits only) ----------------
__global__ __launch_bounds__(256) void k_gemm(
    const float* __restrict__ A, const float* __restrict__ B, float* __restrict__ C,
    int M, int Nc, int K, float oscale)
{
    __shared__ float As[32][130];
    __shared__ float Bs[32][68];

    const int tid = threadIdx.x;
    const int tx = tid & 15, ty = tid >> 4;
    const int m0 = blockIdx.y * 128, n0 = blockIdx.x * 64;

    unsigned long long acc[4][4];
#pragma unroll
    for (int i = 0; i < 4; i++)
#pragma unroll
        for (int j = 0; j < 4; j++) acc[i][j] = 0ull;

    const int nk = (K + 31) >> 5;
    for (int kt = 0; kt < nk; kt++) {
        const int k0 = kt << 5;
#pragma unroll
        for (int i = 0; i < 4; i++) {
            int e = i * 256 + tid;
            int k4 = e & 7, rr = e >> 3;
            int gmm = m0 + rr, gk = k0 + 4 * k4;
            float4 v = make_float4(0.f, 0.f, 0.f, 0.f);
            if (gmm < M && gk < K)
                v = *(const float4*)(A + (long long)gmm * K + gk);
            As[4 * k4 + 0][rr] = v.x; As[4 * k4 + 1][rr] = v.y;
            As[4 * k4 + 2][rr] = v.z; As[4 * k4 + 3][rr] = v.w;
        }
#pragma unroll
        for (int i = 0; i < 2; i++) {
            int e = i * 256 + tid;
            int k4 = e & 7, rr = e >> 3;
            int gn = n0 + rr, gk = k0 + 4 * k4;
            float4 v = make_float4(0.f, 0.f, 0.f, 0.f);
            if (gn < Nc && gk < K)
                v = *(const float4*)(B + (long long)gn * K + gk);
            Bs[4 * k4 + 0][rr] = v.x; Bs[4 * k4 + 1][rr] = v.y;
            Bs[4 * k4 + 2][rr] = v.z; Bs[4 * k4 + 3][rr] = v.w;
        }
        __syncthreads();
#pragma unroll
        for (int kk = 0; kk < 32; kk++) {
            unsigned long long a2[4];
#pragma unroll
            for (int i = 0; i < 4; i++)
                a2[i] = *(const unsigned long long*)&As[kk][ty * 8 + 2 * i];
            float4 bv = *(const float4*)&Bs[kk][tx * 4];
            unsigned long long b2[4];
            {
                unsigned u0 = __float_as_uint(bv.x), u1 = __float_as_uint(bv.y);
                unsigned u2 = __float_as_uint(bv.z), u3 = __float_as_uint(bv.w);
                asm("mov.b64 %0, {%1,%1};" : "=l"(b2[0]) : "r"(u0));
                asm("mov.b64 %0, {%1,%1};" : "=l"(b2[1]) : "r"(u1));
                asm("mov.b64 %0, {%1,%1};" : "=l"(b2[2]) : "r"(u2));
                asm("mov.b64 %0, {%1,%1};" : "=l"(b2[3]) : "r"(u3));
            }
#pragma unroll
            for (int i = 0; i < 4; i++)
#pragma unroll
                for (int j = 0; j < 4; j++)
                    asm("fma.rn.f32x2 %0, %1, %2, %3;"
                        : "=l"(acc[i][j]) : "l"(a2[i]), "l"(b2[j]), "l"(acc[i][j]));
        }
        __syncthreads();
    }

#pragma unroll
    for (int i = 0; i < 4; i++) {
#pragma unroll
        for (int j = 0; j < 4; j++) {
            int gn = n0 + tx * 4 + j;
            if (gn >= Nc) continue;
            float lo = __uint_as_float((unsigned)(acc[i][j] & 0xffffffffull));
            float hi = __uint_as_float((unsigned)(acc[i][j] >> 32));
            int gmm = m0 + ty * 8 + 2 * i;
            if (gmm < M)     C[(long long)gmm * Nc + gn] = lo * oscale;
            if (gmm + 1 < M) C[(long long)(gmm + 1) * Nc + gn] = hi * oscale;
        }
    }
}

// ---------------- host ----------------
static float* symaddr(const void* sym) {
    void* p = nullptr;
    cudaGetSymbolAddress(&p, sym);
    return (float*)p;
}

extern "C" void kernel_launch(void* const* d_in, const int* in_sizes, int n_in,
                              void* d_out, int out_size) {
    const int*   batch_x  = (const int*)d_in[0];
    const int*   batch_ei = (const int*)d_in[1];
    const int*   batch_ea = (const int*)d_in[2];
    const int*   batch_gid= (const int*)d_in[3];
    const int*   frag_x   = (const int*)d_in[4];
    const int*   frag_ei  = (const int*)d_in[5];
    const int*   frag_ea  = (const int*)d_in[6];
    const int*   frag_jid = (const int*)d_in[7];
    const int*   jct_gid  = (const int*)d_in[8];
    const float* jmask    = (const float*)d_in[9];
    const float* ae1      = (const float*)d_in[10];
    const float* ae2      = (const float*)d_in[11];
    const float* gW       = (const float*)d_in[12];
    const float* gb       = (const float*)d_in[13];
    const float* gee1     = (const float*)d_in[14];
    const float* gee2     = (const float*)d_in[15];
    const float* bng      = (const float*)d_in[16];
    const float* bnb      = (const float*)d_in[17];
    const float* jW       = (const float*)d_in[18];
    const float* jb       = (const float*)d_in[19];
    const float* jee1     = (const float*)d_in[20];
    const float* jee2     = (const float*)d_in[21];
    const float* memb     = (const float*)d_in[22];

    const int N  = in_sizes[0] / 2;
    const int E  = in_sizes[1] / 2;
    const int NJ = in_sizes[8];
    const int NG = 1024;
    const int SB = (N + 2047) / 2048;

    __half* buf0h = (__half*)symaddr(g_buf0h);
    __half* buf1h = (__half*)symaddr(g_buf1h);
    float* degp   = symaddr(g_deg);
    float* snormp = symaddr(g_snorm);
    float* statsp = symaddr(g_stats);
    float* scalep = symaddr(g_scale);
    float* shiftp = symaddr(g_shift);
    float* poolp  = symaddr(g_pool);
    float* cntp   = symaddr(g_cnt);
    float* t0p    = symaddr(g_t0);
    float* t1p    = symaddr(g_t1);
    float* f0p    = symaddr(g_f0);
    float* f1p    = symaddr(g_f1);
    int*   rowptr = (int*)symaddr(g_rowptr);
    int*   cursor = (int*)symaddr(g_cursor);
    int*   idegp  = (int*)symaddr(g_ideg);
    int*   bsum   = (int*)symaddr(g_bsum);
    int2*  epack  = (int2*)symaddr(g_epack);
    __half* whp   = (__half*)symaddr(g_wh);

    cudaFuncSetAttribute(k_mma, cudaFuncAttributeMaxDynamicSharedMemorySize, MMA_SMEM);

    k_wh<<<(5 * WMAT + 255) / 256, 256>>>(gW, whp, 5);
    k_wh<<<(2 * WMAT + 255) / 256, 256>>>(jW, whp + (size_t)5 * WMAT, 2);

    // GNN layer GEMM: fp16 in (or fused embed), fp16 out; all 3 n-tiles per CTA
    auto tgemm16 = [&](const __half* Ah, const int* xidx, int mat, __half* C16, int M,
                       const float* bias, const float* sc, const float* sh, int relu) {
        k_mma<<<dim3((M + 127) / 128, 1), 256, MMA_SMEM>>>(
            nullptr, Ah, xidx, ae1, ae2, whp + (size_t)mat * WMAT,
            nullptr, C16, M, D, bias, nullptr, nullptr, sc, sh, relu, 1.0f,
            nullptr, nullptr, nullptr);
    };
    // Junction GEMM: fp32 in/out; n-tiles split over gridDim.y; optional div/mask
    auto tgemm32 = [&](const float* A, int mat, float* C, int M,
                       const float* bias, const float* e1, const float* e2, int relu,
                       const float* rdivc, const float* rmask) {
        k_mma<<<dim3((M + 127) / 128, 3), 256, MMA_SMEM>>>(
            A, nullptr, nullptr, ae1, ae2, whp + (size_t)mat * WMAT,
            C, nullptr, M, D, bias, e1, e2, nullptr, nullptr, relu, 1.0f,
            rdivc, rmask, memb);
    };

    auto run_gnn = [&](const int* x, const int* ei, const int* ea) {
        cudaMemsetAsync(idegp, 0, (size_t)N * sizeof(int));
        cudaMemsetAsync(cursor, 0, (size_t)N * sizeof(int));
        k_count<<<(E + 255) / 256, 256>>>(ei, idegp, cursor, E);
        k_degfin<<<(N + 255) / 256, 256>>>(idegp, degp, snormp, N);
        k_scan1<<<SB, 256>>>(cursor, bsum, N);
        k_scan2<<<1, 1>>>(bsum, rowptr + N, SB);
        k_scan3<<<SB, 256>>>(cursor, bsum, rowptr, cursor, N);
        k_place<<<(E + 255) / 256, 256>>>(ei, ea, degp, cursor, epack, E);

        for (int l = 0; l < 5; l++) {
            const float* sc = l ? scalep : nullptr;
            const float* sh = l ? shiftp : nullptr;
            tgemm16(l ? buf0h : nullptr, l ? nullptr : x, l, buf1h, N,
                    gb + l * D, sc, sh, l ? 1 : 0);
            k_gather<<<592, 256>>>(buf1h, buf0h, epack, rowptr, snormp,
                                   gee1 + (long long)l * 6 * D,
                                   gee2 + (long long)l * 3 * D, statsp, N);
            k_bnfin<<<1, D>>>(statsp, bng + l * D, bnb + l * D, scalep, shiftp, 1.0f / (float)N);
        }
    };

    // ---------- branch 0 ----------
    run_gnn(batch_x, batch_ei, batch_ea);
    cudaMemsetAsync(poolp, 0, (size_t)NG * D * sizeof(float));
    cudaMemsetAsync(cntp, 0, NG * sizeof(float));
    k_poolh<<<(N * 32 + 255) / 256, 256>>>(buf0h, batch_gid, poolp, cntp, scalep, shiftp, N);
    tgemm32(poolp, 5, t0p, NG, jb, jee1 + 4 * D, jee2, 0, cntp, nullptr);
    tgemm32(t0p, 6, t1p, NG, jb + D, jee1 + (6 + 4) * D, jee2 + 3 * D, 1, nullptr, nullptr);
    k_l2norm<<<(NG * 32 + 255) / 256, 256>>>(t1p, f0p, NG);

    // ---------- branch 1 ----------
    run_gnn(frag_x, frag_ei, frag_ea);
    cudaMemsetAsync(poolp, 0, (size_t)NJ * D * sizeof(float));
    cudaMemsetAsync(cntp, 0, NJ * sizeof(float));
    k_poolh<<<(N * 32 + 255) / 256, 256>>>(buf0h, frag_jid, poolp, cntp, scalep, shiftp, N);
    tgemm32(poolp, 5, t0p, NJ, jb, jee1 + 4 * D, jee2, 0, cntp, jmask);
    tgemm32(t0p, 6, t1p, NJ, jb + D, jee1 + (6 + 4) * D, jee2 + 3 * D, 1, nullptr, nullptr);
    cudaMemsetAsync(poolp, 0, (size_t)NG * D * sizeof(float));
    cudaMemsetAsync(cntp, 0, NG * sizeof(float));
    k_poolf<<<(NJ * 32 + 255) / 256, 256>>>(t1p, jct_gid, poolp, cntp, NJ);
    // mean-pool division omitted: l2norm is row-scale invariant
    k_l2norm<<<(NG * 32 + 255) / 256, 256>>>(poolp, f1p, NG);

    // ---------- logits = (f0 @ f1^T) / TEMP ----------
    {
        dim3 gl((NG + 63) / 64, (NG + 127) / 128);
        k_gemm<<<gl, 256>>>(f0p, f1p, (float*)d_out, NG, NG, D, 25.0f);
    }
}

// round 15
// speedup vs baseline: 2.3282x; 1.0194x over previous
#include <cuda_runtime.h>
#include <cuda_fp16.h>
#include <cstdint>
#include <cstdio>

#define D    300
#define D4   75
#define HS   304                  // fp16 buffer row stride (halves); 608 B, 16B-aligned
#define HI4  38                   // uint4 (8-half) items per fp16 row
#define MAXN 200000
#define MAXE 400000
#define NGR  1024
#define NJC  8192

#define KP    320
#define NPAD  320
#define WMAT  (NPAD * KP)
#define ASTRA 328
#define ASTRB 40

#define MMA_SMEM ((128 * ASTRA + 2 * 128 * ASTRB) * 2)

// ---------------- scratch (static device memory; no allocs) ----------------
__device__ __align__(16) __half g_buf0h[(size_t)MAXN * HS + 32];
__device__ __align__(16) __half g_buf1h[(size_t)MAXN * HS + 32];
__device__ float g_deg[MAXN];      // dinv
__device__ float g_snorm[MAXN];
__device__ float g_stats[2 * D];   // zero at start of every replay (bnfin restores)
__device__ float g_scale[D];
__device__ float g_shift[D];
__device__ __align__(16) float g_pool[(size_t)NJC * D];
__device__ float g_cnt[NJC];
__device__ __align__(16) float g_t0[(size_t)NJC * D];
__device__ __align__(16) float g_t1[(size_t)NJC * D];
__device__ __align__(16) float g_f0[(size_t)NGR * D];
__device__ __align__(16) float g_f1[(size_t)NGR * D];
__device__ __align__(16) __half g_wh[(size_t)7 * WMAT];
// edge CSR
__device__ int  g_rowptr[MAXN + 1];
__device__ int  g_cursor[MAXN];
__device__ int  g_cnte[MAXN];      // dst histogram; zeroed by scan3 (replay-safe)
__device__ int  g_ideg[MAXN];      // src degree; zeroed by scan1 (replay-safe)
__device__ int  g_bsum[256];
__device__ __align__(8) int2 g_epack[MAXE];   // {src | comb<<18, bitcast(norm)}
// pool CSR
__device__ int  g_pcnt[NJC];       // zeroed by pscan (replay-safe)
__device__ int  g_prow[NJC + 1];
__device__ int  g_pcur[NJC];
__device__ int  g_pidx[MAXN];

// ====================== helpers ======================
__device__ __forceinline__ uint32_t smem_u32(const void* p) {
    uint32_t a;
    asm("{ .reg .u64 t; cvta.to.shared.u64 t, %1; cvt.u32.u64 %0, t; }" : "=r"(a) : "l"(p));
    return a;
}

#define LDMX4(r, addr) \
    asm volatile("ldmatrix.sync.aligned.m8n8.x4.shared.b16 {%0,%1,%2,%3}, [%4];" \
        : "=r"((r)[0]), "=r"((r)[1]), "=r"((r)[2]), "=r"((r)[3]) : "r"(addr))

__device__ __forceinline__ void mma16816(float* c, const uint32_t* a,
                                         uint32_t b0, uint32_t b1) {
    asm volatile(
        "mma.sync.aligned.m16n8k16.row.col.f32.f16.f16.f32 "
        "{%0,%1,%2,%3},{%4,%5,%6,%7},{%8,%9},{%0,%1,%2,%3};"
        : "+f"(c[0]), "+f"(c[1]), "+f"(c[2]), "+f"(c[3])
        : "r"(a[0]), "r"(a[1]), "r"(a[2]), "r"(a[3]), "r"(b0), "r"(b1));
}

__device__ __forceinline__ uint32_t pack_hf(float a, float b) {
    __half2 t = __floats2half2_rn(a, b);
    return *(uint32_t*)&t;
}
__device__ __forceinline__ void unpack8(uint4 u, float* f) {
    __half2* h = (__half2*)&u;
#pragma unroll
    for (int i = 0; i < 4; i++) {
        float2 v = __half22float2(h[i]);
        f[2 * i] = v.x; f[2 * i + 1] = v.y;
    }
}
__device__ __forceinline__ void acc8(float* a, uint4 u, const float* ec, int c, float nrm) {
    float f[8];
    unpack8(u, f);
    float4 a0 = *(const float4*)(ec + c);
    float4 a1 = *(const float4*)(ec + c + 4);
    a[0] += nrm * (f[0] + a0.x); a[1] += nrm * (f[1] + a0.y);
    a[2] += nrm * (f[2] + a0.z); a[3] += nrm * (f[3] + a0.w);
    a[4] += nrm * (f[4] + a1.x); a[5] += nrm * (f[5] + a1.y);
    a[6] += nrm * (f[6] + a1.z); a[7] += nrm * (f[7] + a1.w);
}

// ======== A-resident tensor GEMM (pure fp16 mma.sync, B double-buffered) ========
__global__ __launch_bounds__(256, 2) void k_mma(
    const float* __restrict__ A, const __half* __restrict__ Ah,
    const int* __restrict__ xidx,
    const float* __restrict__ ae1, const float* __restrict__ ae2,
    const __half* __restrict__ Bh,
    float* __restrict__ C, __half* __restrict__ C16, int M, int Nc,
    const float* __restrict__ bias, const float* __restrict__ e1, const float* __restrict__ e2,
    const float* __restrict__ scale, const float* __restrict__ shift, int relu, float oscale,
    const float* __restrict__ rdivc, const float* __restrict__ rmask,
    const float* __restrict__ memb)
{
    extern __shared__ char dsm[];
    __half* sAh_ = (__half*)dsm;
    __half* sBb_[2];
    sBb_[0] = sAh_ + 128 * ASTRA;
    sBb_[1] = sBb_[0] + 128 * ASTRB;

    const int tid = threadIdx.x, lane = tid & 31, warp = tid >> 5;
    const int m0 = blockIdx.x * 128;
    const int warp_m = (warp & 1) * 64;

    const uint32_t sAh = smem_u32(sAh_);
    const uint32_t sB0 = smem_u32(sBb_[0]), sB1 = smem_u32(sBb_[1]);

    const int g = lane >> 3, r = lane & 7;
    const int aRowB = warp_m + (g & 1) * 8 + r;
    const int aColB = (g >> 1) * 8;
    const int bRowG = (g >> 1) * 8 + r;
    const int bColB = (g & 1) * 8;

    const int row = tid >> 1, half_ = tid & 1;
    const int gm = m0 + row;

    const float* arow1 = nullptr;
    const float* arow2 = nullptr;
    if (xidx) {
        int i1 = 0, i2 = 0;
        if (gm < M) { i1 = xidx[2 * gm]; i2 = xidx[2 * gm + 1]; }
        arow1 = ae1 + (size_t)i1 * D;
        arow2 = ae2 + (size_t)i2 * D;
    } else if (A) {
        arow1 = A + (long long)gm * D;
    }
    float rinv = 1.f;
    bool msk = false;
    if (rdivc && gm < M) rinv = 1.f / fmaxf(rdivc[gm], 1.f);
    if (rmask && gm < M) msk = rmask[gm] > 0.5f;

    for (int kt = 0; kt < 10; kt++) {
        const int gkb = kt * 32 + half_ * 16;
        float x[16];
        if (Ah) {
            if (gm < M && gkb < HS) {
                const char* base = (const char*)(Ah + (size_t)gm * HS) + gkb * 2;
                uint4 u0 = *(const uint4*)base;
                uint4 u1 = *(const uint4*)(base + 16);
                unpack8(u0, x);
                unpack8(u1, x + 8);
            } else {
#pragma unroll
                for (int q = 0; q < 16; q++) x[q] = 0.f;
            }
        } else {
#pragma unroll
            for (int q = 0; q < 16; q += 4) {
                int k = gkb + q;
                if (gm < M && k + 3 < D) {
                    if (xidx) {
                        float4 v1 = *(const float4*)(arow1 + k);
                        float4 v2 = *(const float4*)(arow2 + k);
                        x[q] = v1.x + v2.x; x[q + 1] = v1.y + v2.y;
                        x[q + 2] = v1.z + v2.z; x[q + 3] = v1.w + v2.w;
                    } else {
                        float4 v = *(const float4*)(arow1 + k);
                        x[q] = v.x; x[q + 1] = v.y; x[q + 2] = v.z; x[q + 3] = v.w;
                    }
                } else {
#pragma unroll
                    for (int j = 0; j < 4; j++) {
                        int kk = k + j;
                        float xv = 0.f;
                        if (gm < M && kk < D)
                            xv = xidx ? (arow1[kk] + arow2[kk]) : arow1[kk];
                        x[q + j] = xv;
                    }
                }
            }
        }
        uint32_t uh[8];
#pragma unroll
        for (int q = 0; q < 16; q += 2) {
            float x0 = x[q], x1 = x[q + 1];
            int k = gkb + q;
            if (k < D && gm < M) {
                x0 = msk ? memb[k] : x0 * rinv;
                if (scale) x0 = fmaf(x0, scale[k], shift[k]);
                if (relu)  x0 = fmaxf(x0, 0.f);
            } else x0 = 0.f;
            if (k + 1 < D && gm < M) {
                x1 = msk ? memb[k + 1] : x1 * rinv;
                if (scale) x1 = fmaf(x1, scale[k + 1], shift[k + 1]);
                if (relu)  x1 = fmaxf(x1, 0.f);
            } else x1 = 0.f;
            uh[q >> 1] = pack_hf(x0, x1);
        }
        uint32_t off = (uint32_t)(row * ASTRA + gkb) * 2;
        *(uint4*)((char*)sAh_ + off)      = make_uint4(uh[0], uh[1], uh[2], uh[3]);
        *(uint4*)((char*)sAh_ + off + 16) = make_uint4(uh[4], uh[5], uh[6], uh[7]);
    }

    int ntb = 0, nte = 2;
    if (gridDim.y > 1) { ntb = nte = (int)blockIdx.y; }
    for (int nt = ntb; nt <= nte; nt++) {
        const int n0 = nt * 128;
        const int width = (nt < 2) ? 128 : 64;
        const int nb = (nt < 2) ? 2 : 1;
        const int warp_n = (warp >> 1) * ((nt < 2) ? 32 : 16);
        const int items = width * 4;

        float acc[4][4][4];
#pragma unroll
        for (int i = 0; i < 4; i++)
#pragma unroll
            for (int j = 0; j < 4; j++)
#pragma unroll
                for (int q = 0; q < 4; q++) acc[i][j][q] = 0.f;

        uint4 pre[2];
#pragma unroll
        for (int t = 0; t < 2; t++) {
            int item = tid + t * 256;
            if (item < items) {
                int rr = item >> 2, q = item & 3;
                pre[t] = *(const uint4*)(Bh + (size_t)(n0 + rr) * KP + q * 8);
            }
        }
#pragma unroll
        for (int t = 0; t < 2; t++) {
            int item = tid + t * 256;
            if (item < items) {
                int rr = item >> 2, q = item & 3;
                *(uint4*)((char*)sBb_[0] + (uint32_t)(rr * ASTRB + q * 8) * 2) = pre[t];
            }
        }
        __syncthreads();

        for (int kt = 0; kt < 10; kt++) {
            if (kt < 9) {
#pragma unroll
                for (int t = 0; t < 2; t++) {
                    int item = tid + t * 256;
                    if (item < items) {
                        int rr = item >> 2, q = item & 3;
                        pre[t] = *(const uint4*)(Bh + (size_t)(n0 + rr) * KP + (kt + 1) * 32 + q * 8);
                    }
                }
            }
            const uint32_t sBc = (kt & 1) ? sB1 : sB0;
            const int k0 = kt * 32;
#pragma unroll
            for (int kh = 0; kh < 32; kh += 16) {
                uint32_t ah[4][4];
#pragma unroll
                for (int mt = 0; mt < 4; mt++) {
                    uint32_t off = (uint32_t)((aRowB + mt * 16) * ASTRA + k0 + kh + aColB) * 2;
                    LDMX4(ah[mt], sAh + off);
                }
                uint32_t bh2[2][4];
                for (int bt = 0; bt < nb; bt++) {
                    uint32_t off = (uint32_t)((warp_n + bt * 16 + bRowG) * ASTRB + kh + bColB) * 2;
                    LDMX4(bh2[bt], sBc + off);
                }
#pragma unroll
                for (int mt = 0; mt < 4; mt++)
                    for (int ns = 0; ns < nb * 2; ns++) {
                        uint32_t b0 = bh2[ns >> 1][(ns & 1) * 2];
                        uint32_t b1 = bh2[ns >> 1][(ns & 1) * 2 + 1];
                        mma16816(acc[mt][ns], ah[mt], b0, b1);
                    }
            }
            if (kt < 9) {
                int nbuf = (kt + 1) & 1;
#pragma unroll
                for (int t = 0; t < 2; t++) {
                    int item = tid + t * 256;
                    if (item < items) {
                        int rr = item >> 2, q = item & 3;
                        *(uint4*)((char*)sBb_[nbuf] + (uint32_t)(rr * ASTRB + q * 8) * 2) = pre[t];
                    }
                }
            }
            __syncthreads();
        }

        for (int ns = 0; ns < nb * 2; ns++) {
            int gn = n0 + warp_n + ns * 8 + (lane & 3) * 2;
            if (gn >= Nc) continue;
            float add0 = 0.f, add1 = 0.f;
            if (bias) { add0 += bias[gn]; add1 += bias[gn + 1]; }
            if (e1)   { add0 += e1[gn] + e2[gn]; add1 += e1[gn + 1] + e2[gn + 1]; }
#pragma unroll
            for (int mt = 0; mt < 4; mt++) {
                int gr0 = m0 + warp_m + mt * 16 + (lane >> 2);
#pragma unroll
                for (int hh = 0; hh < 2; hh++) {
                    int gr = gr0 + hh * 8;
                    if (gr >= M) continue;
                    float o0 = (acc[mt][ns][2 * hh] + add0) * oscale;
                    float o1 = (acc[mt][ns][2 * hh + 1] + add1) * oscale;
                    if (C16) {
                        *(uint32_t*)((char*)(C16 + (size_t)gr * HS) + gn * 2) = pack_hf(o0, o1);
                    } else {
                        *(float2*)(C + (long long)gr * Nc + gn) = make_float2(o0, o1);
                    }
                }
            }
        }
    }
}

// ---- convert fp32 weights into padded fp16 ----
__global__ void k_wh(const float* __restrict__ W, __half* __restrict__ wh, int nmat) {
    int idx = blockIdx.x * blockDim.x + threadIdx.x;
    if (idx >= nmat * WMAT) return;
    int m = idx / WMAT, rr = idx - m * WMAT;
    int n = rr / KP, k = rr - n * KP;
    float v = (n < D && k < D) ? W[(long long)m * D * D + n * D + k] : 0.f;
    wh[idx] = __float2half_rn(v);
}

// ---------------- degree + histogram in one pass ----------------
__global__ void k_count(const int* __restrict__ ei, int* __restrict__ ideg,
                        int* __restrict__ cnt, int E) {
    int i = blockIdx.x * blockDim.x + threadIdx.x;
    if (i < E) {
        atomicAdd(&ideg[ei[i]], 1);
        atomicAdd(&cnt[ei[E + i]], 1);
    }
}

// ---------------- CSR build (edge); scan1 fuses degree finalize + ideg reset ---
__global__ void k_scan1(const int* __restrict__ cnt, int* __restrict__ bsum,
                        int* __restrict__ ideg, float* __restrict__ dinv,
                        float* __restrict__ snorm, int N) {
    __shared__ int sh[256];
    int base = blockIdx.x * 2048 + threadIdx.x * 8;
    int s = 0;
#pragma unroll
    for (int i = 0; i < 8; i++) {
        int idx = base + i;
        if (idx < N) {
            s += cnt[idx];
            float v = rsqrtf((float)(1 + ideg[idx]));
            dinv[idx] = v;
            snorm[idx] = v * v;
            ideg[idx] = 0;
        }
    }
    sh[threadIdx.x] = s;
    __syncthreads();
    for (int o = 128; o; o >>= 1) {
        if (threadIdx.x < o) sh[threadIdx.x] += sh[threadIdx.x + o];
        __syncthreads();
    }
    if (threadIdx.x == 0) bsum[blockIdx.x] = sh[0];
}

__global__ void k_scan2(int* __restrict__ bsum, int* __restrict__ rowptrN, int nb) {
    int running = 0;
    for (int i = 0; i < nb; i++) {
        int t = bsum[i];
        bsum[i] = running;
        running += t;
    }
    *rowptrN = running;
}

__global__ void k_scan3(int* __restrict__ cnt, const int* __restrict__ bsum,
                        int* __restrict__ rowptr, int* __restrict__ cursor, int N) {
    __shared__ int wsum[8];
    int tid = threadIdx.x, lane = tid & 31, w = tid >> 5;
    int base = blockIdx.x * 2048 + tid * 8;
    int c[8];
    int s = 0;
#pragma unroll
    for (int i = 0; i < 8; i++) {
        c[i] = (base + i < N) ? cnt[base + i] : 0;
        s += c[i];
    }
    int inc = s;
    for (int o = 1; o < 32; o <<= 1) {
        int t = __shfl_up_sync(0xffffffffu, inc, o);
        if (lane >= o) inc += t;
    }
    if (lane == 31) wsum[w] = inc;
    __syncthreads();
    if (tid == 0) {
        int rr = 0;
        for (int i = 0; i < 8; i++) { int t = wsum[i]; wsum[i] = rr; rr += t; }
    }
    __syncthreads();
    int run = bsum[blockIdx.x] + wsum[w] + inc - s;
#pragma unroll
    for (int i = 0; i < 8; i++)
        if (base + i < N) {
            rowptr[base + i] = run;
            cursor[base + i] = run;
            cnt[base + i] = 0;     // replay/branch-safe reset
            run += c[i];
        }
}

__global__ void k_place(const int* __restrict__ ei, const int* __restrict__ ea,
                        const float* __restrict__ dinv, int* __restrict__ cursor,
                        int2* __restrict__ epack, int E) {
    int i = blockIdx.x * blockDim.x + threadIdx.x;
    if (i >= E) return;
    int src = ei[i], dst = ei[E + i];
    float nrm = dinv[src] * dinv[dst];
    int comb = ea[2 * i] * 3 + ea[2 * i + 1];
    int p = atomicAdd(&cursor[dst], 1);
    epack[p] = make_int2(src | (comb << 18), __float_as_int(nrm));
}

// ---------------- CSR gather-aggregate (fp16 buffers, smem eec) + BN stats ----------------
__global__ __launch_bounds__(256) void k_gather(
    const __half* __restrict__ T, __half* __restrict__ AGG,
    const int2* __restrict__ epack, const int* __restrict__ rowptr,
    const float* __restrict__ snorm,
    const float* __restrict__ ee1, const float* __restrict__ ee2,
    float* __restrict__ stats, int N)
{
    __shared__ __align__(16) float seec[18 * HS];
    __shared__ float sst[2 * HS];
    for (int i = threadIdx.x; i < 18 * HS; i += 256) {
        int rr = i / HS, c = i - rr * HS;
        seec[i] = (c < D) ? ee1[(rr / 3) * D + c] + ee2[(rr % 3) * D + c] : 0.f;
    }
    for (int i = threadIdx.x; i < 2 * HS; i += 256) sst[i] = 0.f;
    __syncthreads();

    const int lane = threadIdx.x & 31, w = threadIdx.x >> 5;
    const int gw = blockIdx.x * 8 + w, nw = gridDim.x * 8;
    const bool hi = lane < (HI4 - 32);
    const int c0 = lane * 8, c1 = (lane + 32) * 8;

    float lsum[16], lsq[16];
#pragma unroll
    for (int i = 0; i < 16; i++) { lsum[i] = 0.f; lsq[i] = 0.f; }

    const float* e12 = seec + 12 * HS;

    for (int node = gw; node < N; node += nw) {
        float acc[16];
#pragma unroll
        for (int q = 0; q < 16; q++) acc[q] = 0.f;
        float sn = snorm[node];
        const uint4* ts = (const uint4*)(T + (size_t)node * HS);
        acc8(acc, ts[lane], e12, c0, sn);
        if (hi) acc8(acc + 8, ts[lane + 32], e12, c1, sn);

        int p = rowptr[node], pend = rowptr[node + 1];
        for (; p + 2 <= pend; p += 2) {
            int2 e0 = epack[p], e1 = epack[p + 1];
            const uint4* t0 = (const uint4*)(T + (size_t)(e0.x & 0x3FFFF) * HS);
            const uint4* t1 = (const uint4*)(T + (size_t)(e1.x & 0x3FFFF) * HS);
            float n0 = __int_as_float(e0.y), n1 = __int_as_float(e1.y);
            const float* ec0 = seec + (e0.x >> 18) * HS;
            const float* ec1 = seec + (e1.x >> 18) * HS;
            uint4 u0a = t0[lane], u1a = t1[lane];
            uint4 u0b, u1b;
            if (hi) { u0b = t0[lane + 32]; u1b = t1[lane + 32]; }
            acc8(acc, u0a, ec0, c0, n0);
            acc8(acc, u1a, ec1, c0, n1);
            if (hi) {
                acc8(acc + 8, u0b, ec0, c1, n0);
                acc8(acc + 8, u1b, ec1, c1, n1);
            }
        }
        if (p < pend) {
            int2 e0 = epack[p];
            const uint4* t0 = (const uint4*)(T + (size_t)(e0.x & 0x3FFFF) * HS);
            float n0 = __int_as_float(e0.y);
            const float* ec0 = seec + (e0.x >> 18) * HS;
            acc8(acc, t0[lane], ec0, c0, n0);
            if (hi) acc8(acc + 8, t0[lane + 32], ec0, c1, n0);
        }

        uint4* op = (uint4*)(AGG + (size_t)node * HS);
        {
            uint4 u;
            u.x = pack_hf(acc[0], acc[1]); u.y = pack_hf(acc[2], acc[3]);
            u.z = pack_hf(acc[4], acc[5]); u.w = pack_hf(acc[6], acc[7]);
            op[lane] = u;
        }
        if (hi) {
            uint4 u;
            u.x = pack_hf(acc[8], acc[9]);  u.y = pack_hf(acc[10], acc[11]);
            u.z = pack_hf(acc[12], acc[13]); u.w = pack_hf(acc[14], acc[15]);
            op[lane + 32] = u;
        }
#pragma unroll
        for (int q = 0; q < 16; q++) {
            lsum[q] += acc[q];
            lsq[q] = fmaf(acc[q], acc[q], lsq[q]);
        }
    }
#pragma unroll
    for (int q = 0; q < 8; q++) {
        atomicAdd(&sst[c0 + q], lsum[q]);
        atomicAdd(&sst[HS + c0 + q], lsq[q]);
    }
    if (hi) {
#pragma unroll
        for (int q = 0; q < 8; q++) {
            atomicAdd(&sst[c1 + q], lsum[8 + q]);
            atomicAdd(&sst[HS + c1 + q], lsq[8 + q]);
        }
    }
    __syncthreads();
    for (int i = threadIdx.x; i < D; i += 256) {
        atomicAdd(&stats[i], sst[i]);
        atomicAdd(&stats[D + i], sst[HS + i]);
    }
}

__global__ void k_bnfin(float* __restrict__ st, const float* __restrict__ gamma,
                        const float* __restrict__ beta, float* __restrict__ sc,
                        float* __restrict__ sh, float invn) {
    int c = threadIdx.x;
    if (c >= D) return;
    float mean = st[c] * invn;
    float var = fmaxf(st[D + c] * invn - mean * mean, 0.f);
    float s = gamma[c] / sqrtf(var + 1e-5f);
    sc[c] = s;
    sh[c] = beta[c] - mean * s;
    st[c] = 0.f;
    st[D + c] = 0.f;
}

// ---------------- pool CSR build (small id spaces) ----------------
__global__ void k_pcnt(const int* __restrict__ ids, int* __restrict__ cnt, int n) {
    int i = blockIdx.x * blockDim.x + threadIdx.x;
    if (i < n) atomicAdd(&cnt[ids[i]], 1);
}

// single-block scan over M <= 8192; zeroes cnt after read (replay-safe)
__global__ void k_pscan(int* __restrict__ cnt, int* __restrict__ rowptr,
                        int* __restrict__ cursor, int M) {
    __shared__ int sh[256];
    int tid = threadIdx.x;
    int per = (M + 255) / 256;
    int base = tid * per;
    int s = 0;
    for (int j = 0; j < per; j++) {
        int i = base + j;
        if (i < M) s += cnt[i];
    }
    sh[tid] = s;
    __syncthreads();
    for (int o = 1; o < 256; o <<= 1) {
        int v = (tid >= o) ? sh[tid - o] : 0;
        __syncthreads();
        sh[tid] += v;
        __syncthreads();
    }
    int run = sh[tid] - s;   // exclusive
    for (int j = 0; j < per; j++) {
        int i = base + j;
        if (i < M) {
            rowptr[i] = run;
            cursor[i] = run;
            run += cnt[i];
            cnt[i] = 0;
        }
    }
    if (tid == 255) rowptr[M] = sh[255];
}

__global__ void k_pplace(const int* __restrict__ ids, int* __restrict__ cursor,
                         int* __restrict__ pidx, int n) {
    int i = blockIdx.x * blockDim.x + threadIdx.x;
    if (i < n) pidx[atomicAdd(&cursor[ids[i]], 1)] = i;
}

// ---------------- CSR mean-pool: warp per group, no atomics ----------------
// source: Th (fp16 stride HS) or Tf (fp32 stride D). Optional BN affine applied
// post-sum (linear: sum(s*x+t) = s*sum + cnt*t). Writes raw SUMS + count.
__global__ __launch_bounds__(256) void k_poolg(
    const __half* __restrict__ Th, const float* __restrict__ Tf,
    const int* __restrict__ prow, const int* __restrict__ pidx,
    const float* __restrict__ scale, const float* __restrict__ shift,
    float* __restrict__ pool, float* __restrict__ cntf, int G)
{
    int w = (blockIdx.x * blockDim.x + threadIdx.x) >> 5;
    int lane = threadIdx.x & 31;
    if (w >= G) return;
    int p0 = prow[w], p1 = prow[w + 1];
    const int c0 = lane * 8, c1 = (lane + 32) * 8;
    const bool hi = (lane + 32) < HI4;   // lane < 6

    float a0[8], a1[8];
#pragma unroll
    for (int q = 0; q < 8; q++) { a0[q] = 0.f; a1[q] = 0.f; }

    for (int p = p0; p < p1; p++) {
        int node = pidx[p];
        if (Th) {
            const uint4* ts = (const uint4*)(Th + (size_t)node * HS);
            float f[8];
            unpack8(ts[lane], f);
#pragma unroll
            for (int q = 0; q < 8; q++) a0[q] += f[q];
            if (hi) {
                unpack8(ts[lane + 32], f);
#pragma unroll
                for (int q = 0; q < 8; q++) a1[q] += f[q];
            }
        } else {
            const float* tr = Tf + (size_t)node * D;
            float4 v0 = *(const float4*)(tr + c0);
            float4 v1 = *(const float4*)(tr + c0 + 4);
            a0[0] += v0.x; a0[1] += v0.y; a0[2] += v0.z; a0[3] += v0.w;
            a0[4] += v1.x; a0[5] += v1.y; a0[6] += v1.z; a0[7] += v1.w;
            if (hi) {
                float4 u0 = *(const float4*)(tr + c1);
                a1[0] += u0.x; a1[1] += u0.y; a1[2] += u0.z; a1[3] += u0.w;
                if (c1 + 4 < D) {
                    float4 u1 = *(const float4*)(tr + c1 + 4);
                    a1[4] += u1.x; a1[5] += u1.y; a1[6] += u1.z; a1[7] += u1.w;
                }
            }
        }
    }
    float cn = (float)(p1 - p0);
    if (scale) {
#pragma unroll
        for (int q = 0; q < 8; q++)
            a0[q] = fmaf(a0[q], scale[c0 + q], cn * shift[c0 + q]);
        if (hi) {
#pragma unroll
            for (int q = 0; q < 8; q++) {
                int c = c1 + q;
                if (c < D) a1[q] = fmaf(a1[q], scale[c], cn * shift[c]);
            }
        }
    }
    float* op = pool + (size_t)w * D;
    *(float4*)(op + c0)     = make_float4(a0[0], a0[1], a0[2], a0[3]);
    *(float4*)(op + c0 + 4) = make_float4(a0[4], a0[5], a0[6], a0[7]);
    if (hi) {
        *(float4*)(op + c1) = make_float4(a1[0], a1[1], a1[2], a1[3]);
        if (c1 + 4 < D)
            *(float4*)(op + c1 + 4) = make_float4(a1[4], a1[5], a1[6], a1[7]);
    }
    if (lane == 0) cntf[w] = cn;
}

__global__ void k_l2norm(const float* __restrict__ A, float* __restrict__ out, int n) {
    int w = (blockIdx.x * blockDim.x + threadIdx.x) >> 5;
    int lane = threadIdx.x & 31;
    if (w >= n) return;
    const float4* ap = (const float4*)(A + (long long)w * D);
    float s = 0.f;
    for (int idx = lane; idx < D4; idx += 32) {
        float4 v = ap[idx];
        s += v.x * v.x + v.y * v.y + v.z * v.z + v.w * v.w;
    }
#pragma unroll
    for (int o = 16; o; o >>= 1) s += __shfl_xor_sync(0xffffffffu, s, o);
    float inv = 1.0f / fmaxf(sqrtf(s), 1e-12f);
    float4* op = (float4*)(out + (long long)w * D);
    for (int idx = lane; idx < D4; idx += 32) {
        float4 v = ap[idx];
        op[idx] = make_float4(v.x * inv, v.y * inv, v.z * inv, v.w * inv);
    }
}

// ---------------- FFMA2 GEMM (exact fp32, logits only) ----------------
__global__ __launch_bounds__(256) void k_gemm(
    const float* __restrict__ A, const float* __restrict__ B, float* __restrict__ C,
    int M, int Nc, int K, float oscale)
{
    __shared__ float As[32][130];
    __shared__ float Bs[32][68];

    const int tid = threadIdx.x;
    const int tx = tid & 15, ty = tid >> 4;
    const int m0 = blockIdx.y * 128, n0 = blockIdx.x * 64;

    unsigned long long acc[4][4];
#pragma unroll
    for (int i = 0; i < 4; i++)
#pragma unroll
        for (int j = 0; j < 4; j++) acc[i][j] = 0ull;

    const int nk = (K + 31) >> 5;
    for (int kt = 0; kt < nk; kt++) {
        const int k0 = kt << 5;
#pragma unroll
        for (int i = 0; i < 4; i++) {
            int e = i * 256 + tid;
            int k4 = e & 7, rr = e >> 3;
            int gmm = m0 + rr, gk = k0 + 4 * k4;
            float4 v = make_float4(0.f, 0.f, 0.f, 0.f);
            if (gmm < M && gk < K)
                v = *(const float4*)(A + (long long)gmm * K + gk);
            As[4 * k4 + 0][rr] = v.x; As[4 * k4 + 1][rr] = v.y;
            As[4 * k4 + 2][rr] = v.z; As[4 * k4 + 3][rr] = v.w;
        }
#pragma unroll
        for (int i = 0; i < 2; i++) {
            int e = i * 256 + tid;
            int k4 = e & 7, rr = e >> 3;
            int gn = n0 + rr, gk = k0 + 4 * k4;
            float4 v = make_float4(0.f, 0.f, 0.f, 0.f);
            if (gn < Nc && gk < K)
                v = *(const float4*)(B + (long long)gn * K + gk);
            Bs[4 * k4 + 0][rr] = v.x; Bs[4 * k4 + 1][rr] = v.y;
            Bs[4 * k4 + 2][rr] = v.z; Bs[4 * k4 + 3][rr] = v.w;
        }
        __syncthreads();
#pragma unroll
        for (int kk = 0; kk < 32; kk++) {
            unsigned long long a2[4];
#pragma unroll
            for (int i = 0; i < 4; i++)
                a2[i] = *(const unsigned long long*)&As[kk][ty * 8 + 2 * i];
            float4 bv = *(const float4*)&Bs[kk][tx * 4];
            unsigned long long b2[4];
            {
                unsigned u0 = __float_as_uint(bv.x), u1 = __float_as_uint(bv.y);
                unsigned u2 = __float_as_uint(bv.z), u3 = __float_as_uint(bv.w);
                asm("mov.b64 %0, {%1,%1};" : "=l"(b2[0]) : "r"(u0));
                asm("mov.b64 %0, {%1,%1};" : "=l"(b2[1]) : "r"(u1));
                asm("mov.b64 %0, {%1,%1};" : "=l"(b2[2]) : "r"(u2));
                asm("mov.b64 %0, {%1,%1};" : "=l"(b2[3]) : "r"(u3));
            }
#pragma unroll
            for (int i = 0; i < 4; i++)
#pragma unroll
                for (int j = 0; j < 4; j++)
                    asm("fma.rn.f32x2 %0, %1, %2, %3;"
                        : "=l"(acc[i][j]) : "l"(a2[i]), "l"(b2[j]), "l"(acc[i][j]));
        }
        __syncthreads();
    }

#pragma unroll
    for (int i = 0; i < 4; i++) {
#pragma unroll
        for (int j = 0; j < 4; j++) {
            int gn = n0 + tx * 4 + j;
            if (gn >= Nc) continue;
            float lo = __uint_as_float((unsigned)(acc[i][j] & 0xffffffffull));
            float hi = __uint_as_float((unsigned)(acc[i][j] >> 32));
            int gmm = m0 + ty * 8 + 2 * i;
            if (gmm < M)     C[(long long)gmm * Nc + gn] = lo * oscale;
            if (gmm + 1 < M) C[(long long)(gmm + 1) * Nc + gn] = hi * oscale;
        }
    }
}

// ---------------- host ----------------
static float* symaddr(const void* sym) {
    void* p = nullptr;
    cudaGetSymbolAddress(&p, sym);
    return (float*)p;
}

extern "C" void kernel_launch(void* const* d_in, const int* in_sizes, int n_in,
                              void* d_out, int out_size) {
    const int*   batch_x  = (const int*)d_in[0];
    const int*   batch_ei = (const int*)d_in[1];
    const int*   batch_ea = (const int*)d_in[2];
    const int*   batch_gid= (const int*)d_in[3];
    const int*   frag_x   = (const int*)d_in[4];
    const int*   frag_ei  = (const int*)d_in[5];
    const int*   frag_ea  = (const int*)d_in[6];
    const int*   frag_jid = (const int*)d_in[7];
    const int*   jct_gid  = (const int*)d_in[8];
    const float* jmask    = (const float*)d_in[9];
    const float* ae1      = (const float*)d_in[10];
    const float* ae2      = (const float*)d_in[11];
    const float* gW       = (const float*)d_in[12];
    const float* gb       = (const float*)d_in[13];
    const float* gee1     = (const float*)d_in[14];
    const float* gee2     = (const float*)d_in[15];
    const float* bng      = (const float*)d_in[16];
    const float* bnb      = (const float*)d_in[17];
    const float* jW       = (const float*)d_in[18];
    const float* jb       = (const float*)d_in[19];
    const float* jee1     = (const float*)d_in[20];
    const float* jee2     = (const float*)d_in[21];
    const float* memb     = (const float*)d_in[22];

    const int N  = in_sizes[0] / 2;
    const int E  = in_sizes[1] / 2;
    const int NJ = in_sizes[8];
    const int NG = 1024;
    const int SB = (N + 2047) / 2048;

    __half* buf0h = (__half*)symaddr(g_buf0h);
    __half* buf1h = (__half*)symaddr(g_buf1h);
    float* degp   = symaddr(g_deg);
    float* snormp = symaddr(g_snorm);
    float* statsp = symaddr(g_stats);
    float* scalep = symaddr(g_scale);
    float* shiftp = symaddr(g_shift);
    float* poolp  = symaddr(g_pool);
    float* cntp   = symaddr(g_cnt);
    float* t0p    = symaddr(g_t0);
    float* t1p    = symaddr(g_t1);
    float* f0p    = symaddr(g_f0);
    float* f1p    = symaddr(g_f1);
    int*   rowptr = (int*)symaddr(g_rowptr);
    int*   cursor = (int*)symaddr(g_cursor);
    int*   cnte   = (int*)symaddr(g_cnte);
    int*   idegp  = (int*)symaddr(g_ideg);
    int*   bsum   = (int*)symaddr(g_bsum);
    int2*  epack  = (int2*)symaddr(g_epack);
    int*   pcnt   = (int*)symaddr(g_pcnt);
    int*   prow   = (int*)symaddr(g_prow);
    int*   pcur   = (int*)symaddr(g_pcur);
    int*   pidx   = (int*)symaddr(g_pidx);
    __half* whp   = (__half*)symaddr(g_wh);

    cudaFuncSetAttribute(k_mma, cudaFuncAttributeMaxDynamicSharedMemorySize, MMA_SMEM);

    k_wh<<<(5 * WMAT + 255) / 256, 256>>>(gW, whp, 5);
    k_wh<<<(2 * WMAT + 255) / 256, 256>>>(jW, whp + (size_t)5 * WMAT, 2);

    auto tgemm16 = [&](const __half* Ah, const int* xidx, int mat, __half* C16, int M,
                       const float* bias, const float* sc, const float* sh, int relu) {
        k_mma<<<dim3((M + 127) / 128, 1), 256, MMA_SMEM>>>(
            nullptr, Ah, xidx, ae1, ae2, whp + (size_t)mat * WMAT,
            nullptr, C16, M, D, bias, nullptr, nullptr, sc, sh, relu, 1.0f,
            nullptr, nullptr, nullptr);
    };
    auto tgemm32 = [&](const float* A, int mat, float* C, int M,
                       const float* bias, const float* e1, const float* e2, int relu,
                       const float* rdivc, const float* rmask) {
        k_mma<<<dim3((M + 127) / 128, 3), 256, MMA_SMEM>>>(
            A, nullptr, nullptr, ae1, ae2, whp + (size_t)mat * WMAT,
            C, nullptr, M, D, bias, e1, e2, nullptr, nullptr, relu, 1.0f,
            rdivc, rmask, memb);
    };
    auto pool_build = [&](const int* ids, int n, int G) {
        k_pcnt<<<(n + 255) / 256, 256>>>(ids, pcnt, n);
        k_pscan<<<1, 256>>>(pcnt, prow, pcur, G);
        k_pplace<<<(n + 255) / 256, 256>>>(ids, pcur, pidx, n);
    };

    auto run_gnn = [&](const int* x, const int* ei, const int* ea) {
        k_count<<<(E + 255) / 256, 256>>>(ei, idegp, cnte, E);
        k_scan1<<<SB, 256>>>(cnte, bsum, idegp, degp, snormp, N);
        k_scan2<<<1, 1>>>(bsum, rowptr + N, SB);
        k_scan3<<<SB, 256>>>(cnte, bsum, rowptr, cursor, N);
        k_place<<<(E + 255) / 256, 256>>>(ei, ea, degp, cursor, epack, E);

        for (int l = 0; l < 5; l++) {
            const float* sc = l ? scalep : nullptr;
            const float* sh = l ? shiftp : nullptr;
            tgemm16(l ? buf0h : nullptr, l ? nullptr : x, l, buf1h, N,
                    gb + l * D, sc, sh, l ? 1 : 0);
            k_gather<<<592, 256>>>(buf1h, buf0h, epack, rowptr, snormp,
                                   gee1 + (long long)l * 6 * D,
                                   gee2 + (long long)l * 3 * D, statsp, N);
            k_bnfin<<<1, D>>>(statsp, bng + l * D, bnb + l * D, scalep, shiftp, 1.0f / (float)N);
        }
    };

    // ---------- branch 0 ----------
    run_gnn(batch_x, batch_ei, batch_ea);
    pool_build(batch_gid, N, NG);
    k_poolg<<<(NG * 32 + 255) / 256, 256>>>(buf0h, nullptr, prow, pidx,
                                            scalep, shiftp, poolp, cntp, NG);
    tgemm32(poolp, 5, t0p, NG, jb, jee1 + 4 * D, jee2, 0, cntp, nullptr);
    tgemm32(t0p, 6, t1p, NG, jb + D, jee1 + (6 + 4) * D, jee2 + 3 * D, 1, nullptr, nullptr);
    k_l2norm<<<(NG * 32 + 255) / 256, 256>>>(t1p, f0p, NG);

    // ---------- branch 1 ----------
    run_gnn(frag_x, frag_ei, frag_ea);
    pool_build(frag_jid, N, NJ);
    k_poolg<<<(NJ * 32 + 255) / 256, 256>>>(buf0h, nullptr, prow, pidx,
                                            scalep, shiftp, poolp, cntp, NJ);
    tgemm32(poolp, 5, t0p, NJ, jb, jee1 + 4 * D, jee2, 0, cntp, jmask);
    tgemm32(t0p, 6, t1p, NJ, jb + D, jee1 + (6 + 4) * D, jee2 + 3 * D, 1, nullptr, nullptr);
    pool_build(jct_gid, NJ, NG);
    k_poolg<<<(NG * 32 + 255) / 256, 256>>>(nullptr, t1p, prow, pidx,
                                            nullptr, nullptr, poolp, cntp, NG);
    // mean-pool division omitted: l2norm is row-scale invariant
    k_l2norm<<<(NG * 32 + 255) / 256, 256>>>(poolp, f1p, NG);

    // ---------- logits = (f0 @ f1^T) / TEMP ----------
    {
        dim3 gl((NG + 63) / 64, (NG + 127) / 128);
        k_gemm<<<gl, 256>>>(f0p, f1p, (float*)d_out, NG, NG, D, 25.0f);
    }
}